// round 1
// baseline (speedup 1.0000x reference)
#include <cuda_runtime.h>
#include <cstdint>

#define NN 100000
#define EE 1600000
#define DD 128
#define GG 64
#define CC 2
#define EPSBN 1e-5f

// ---------------- scratch (static device globals; no allocation) ----------------
__device__ float g_bufA[(size_t)NN * DD];
__device__ float g_bufB[(size_t)NN * DD];
__device__ float g_dinv[NN];          // also used as deg accumulator
__device__ int   g_count[NN];
__device__ int   g_offs[NN + 1];
__device__ int   g_cursor[NN];
__device__ int   g_bsums[512];
__device__ int   g_csrc[EE];
__device__ float g_ccoef[EE];
__device__ float g_stats[2 * DD];

// ---------------- utility kernels ----------------
__global__ void zero_f(float* p, int n) {
    int i = blockIdx.x * blockDim.x + threadIdx.x;
    if (i < n) p[i] = 0.f;
}
__global__ void zero_i(int* p, int n) {
    int i = blockIdx.x * blockDim.x + threadIdx.x;
    if (i < n) p[i] = 0;
}
__global__ void copy_i(int* dst, const int* src, int n) {
    int i = blockIdx.x * blockDim.x + threadIdx.x;
    if (i < n) dst[i] = src[i];
}

// ---------------- degree histogram ----------------
__global__ void hist_kernel(const int* __restrict__ src, const int* __restrict__ dst,
                            const float* __restrict__ attr, float* deg, int* cnt) {
    int e = blockIdx.x * blockDim.x + threadIdx.x;
    if (e >= EE) return;
    int d = dst[e];
    float w = attr[(size_t)e * 2 + 1];
    atomicAdd(&deg[d], w);
    atomicAdd(&cnt[d], 1);
}

__global__ void dinv_kernel(float* dinv) {
    int i = blockIdx.x * blockDim.x + threadIdx.x;
    if (i < NN) dinv[i] = rsqrtf(dinv[i] + 1.0f);
}

// ---------------- scan (3 kernels) ----------------
__global__ void scan1(const int* __restrict__ in, int* __restrict__ out /* = offs+1 */,
                      int* __restrict__ bsums, int n) {
    __shared__ int sh[256];
    int tid = threadIdx.x;
    int base = blockIdx.x * 1024;
    int v[4]; int tsum = 0;
#pragma unroll
    for (int j = 0; j < 4; j++) {
        int idx = base + tid * 4 + j;
        v[j] = (idx < n) ? in[idx] : 0;
        tsum += v[j];
    }
    sh[tid] = tsum; __syncthreads();
#pragma unroll
    for (int off = 1; off < 256; off <<= 1) {
        int t = (tid >= off) ? sh[tid - off] : 0;
        __syncthreads();
        sh[tid] += t;
        __syncthreads();
    }
    int run = sh[tid] - tsum; // exclusive prefix of this thread
#pragma unroll
    for (int j = 0; j < 4; j++) {
        int idx = base + tid * 4 + j;
        run += v[j];
        if (idx < n) out[idx] = run; // inclusive
    }
    if (tid == 255) bsums[blockIdx.x] = sh[255];
}

__global__ void scan2(int* bs, int nb) {
    __shared__ int sh[128];
    int tid = threadIdx.x;
    int orig = (tid < nb) ? bs[tid] : 0;
    sh[tid] = orig; __syncthreads();
#pragma unroll
    for (int off = 1; off < 128; off <<= 1) {
        int t = (tid >= off) ? sh[tid - off] : 0;
        __syncthreads();
        sh[tid] += t;
        __syncthreads();
    }
    if (tid < nb) bs[tid] = sh[tid] - orig; // exclusive
}

__global__ void scan3(int* out /* = offs+1 */, const int* __restrict__ bs, int n, int* offs0) {
    int tid = threadIdx.x;
    int base = blockIdx.x * 1024;
    int add = bs[blockIdx.x];
#pragma unroll
    for (int j = 0; j < 4; j++) {
        int idx = base + tid * 4 + j;
        if (idx < n) out[idx] += add;
    }
    if (blockIdx.x == 0 && tid == 0) offs0[0] = 0;
}

// ---------------- CSR fill ----------------
__global__ void fill_kernel(const int* __restrict__ src, const int* __restrict__ dst,
                            const float* __restrict__ attr, const float* __restrict__ dinv,
                            int* cursor, int* csrc, float* ccoef) {
    int e = blockIdx.x * blockDim.x + threadIdx.x;
    if (e >= EE) return;
    int s = src[e], d = dst[e];
    float w = attr[(size_t)e * 2 + 1];
    int pos = atomicAdd(&cursor[d], 1);
    csrc[pos] = s;
    ccoef[pos] = dinv[s] * w * dinv[d];
}

// ---------------- GEMM: C[nrows x 128] = A[nrows x 128] @ W[128 x 128] (+bias, relu) ----------------
__global__ void __launch_bounds__(256) gemm128(const float* __restrict__ A,
                                               const float* __restrict__ W,
                                               const float* __restrict__ bias,
                                               float* __restrict__ Cout,
                                               int nrows, int relu) {
    __shared__ float As[16][132];
    __shared__ float Bs[16][132];
    int tid = threadIdx.x;
    int ty = tid >> 4, tx = tid & 15;
    int row0 = blockIdx.x * 128;

    float acc[8][8];
#pragma unroll
    for (int r = 0; r < 8; r++)
#pragma unroll
        for (int c = 0; c < 8; c++) acc[r][c] = 0.f;

    for (int k0 = 0; k0 < 128; k0 += 16) {
        // load A tile (transposed into k-major)
#pragma unroll
        for (int i = 0; i < 2; i++) {
            int f = tid + i * 256;        // 0..511
            int r = f >> 2, q = f & 3;
            int row = row0 + r;
            float4 v = make_float4(0.f, 0.f, 0.f, 0.f);
            if (row < nrows) v = *(const float4*)(A + (size_t)row * 128 + k0 + q * 4);
            As[q * 4 + 0][r] = v.x;
            As[q * 4 + 1][r] = v.y;
            As[q * 4 + 2][r] = v.z;
            As[q * 4 + 3][r] = v.w;
        }
        // load W tile
#pragma unroll
        for (int i = 0; i < 2; i++) {
            int f = tid + i * 256;
            int kk = f >> 5, c4 = f & 31;
            float4 v = *(const float4*)(W + (size_t)(k0 + kk) * 128 + c4 * 4);
            *(float4*)&Bs[kk][c4 * 4] = v;
        }
        __syncthreads();
#pragma unroll
        for (int kk = 0; kk < 16; kk++) {
            float a[8], b[8];
            *(float4*)&a[0] = *(const float4*)&As[kk][ty * 8];
            *(float4*)&a[4] = *(const float4*)&As[kk][ty * 8 + 4];
            *(float4*)&b[0] = *(const float4*)&Bs[kk][tx * 8];
            *(float4*)&b[4] = *(const float4*)&Bs[kk][tx * 8 + 4];
#pragma unroll
            for (int r = 0; r < 8; r++)
#pragma unroll
                for (int c = 0; c < 8; c++) acc[r][c] += a[r] * b[c];
        }
        __syncthreads();
    }

    float bv[8];
    if (bias) {
        *(float4*)&bv[0] = *(const float4*)(bias + tx * 8);
        *(float4*)&bv[4] = *(const float4*)(bias + tx * 8 + 4);
    } else {
#pragma unroll
        for (int c = 0; c < 8; c++) bv[c] = 0.f;
    }
#pragma unroll
    for (int r = 0; r < 8; r++) {
        int row = row0 + ty * 8 + r;
        if (row < nrows) {
            float o[8];
#pragma unroll
            for (int c = 0; c < 8; c++) {
                float v = acc[r][c] + bv[c];
                o[c] = relu ? fmaxf(v, 0.f) : v;
            }
            *(float4*)(Cout + (size_t)row * 128 + tx * 8) = *(float4*)&o[0];
            *(float4*)(Cout + (size_t)row * 128 + tx * 8 + 4) = *(float4*)&o[4];
        }
    }
}

// ---------------- GCN aggregation: warp per node, gather over CSR ----------------
__global__ void agg_kernel(const float* __restrict__ hw, const float* __restrict__ dinv,
                           const int* __restrict__ offs, const int* __restrict__ csrc,
                           const float* __restrict__ ccoef, const float* __restrict__ bias,
                           float* __restrict__ out, int relu) {
    int gtid = blockIdx.x * blockDim.x + threadIdx.x;
    int node = gtid >> 5;
    if (node >= NN) return;
    int lane = threadIdx.x & 31;

    float di = dinv[node];
    float self = di * di;
    float4 h0 = ((const float4*)(hw + (size_t)node * 128))[lane];
    float4 acc;
    acc.x = self * h0.x; acc.y = self * h0.y; acc.z = self * h0.z; acc.w = self * h0.w;

    int p0 = offs[node], p1 = offs[node + 1];
    for (int p = p0; p < p1; p++) {
        int s = csrc[p];
        float c = ccoef[p];
        float4 v = ((const float4*)(hw + (size_t)s * 128))[lane];
        acc.x += c * v.x; acc.y += c * v.y; acc.z += c * v.z; acc.w += c * v.w;
    }
    float4 b = ((const float4*)bias)[lane];
    acc.x += b.x; acc.y += b.y; acc.z += b.z; acc.w += b.w;
    if (relu) {
        acc.x = fmaxf(acc.x, 0.f); acc.y = fmaxf(acc.y, 0.f);
        acc.z = fmaxf(acc.z, 0.f); acc.w = fmaxf(acc.w, 0.f);
    }
    ((float4*)(out + (size_t)node * 128))[lane] = acc;
}

// ---------------- BatchNorm ----------------
__global__ void bn_stats(const float* __restrict__ X, float* stats, int nrows) {
    __shared__ float sh[256];
    int d = threadIdx.x & 127;
    int half = threadIdx.x >> 7;
    int r0 = blockIdx.x * 128;
    int rend = min(r0 + 128, nrows);
    float s = 0.f, q = 0.f;
    for (int r = r0 + half; r < rend; r += 2) {
        float v = X[(size_t)r * 128 + d];
        s += v; q += v * v;
    }
    sh[threadIdx.x] = s; __syncthreads();
    if (half == 0) atomicAdd(&stats[d], s + sh[128 + d]);
    __syncthreads();
    sh[threadIdx.x] = q; __syncthreads();
    if (half == 0) atomicAdd(&stats[128 + d], q + sh[128 + d]);
}

__global__ void bn_finalize(float* stats, const float* __restrict__ gamma,
                            const float* __restrict__ beta) {
    int d = threadIdx.x; // 128 threads
    float invn = 1.0f / (float)NN;
    float m = stats[d] * invn;
    float v = stats[128 + d] * invn - m * m;
    float sc = gamma[d] * rsqrtf(v + EPSBN);
    stats[d] = sc;
    stats[128 + d] = beta[d] - m * sc;
}

__global__ void bn_apply(const float* __restrict__ X, const float* __restrict__ stats,
                         float* __restrict__ out) {
    int i = blockIdx.x * blockDim.x + threadIdx.x; // float4 index
    if (i >= NN * 32) return;
    int d0 = (i & 31) * 4;
    float4 v = ((const float4*)X)[i];
    float4 o;
    o.x = v.x * stats[d0 + 0] + stats[128 + d0 + 0];
    o.y = v.y * stats[d0 + 1] + stats[128 + d0 + 1];
    o.z = v.z * stats[d0 + 2] + stats[128 + d0 + 2];
    o.w = v.w * stats[d0 + 3] + stats[128 + d0 + 3];
    ((float4*)out)[i] = o;
}

// ---------------- graph pooling (batch is sorted) ----------------
__global__ void pool_kernel(const float* __restrict__ h, const int* __restrict__ batch,
                            float* __restrict__ reps) {
    int g = blockIdx.x;
    int lo = 0, hi = NN;
    while (lo < hi) { int mid = (lo + hi) >> 1; if (batch[mid] < g) lo = mid + 1; else hi = mid; }
    int start = lo;
    lo = start; hi = NN;
    while (lo < hi) { int mid = (lo + hi) >> 1; if (batch[mid] < g + 1) lo = mid + 1; else hi = mid; }
    int end = lo;
    int cnt = end - start;
    float inv = 1.0f / (float)max(cnt, 1);
    int d = threadIdx.x;
    float s = 0.f;
    for (int r = start; r < end; r++) s += h[(size_t)r * 128 + d];
    reps[g * 128 + d] = s * inv;
}

// ---------------- classifier ----------------
__global__ void classify_kernel(const float* __restrict__ reps,
                                const float* __restrict__ Wc1, const float* __restrict__ bc1,
                                const float* __restrict__ Wc2, const float* __restrict__ bc2,
                                float* __restrict__ logits) {
    __shared__ float rsh[128];
    __shared__ float tsh[128];
    int d = threadIdx.x; // 128 threads
    for (int g = 0; g < GG; g++) {
        rsh[d] = reps[g * 128 + d];
        __syncthreads();
        float s = bc1[d];
#pragma unroll
        for (int k = 0; k < 128; k++) s += rsh[k] * Wc1[k * 128 + d];
        tsh[d] = fmaxf(s, 0.f);
        __syncthreads();
        if (d < CC) {
            float s2 = bc2[d];
#pragma unroll
            for (int k = 0; k < 128; k++) s2 += tsh[k] * Wc2[k * CC + d];
            logits[g * CC + d] = s2;
        }
        __syncthreads();
    }
}

// ---------------- launch ----------------
extern "C" void kernel_launch(void* const* d_in, const int* in_sizes, int n_in,
                              void* d_out, int out_size) {
    const float* x     = (const float*)d_in[0];
    const int*   ei    = (const int*)d_in[1];
    const float* ea    = (const float*)d_in[2];
    const int*   batch = (const int*)d_in[3];
    const float* Wg0 = (const float*)d_in[4],  *bg0 = (const float*)d_in[5];
    const float* gamma0 = (const float*)d_in[6], *beta0 = (const float*)d_in[7];
    const float* Wg1 = (const float*)d_in[8],  *bg1 = (const float*)d_in[9];
    const float* gamma1 = (const float*)d_in[10], *beta1 = (const float*)d_in[11];
    const float* Wl1 = (const float*)d_in[12], *bl1 = (const float*)d_in[13];
    const float* Wl2 = (const float*)d_in[14], *bl2 = (const float*)d_in[15];
    const float* Wc1 = (const float*)d_in[16], *bc1 = (const float*)d_in[17];
    const float* Wc2 = (const float*)d_in[18], *bc2 = (const float*)d_in[19];

    float* out = (float*)d_out;
    float* h_out   = out;
    float* reps    = out + (size_t)NN * DD;
    float* logits  = out + (size_t)NN * DD + (size_t)GG * DD;

    float *bufA, *bufB, *dinv, *ccoef, *stats;
    int *cnt, *offs, *cur, *bsums, *csrc;
    cudaGetSymbolAddress((void**)&bufA, g_bufA);
    cudaGetSymbolAddress((void**)&bufB, g_bufB);
    cudaGetSymbolAddress((void**)&dinv, g_dinv);
    cudaGetSymbolAddress((void**)&cnt, g_count);
    cudaGetSymbolAddress((void**)&offs, g_offs);
    cudaGetSymbolAddress((void**)&cur, g_cursor);
    cudaGetSymbolAddress((void**)&bsums, g_bsums);
    cudaGetSymbolAddress((void**)&csrc, g_csrc);
    cudaGetSymbolAddress((void**)&ccoef, g_ccoef);
    cudaGetSymbolAddress((void**)&stats, g_stats);

    const int* src = ei;
    const int* dst = ei + EE;

    const int TB = 256;
    const int gridN  = (NN + TB - 1) / TB;          // 391
    const int gridE  = (EE + TB - 1) / TB;          // 6250
    const int gridG  = (NN + 127) / 128;            // 782 (gemm / bn_stats blocks)
    const int gridAg = (NN * 32 + TB - 1) / TB;     // 12500
    const int nScanB = (NN + 1023) / 1024;          // 98

    // degrees + CSR build
    zero_f<<<gridN, TB>>>(dinv, NN);
    zero_i<<<gridN, TB>>>(cnt, NN);
    hist_kernel<<<gridE, TB>>>(src, dst, ea, dinv, cnt);
    dinv_kernel<<<gridN, TB>>>(dinv);
    scan1<<<nScanB, 256>>>(cnt, offs + 1, bsums, NN);
    scan2<<<1, 128>>>(bsums, nScanB);
    scan3<<<nScanB, 256>>>(offs + 1, bsums, NN, offs);
    copy_i<<<gridN, TB>>>(cur, offs, NN);
    fill_kernel<<<gridE, TB>>>(src, dst, ea, dinv, cur, csrc, ccoef);

    // GCN layer 0
    gemm128<<<gridG, 256>>>(x, Wg0, nullptr, bufA, NN, 0);
    agg_kernel<<<gridAg, TB>>>(bufA, dinv, offs, csrc, ccoef, bg0, bufB, 1);
    zero_f<<<1, 256>>>(stats, 256);
    bn_stats<<<gridG, 256>>>(bufB, stats, NN);
    bn_finalize<<<1, 128>>>(stats, gamma0, beta0);
    bn_apply<<<gridAg, TB>>>(bufB, stats, bufA);

    // GCN layer 1
    gemm128<<<gridG, 256>>>(bufA, Wg1, nullptr, bufB, NN, 0);
    agg_kernel<<<gridAg, TB>>>(bufB, dinv, offs, csrc, ccoef, bg1, bufA, 1);
    zero_f<<<1, 256>>>(stats, 256);
    bn_stats<<<gridG, 256>>>(bufA, stats, NN);
    bn_finalize<<<1, 128>>>(stats, gamma1, beta1);
    bn_apply<<<gridAg, TB>>>(bufA, stats, bufB);

    // MLP head
    gemm128<<<gridG, 256>>>(bufB, Wl1, bl1, bufA, NN, 1);
    gemm128<<<gridG, 256>>>(bufA, Wl2, bl2, h_out, NN, 0);

    // pooling + classifier
    pool_kernel<<<GG, 128>>>(h_out, batch, reps);
    classify_kernel<<<1, 128>>>(reps, Wc1, bc1, Wc2, bc2, logits);
}

// round 3
// speedup vs baseline: 1.4539x; 1.4539x over previous
#include <cuda_runtime.h>
#include <cstdint>

#define NN 100000
#define EE 1600000
#define DD 128
#define GG 64
#define CC 2
#define EPSBN 1e-5f

// ---------------- scratch (static device globals; no allocation) ----------------
__device__ float g_bufA[(size_t)NN * DD];
__device__ float g_bufB[(size_t)NN * DD];
__device__ float g_dinv[NN];
__device__ int   g_count[NN];
__device__ int   g_offs[NN + 1];
__device__ int   g_cursor[NN];
__device__ int   g_bsums[512];
__device__ int   g_csrc[EE];
__device__ float g_ccoef[EE];
__device__ float g_stats[2 * DD];

// ---------------- helpers ----------------
__device__ __forceinline__ uint32_t cvt_tf32(float x) {
    uint32_t u;
    asm("cvt.rna.tf32.f32 %0, %1;" : "=r"(u) : "f"(x));
    return u;
}

__device__ __forceinline__ void mma_tf32(float* d, const uint32_t* a, const uint32_t* b) {
    asm volatile(
        "mma.sync.aligned.m16n8k8.row.col.f32.tf32.tf32.f32 "
        "{%0,%1,%2,%3}, {%4,%5,%6,%7}, {%8,%9}, {%0,%1,%2,%3};"
        : "+f"(d[0]), "+f"(d[1]), "+f"(d[2]), "+f"(d[3])
        : "r"(a[0]), "r"(a[1]), "r"(a[2]), "r"(a[3]), "r"(b[0]), "r"(b[1]));
}

// ---------------- utility kernels ----------------
__global__ void zero_f(float* p, int n) {
    int i = blockIdx.x * blockDim.x + threadIdx.x;
    if (i < n) p[i] = 0.f;
}
__global__ void zero_i(int* p, int n) {
    int i = blockIdx.x * blockDim.x + threadIdx.x;
    if (i < n) p[i] = 0;
}
__global__ void copy_i(int* dst, const int* src, int n) {
    int i = blockIdx.x * blockDim.x + threadIdx.x;
    if (i < n) dst[i] = src[i];
}

// ---------------- tf32 HMMA GEMM: out[nrows x 128] = affine(A) @ W (+bias, relu) ----------
// A: row-major [nrows][128]; W: row-major [128 k][128 n]
#define PA 132
#define PB 136
#define GSMEM ((128 * PA + 128 * PB) * 4)

__global__ void __launch_bounds__(256) gemm_tc(const float* __restrict__ A,
                                               const float* __restrict__ W,
                                               const float* __restrict__ affine,
                                               const float* __restrict__ bias,
                                               float* __restrict__ out,
                                               int nrows, int relu) {
    extern __shared__ float smem[];
    float* As = smem;              // [128][PA]
    float* Bs = smem + 128 * PA;   // [128][PB]  (k-major: Bs[k][n])
    int tid = threadIdx.x, wid = tid >> 5, lane = tid & 31;
    int row0 = blockIdx.x * 128;
    int gid = lane >> 2, tg = lane & 3;

    // --- stage A (affine + tf32) ---
#pragma unroll
    for (int i = 0; i < 16; i++) {
        int f = i * 256 + tid;
        int row = f >> 5, kq = f & 31;
        float4 v = make_float4(0.f, 0.f, 0.f, 0.f);
        if (row0 + row < nrows)
            v = ((const float4*)A)[(size_t)(row0 + row) * 32 + kq];
        if (affine) {
            int k0 = kq * 4;
            v.x = v.x * affine[k0 + 0] + affine[128 + k0 + 0];
            v.y = v.y * affine[k0 + 1] + affine[128 + k0 + 1];
            v.z = v.z * affine[k0 + 2] + affine[128 + k0 + 2];
            v.w = v.w * affine[k0 + 3] + affine[128 + k0 + 3];
        }
        uint4 t;
        t.x = cvt_tf32(v.x); t.y = cvt_tf32(v.y); t.z = cvt_tf32(v.z); t.w = cvt_tf32(v.w);
        *(uint4*)&As[row * PA + kq * 4] = t;
    }
    // --- stage B (tf32) ---
#pragma unroll
    for (int i = 0; i < 16; i++) {
        int f = i * 256 + tid;
        int k = f >> 5, nq = f & 31;
        float4 v = ((const float4*)W)[(size_t)k * 32 + nq];
        uint4 t;
        t.x = cvt_tf32(v.x); t.y = cvt_tf32(v.y); t.z = cvt_tf32(v.z); t.w = cvt_tf32(v.w);
        *(uint4*)&Bs[k * PB + nq * 4] = t;
    }
    __syncthreads();

    // --- warp tiling: 2x4 warps, each 64(M) x 32(N) ---
    int wm = (wid >> 2) * 64;
    int wn = (wid & 3) * 32;

    float acc[4][4][4];
#pragma unroll
    for (int mi = 0; mi < 4; mi++)
#pragma unroll
        for (int ni = 0; ni < 4; ni++)
#pragma unroll
            for (int j = 0; j < 4; j++) acc[mi][ni][j] = 0.f;

    const uint32_t* Asu = (const uint32_t*)As;
    const uint32_t* Bsu = (const uint32_t*)Bs;

#pragma unroll
    for (int ks = 0; ks < 16; ks++) {
        int k0 = ks * 8;
        uint32_t a[4][4];
#pragma unroll
        for (int mi = 0; mi < 4; mi++) {
            int r = wm + mi * 16 + gid;
            a[mi][0] = Asu[r * PA + k0 + tg];
            a[mi][1] = Asu[(r + 8) * PA + k0 + tg];
            a[mi][2] = Asu[r * PA + k0 + tg + 4];
            a[mi][3] = Asu[(r + 8) * PA + k0 + tg + 4];
        }
        uint32_t b[4][2];
#pragma unroll
        for (int ni = 0; ni < 4; ni++) {
            int c = wn + ni * 8 + gid;
            b[ni][0] = Bsu[(k0 + tg) * PB + c];
            b[ni][1] = Bsu[(k0 + tg + 4) * PB + c];
        }
#pragma unroll
        for (int mi = 0; mi < 4; mi++)
#pragma unroll
            for (int ni = 0; ni < 4; ni++)
                mma_tf32(acc[mi][ni], a[mi], b[ni]);
    }

    // --- epilogue: direct float2 stores ---
    float2 bv[4];
#pragma unroll
    for (int ni = 0; ni < 4; ni++) {
        int c = wn + ni * 8 + 2 * tg;
        if (bias) { bv[ni].x = bias[c]; bv[ni].y = bias[c + 1]; }
        else      { bv[ni].x = 0.f;     bv[ni].y = 0.f; }
    }
#pragma unroll
    for (int mi = 0; mi < 4; mi++) {
        int r_lo = row0 + wm + mi * 16 + gid;
        int r_hi = r_lo + 8;
#pragma unroll
        for (int ni = 0; ni < 4; ni++) {
            int c = wn + ni * 8 + 2 * tg;
            float2 v0, v1;
            v0.x = acc[mi][ni][0] + bv[ni].x;
            v0.y = acc[mi][ni][1] + bv[ni].y;
            v1.x = acc[mi][ni][2] + bv[ni].x;
            v1.y = acc[mi][ni][3] + bv[ni].y;
            if (relu) {
                v0.x = fmaxf(v0.x, 0.f); v0.y = fmaxf(v0.y, 0.f);
                v1.x = fmaxf(v1.x, 0.f); v1.y = fmaxf(v1.y, 0.f);
            }
            if (r_lo < nrows) *(float2*)(out + (size_t)r_lo * 128 + c) = v0;
            if (r_hi < nrows) *(float2*)(out + (size_t)r_hi * 128 + c) = v1;
        }
    }
}

// ---------------- degree histogram ----------------
__global__ void hist_kernel(const int* __restrict__ src, const int* __restrict__ dst,
                            const float* __restrict__ attr, float* deg, int* cnt) {
    int e = blockIdx.x * blockDim.x + threadIdx.x;
    if (e >= EE) return;
    int d = dst[e];
    float w = attr[(size_t)e * 2 + 1];
    atomicAdd(&deg[d], w);
    atomicAdd(&cnt[d], 1);
}

__global__ void dinv_kernel(float* dinv) {
    int i = blockIdx.x * blockDim.x + threadIdx.x;
    if (i < NN) dinv[i] = rsqrtf(dinv[i] + 1.0f);
}

// ---------------- scan (3 kernels) ----------------
__global__ void scan1(const int* __restrict__ in, int* __restrict__ out,
                      int* __restrict__ bsums, int n) {
    __shared__ int sh[256];
    int tid = threadIdx.x;
    int base = blockIdx.x * 1024;
    int v[4]; int tsum = 0;
#pragma unroll
    for (int j = 0; j < 4; j++) {
        int idx = base + tid * 4 + j;
        v[j] = (idx < n) ? in[idx] : 0;
        tsum += v[j];
    }
    sh[tid] = tsum; __syncthreads();
#pragma unroll
    for (int off = 1; off < 256; off <<= 1) {
        int t = (tid >= off) ? sh[tid - off] : 0;
        __syncthreads();
        sh[tid] += t;
        __syncthreads();
    }
    int run = sh[tid] - tsum;
#pragma unroll
    for (int j = 0; j < 4; j++) {
        int idx = base + tid * 4 + j;
        run += v[j];
        if (idx < n) out[idx] = run;
    }
    if (tid == 255) bsums[blockIdx.x] = sh[255];
}

__global__ void scan2(int* bs, int nb) {
    __shared__ int sh[128];
    int tid = threadIdx.x;
    int orig = (tid < nb) ? bs[tid] : 0;
    sh[tid] = orig; __syncthreads();
#pragma unroll
    for (int off = 1; off < 128; off <<= 1) {
        int t = (tid >= off) ? sh[tid - off] : 0;
        __syncthreads();
        sh[tid] += t;
        __syncthreads();
    }
    if (tid < nb) bs[tid] = sh[tid] - orig;
}

__global__ void scan3(int* out, const int* __restrict__ bs, int n, int* offs0) {
    int tid = threadIdx.x;
    int base = blockIdx.x * 1024;
    int add = bs[blockIdx.x];
#pragma unroll
    for (int j = 0; j < 4; j++) {
        int idx = base + tid * 4 + j;
        if (idx < n) out[idx] += add;
    }
    if (blockIdx.x == 0 && tid == 0) offs0[0] = 0;
}

// ---------------- CSR fill ----------------
__global__ void fill_kernel(const int* __restrict__ src, const int* __restrict__ dst,
                            const float* __restrict__ attr, const float* __restrict__ dinv,
                            int* cursor, int* csrc, float* ccoef) {
    int e = blockIdx.x * blockDim.x + threadIdx.x;
    if (e >= EE) return;
    int s = src[e], d = dst[e];
    float w = attr[(size_t)e * 2 + 1];
    int pos = atomicAdd(&cursor[d], 1);
    csrc[pos] = s;
    ccoef[pos] = dinv[s] * w * dinv[d];
}

// ---------------- GCN aggregation: warp per node, gather over CSR ----------------
__global__ void agg_kernel(const float* __restrict__ hw, const float* __restrict__ dinv,
                           const int* __restrict__ offs, const int* __restrict__ csrc,
                           const float* __restrict__ ccoef, const float* __restrict__ bias,
                           float* __restrict__ out, int relu) {
    int gtid = blockIdx.x * blockDim.x + threadIdx.x;
    int node = gtid >> 5;
    if (node >= NN) return;
    int lane = threadIdx.x & 31;

    float di = dinv[node];
    float self = di * di;
    float4 h0 = ((const float4*)(hw + (size_t)node * 128))[lane];
    float4 acc;
    acc.x = self * h0.x; acc.y = self * h0.y; acc.z = self * h0.z; acc.w = self * h0.w;

    int p0 = offs[node], p1 = offs[node + 1];
    for (int p = p0; p < p1; p++) {
        int s = csrc[p];
        float c = ccoef[p];
        float4 v = ((const float4*)(hw + (size_t)s * 128))[lane];
        acc.x += c * v.x; acc.y += c * v.y; acc.z += c * v.z; acc.w += c * v.w;
    }
    float4 b = ((const float4*)bias)[lane];
    acc.x += b.x; acc.y += b.y; acc.z += b.z; acc.w += b.w;
    if (relu) {
        acc.x = fmaxf(acc.x, 0.f); acc.y = fmaxf(acc.y, 0.f);
        acc.z = fmaxf(acc.z, 0.f); acc.w = fmaxf(acc.w, 0.f);
    }
    ((float4*)(out + (size_t)node * 128))[lane] = acc;
}

// ---------------- BatchNorm stats ----------------
__global__ void bn_stats(const float* __restrict__ X, float* stats, int nrows) {
    __shared__ float sh[256];
    int d = threadIdx.x & 127;
    int half = threadIdx.x >> 7;
    int r0 = blockIdx.x * 128;
    int rend = min(r0 + 128, nrows);
    float s = 0.f, q = 0.f;
    for (int r = r0 + half; r < rend; r += 2) {
        float v = X[(size_t)r * 128 + d];
        s += v; q += v * v;
    }
    sh[threadIdx.x] = s; __syncthreads();
    if (half == 0) atomicAdd(&stats[d], s + sh[128 + d]);
    __syncthreads();
    sh[threadIdx.x] = q; __syncthreads();
    if (half == 0) atomicAdd(&stats[128 + d], q + sh[128 + d]);
}

__global__ void bn_finalize(float* stats, const float* __restrict__ gamma,
                            const float* __restrict__ beta) {
    int d = threadIdx.x;
    float invn = 1.0f / (float)NN;
    float m = stats[d] * invn;
    float v = stats[128 + d] * invn - m * m;
    float sc = gamma[d] * rsqrtf(v + EPSBN);
    stats[d] = sc;
    stats[128 + d] = beta[d] - m * sc;
}

// ---------------- graph pooling (batch is sorted) ----------------
__global__ void pool_kernel(const float* __restrict__ h, const int* __restrict__ batch,
                            float* __restrict__ reps) {
    int g = blockIdx.x;
    int lo = 0, hi = NN;
    while (lo < hi) { int mid = (lo + hi) >> 1; if (batch[mid] < g) lo = mid + 1; else hi = mid; }
    int start = lo;
    lo = start; hi = NN;
    while (lo < hi) { int mid = (lo + hi) >> 1; if (batch[mid] < g + 1) lo = mid + 1; else hi = mid; }
    int end = lo;
    int cnt = end - start;
    float inv = 1.0f / (float)max(cnt, 1);
    int d = threadIdx.x;
    float s = 0.f;
    for (int r = start; r < end; r++) s += h[(size_t)r * 128 + d];
    reps[g * 128 + d] = s * inv;
}

// ---------------- classifier ----------------
__global__ void classify_kernel(const float* __restrict__ reps,
                                const float* __restrict__ Wc1, const float* __restrict__ bc1,
                                const float* __restrict__ Wc2, const float* __restrict__ bc2,
                                float* __restrict__ logits) {
    __shared__ float rsh[128];
    __shared__ float tsh[128];
    int d = threadIdx.x;
    for (int g = 0; g < GG; g++) {
        rsh[d] = reps[g * 128 + d];
        __syncthreads();
        float s = bc1[d];
#pragma unroll
        for (int k = 0; k < 128; k++) s += rsh[k] * Wc1[k * 128 + d];
        tsh[d] = fmaxf(s, 0.f);
        __syncthreads();
        if (d < CC) {
            float s2 = bc2[d];
#pragma unroll
            for (int k = 0; k < 128; k++) s2 += tsh[k] * Wc2[k * CC + d];
            logits[g * CC + d] = s2;
        }
        __syncthreads();
    }
}

// ---------------- launch ----------------
extern "C" void kernel_launch(void* const* d_in, const int* in_sizes, int n_in,
                              void* d_out, int out_size) {
    const float* x     = (const float*)d_in[0];
    const int*   ei    = (const int*)d_in[1];
    const float* ea    = (const float*)d_in[2];
    const int*   batch = (const int*)d_in[3];
    const float* Wg0 = (const float*)d_in[4],  *bg0 = (const float*)d_in[5];
    const float* gamma0 = (const float*)d_in[6], *beta0 = (const float*)d_in[7];
    const float* Wg1 = (const float*)d_in[8],  *bg1 = (const float*)d_in[9];
    const float* gamma1 = (const float*)d_in[10], *beta1 = (const float*)d_in[11];
    const float* Wl1 = (const float*)d_in[12], *bl1 = (const float*)d_in[13];
    const float* Wl2 = (const float*)d_in[14], *bl2 = (const float*)d_in[15];
    const float* Wc1 = (const float*)d_in[16], *bc1 = (const float*)d_in[17];
    const float* Wc2 = (const float*)d_in[18], *bc2 = (const float*)d_in[19];

    float* out = (float*)d_out;
    float* h_out  = out;
    float* reps   = out + (size_t)NN * DD;
    float* logits = out + (size_t)NN * DD + (size_t)GG * DD;

    float *bufA, *bufB, *dinv, *ccoef, *stats;
    int *cnt, *offs, *cur, *bsums, *csrc;
    cudaGetSymbolAddress((void**)&bufA, g_bufA);
    cudaGetSymbolAddress((void**)&bufB, g_bufB);
    cudaGetSymbolAddress((void**)&dinv, g_dinv);
    cudaGetSymbolAddress((void**)&cnt, g_count);
    cudaGetSymbolAddress((void**)&offs, g_offs);
    cudaGetSymbolAddress((void**)&cur, g_cursor);
    cudaGetSymbolAddress((void**)&bsums, g_bsums);
    cudaGetSymbolAddress((void**)&csrc, g_csrc);
    cudaGetSymbolAddress((void**)&ccoef, g_ccoef);
    cudaGetSymbolAddress((void**)&stats, g_stats);

    cudaFuncSetAttribute(gemm_tc, cudaFuncAttributeMaxDynamicSharedMemorySize, GSMEM);

    const int* src = ei;
    const int* dst = ei + EE;

    const int TB = 256;
    const int gridN  = (NN + TB - 1) / TB;
    const int gridE  = (EE + TB - 1) / TB;
    const int gridG  = (NN + 127) / 128;   // 782
    const int gridAg = (NN * 32 + TB - 1) / TB;
    const int nScanB = (NN + 1023) / 1024;

    // degrees + CSR build
    zero_f<<<gridN, TB>>>(dinv, NN);
    zero_i<<<gridN, TB>>>(cnt, NN);
    hist_kernel<<<gridE, TB>>>(src, dst, ea, dinv, cnt);
    dinv_kernel<<<gridN, TB>>>(dinv);
    scan1<<<nScanB, 256>>>(cnt, offs + 1, bsums, NN);
    scan2<<<1, 128>>>(bsums, nScanB);
    scan3<<<nScanB, 256>>>(offs + 1, bsums, NN, offs);
    copy_i<<<gridN, TB>>>(cur, offs, NN);
    fill_kernel<<<gridE, TB>>>(src, dst, ea, dinv, cur, csrc, ccoef);

    // GCN layer 0: bufA = x @ Wg0 ; agg -> bufB = relu(gcn0)
    gemm_tc<<<gridG, 256, GSMEM>>>(x, Wg0, nullptr, nullptr, bufA, NN, 0);
    agg_kernel<<<gridAg, TB>>>(bufA, dinv, offs, csrc, ccoef, bg0, bufB, 1);
    zero_f<<<1, 256>>>(stats, 256);
    bn_stats<<<gridG, 256>>>(bufB, stats, NN);
    bn_finalize<<<1, 128>>>(stats, gamma0, beta0);

    // GCN layer 1: bufA = bn0(bufB) @ Wg1 (affine fused) ; agg -> bufB = relu(gcn1)
    gemm_tc<<<gridG, 256, GSMEM>>>(bufB, Wg1, stats, nullptr, bufA, NN, 0);
    agg_kernel<<<gridAg, TB>>>(bufA, dinv, offs, csrc, ccoef, bg1, bufB, 1);
    zero_f<<<1, 256>>>(stats, 256);
    bn_stats<<<gridG, 256>>>(bufB, stats, NN);
    bn_finalize<<<1, 128>>>(stats, gamma1, beta1);

    // MLP head: bufA = relu(bn1(bufB) @ Wl1 + bl1) ; h_out = bufA @ Wl2 + bl2
    gemm_tc<<<gridG, 256, GSMEM>>>(bufB, Wl1, stats, bl1, bufA, NN, 1);
    gemm_tc<<<gridG, 256, GSMEM>>>(bufA, Wl2, nullptr, bl2, h_out, NN, 0);

    // pooling + classifier
    pool_kernel<<<GG, 128>>>(h_out, batch, reps);
    classify_kernel<<<1, 128>>>(reps, Wc1, bc1, Wc2, bc2, logits);
}

// round 4
// speedup vs baseline: 1.5509x; 1.0667x over previous
#include <cuda_runtime.h>
#include <cstdint>

#define NN 100000
#define EE 1600000
#define DD 128
#define GG 64
#define CC 2
#define EPSBN 1e-5f

// ---------------- scratch (static device globals; no allocation) ----------------
__device__ float g_bufA[(size_t)NN * DD];
__device__ float g_bufB[(size_t)NN * DD];
__device__ float g_dinv[NN];
__device__ int   g_count[NN];
__device__ int   g_offs[NN + 1];
__device__ int   g_cursor[NN];
__device__ int   g_bsums[512];
__device__ int2  g_cpack[EE];
__device__ float g_stats[2 * DD];
__device__ float g_pool[GG * 8 * DD];
__device__ float g_pcnt[GG];

// ---------------- helpers ----------------
__device__ __forceinline__ uint32_t cvt_tf32(float x) {
    uint32_t u;
    asm("cvt.rna.tf32.f32 %0, %1;" : "=r"(u) : "f"(x));
    return u;
}
__device__ __forceinline__ uint32_t smem_u32(const void* p) {
    uint32_t a;
    asm("{ .reg .u64 t; cvta.to.shared.u64 t, %1; cvt.u32.u64 %0, t; }" : "=r"(a) : "l"(p));
    return a;
}
__device__ __forceinline__ void mma_tf32(float* d, const uint32_t* a, const uint32_t* b) {
    asm volatile(
        "mma.sync.aligned.m16n8k8.row.col.f32.tf32.tf32.f32 "
        "{%0,%1,%2,%3}, {%4,%5,%6,%7}, {%8,%9}, {%0,%1,%2,%3};"
        : "+f"(d[0]), "+f"(d[1]), "+f"(d[2]), "+f"(d[3])
        : "r"(a[0]), "r"(a[1]), "r"(a[2]), "r"(a[3]), "r"(b[0]), "r"(b[1]));
}
__device__ __forceinline__ void ldsm4(uint32_t* a, uint32_t addr) {
    asm volatile("ldmatrix.sync.aligned.m8n8.x4.shared.b16 {%0,%1,%2,%3}, [%4];"
        : "=r"(a[0]), "=r"(a[1]), "=r"(a[2]), "=r"(a[3]) : "r"(addr));
}

#define PA 132
#define PB 136
#define GSMEM ((128 * PA + 128 * PB) * 4)
#define FSMEM ((128 * PA + 2 * 128 * PB) * 4)

// ---------------- utility ----------------
__global__ void zero2(float* a, int* b, int n) {
    int i = blockIdx.x * blockDim.x + threadIdx.x;
    if (i < n) { a[i] = 0.f; b[i] = 0; }
}

// ---------------- A staging (shared by gemm kernels) ----------------
__device__ __forceinline__ void stage_A(const float* __restrict__ A, const float* __restrict__ affine,
                                        float* As, int row0, int nrows, int tid) {
#pragma unroll
    for (int i = 0; i < 16; i++) {
        int f = i * 256 + tid;
        int row = f >> 5, kq = f & 31;
        float4 v = make_float4(0.f, 0.f, 0.f, 0.f);
        if (row0 + row < nrows)
            v = ((const float4*)A)[(size_t)(row0 + row) * 32 + kq];
        if (affine) {
            int k0 = kq * 4;
            v.x = v.x * affine[k0 + 0] + affine[128 + k0 + 0];
            v.y = v.y * affine[k0 + 1] + affine[128 + k0 + 1];
            v.z = v.z * affine[k0 + 2] + affine[128 + k0 + 2];
            v.w = v.w * affine[k0 + 3] + affine[128 + k0 + 3];
        }
        uint4 t;
        t.x = cvt_tf32(v.x); t.y = cvt_tf32(v.y); t.z = cvt_tf32(v.z); t.w = cvt_tf32(v.w);
        *(uint4*)&As[row * PA + kq * 4] = t;
    }
}
__device__ __forceinline__ void stage_B(const float* __restrict__ W, float* Bs, int tid) {
#pragma unroll
    for (int i = 0; i < 16; i++) {
        int f = i * 256 + tid;
        int k = f >> 5, nq = f & 31;
        float4 v = ((const float4*)W)[(size_t)k * 32 + nq];
        uint4 t;
        t.x = cvt_tf32(v.x); t.y = cvt_tf32(v.y); t.z = cvt_tf32(v.z); t.w = cvt_tf32(v.w);
        *(uint4*)&Bs[k * PB + nq * 4] = t;
    }
}

// ---------------- MMA mainloop (As/Bs -> acc) ----------------
__device__ __forceinline__ void mma_loop(uint32_t abase, const uint32_t* Bsu,
                                         int wn, int gid, int tg, float acc[4][4][4]) {
#pragma unroll
    for (int ks = 0; ks < 16; ks++) {
        int k0 = ks * 8;
        uint32_t a[4][4];
#pragma unroll
        for (int mi = 0; mi < 4; mi++)
            ldsm4(a[mi], abase + (uint32_t)(mi * 16 * PA * 4 + ks * 32));
        uint32_t b[4][2];
#pragma unroll
        for (int ni = 0; ni < 4; ni++) {
            int c = wn + ni * 8 + gid;
            b[ni][0] = Bsu[(k0 + tg) * PB + c];
            b[ni][1] = Bsu[(k0 + tg + 4) * PB + c];
        }
#pragma unroll
        for (int mi = 0; mi < 4; mi++)
#pragma unroll
            for (int ni = 0; ni < 4; ni++)
                mma_tf32(acc[mi][ni], a[mi], b[ni]);
    }
}

// ---------------- single GEMM: out = affine(A) @ W (+bias, relu) ----------------
__global__ void __launch_bounds__(256) gemm_tc(const float* __restrict__ A,
                                               const float* __restrict__ W,
                                               const float* __restrict__ affine,
                                               const float* __restrict__ bias,
                                               float* __restrict__ out,
                                               int nrows, int relu) {
    extern __shared__ float smem[];
    float* As = smem;
    float* Bs = smem + 128 * PA;
    int tid = threadIdx.x, wid = tid >> 5, lane = tid & 31;
    int row0 = blockIdx.x * 128;
    int gid = lane >> 2, tg = lane & 3;
    int wm = (wid >> 2) * 64, wn = (wid & 3) * 32;

    stage_A(A, affine, As, row0, nrows, tid);
    stage_B(W, Bs, tid);
    __syncthreads();

    int ldrow = wm + ((lane >> 3) & 1) * 8 + (lane & 7);
    uint32_t abase = smem_u32(As) + (uint32_t)((ldrow * PA + ((lane >> 4) << 2)) << 2);

    float acc[4][4][4];
#pragma unroll
    for (int mi = 0; mi < 4; mi++)
#pragma unroll
        for (int ni = 0; ni < 4; ni++)
#pragma unroll
            for (int j = 0; j < 4; j++) acc[mi][ni][j] = 0.f;

    mma_loop(abase, (const uint32_t*)Bs, wn, gid, tg, acc);

    float2 bv[4];
#pragma unroll
    for (int ni = 0; ni < 4; ni++) {
        int c = wn + ni * 8 + 2 * tg;
        if (bias) { bv[ni].x = bias[c]; bv[ni].y = bias[c + 1]; }
        else      { bv[ni].x = 0.f;     bv[ni].y = 0.f; }
    }
#pragma unroll
    for (int mi = 0; mi < 4; mi++) {
        int r_lo = row0 + wm + mi * 16 + gid;
        int r_hi = r_lo + 8;
#pragma unroll
        for (int ni = 0; ni < 4; ni++) {
            int c = wn + ni * 8 + 2 * tg;
            float2 v0, v1;
            v0.x = acc[mi][ni][0] + bv[ni].x;
            v0.y = acc[mi][ni][1] + bv[ni].y;
            v1.x = acc[mi][ni][2] + bv[ni].x;
            v1.y = acc[mi][ni][3] + bv[ni].y;
            if (relu) {
                v0.x = fmaxf(v0.x, 0.f); v0.y = fmaxf(v0.y, 0.f);
                v1.x = fmaxf(v1.x, 0.f); v1.y = fmaxf(v1.y, 0.f);
            }
            if (r_lo < nrows) *(float2*)(out + (size_t)r_lo * 128 + c) = v0;
            if (r_hi < nrows) *(float2*)(out + (size_t)r_hi * 128 + c) = v1;
        }
    }
}

// ---------------- fused MLP head: out = (relu(affine(A)@W1+b1)) @ W2 + b2 ----------------
__global__ void __launch_bounds__(256) mlp_fused(const float* __restrict__ A,
                                                 const float* __restrict__ W1,
                                                 const float* __restrict__ W2,
                                                 const float* __restrict__ affine,
                                                 const float* __restrict__ b1,
                                                 const float* __restrict__ b2,
                                                 float* __restrict__ out, int nrows) {
    extern __shared__ float smem[];
    float* As  = smem;
    float* Bs1 = smem + 128 * PA;
    float* Bs2 = Bs1 + 128 * PB;
    int tid = threadIdx.x, wid = tid >> 5, lane = tid & 31;
    int row0 = blockIdx.x * 128;
    int gid = lane >> 2, tg = lane & 3;
    int wm = (wid >> 2) * 64, wn = (wid & 3) * 32;

    stage_A(A, affine, As, row0, nrows, tid);
    stage_B(W1, Bs1, tid);
    stage_B(W2, Bs2, tid);
    __syncthreads();

    int ldrow = wm + ((lane >> 3) & 1) * 8 + (lane & 7);
    uint32_t abase = smem_u32(As) + (uint32_t)((ldrow * PA + ((lane >> 4) << 2)) << 2);

    float acc[4][4][4];
#pragma unroll
    for (int mi = 0; mi < 4; mi++)
#pragma unroll
        for (int ni = 0; ni < 4; ni++)
#pragma unroll
            for (int j = 0; j < 4; j++) acc[mi][ni][j] = 0.f;

    mma_loop(abase, (const uint32_t*)Bs1, wn, gid, tg, acc);
    __syncthreads();   // all fragment reads of As done

    // write T = relu(acc + b1) back into As as tf32
    uint32_t* Asu = (uint32_t*)As;
#pragma unroll
    for (int ni = 0; ni < 4; ni++) {
        int c = wn + ni * 8 + 2 * tg;
        float bx = b1[c], by = b1[c + 1];
#pragma unroll
        for (int mi = 0; mi < 4; mi++) {
            int r = wm + mi * 16 + gid;
            uint2 t0, t1;
            t0.x = cvt_tf32(fmaxf(acc[mi][ni][0] + bx, 0.f));
            t0.y = cvt_tf32(fmaxf(acc[mi][ni][1] + by, 0.f));
            t1.x = cvt_tf32(fmaxf(acc[mi][ni][2] + bx, 0.f));
            t1.y = cvt_tf32(fmaxf(acc[mi][ni][3] + by, 0.f));
            *(uint2*)&Asu[r * PA + c] = t0;
            *(uint2*)&Asu[(r + 8) * PA + c] = t1;
        }
    }
    __syncthreads();

#pragma unroll
    for (int mi = 0; mi < 4; mi++)
#pragma unroll
        for (int ni = 0; ni < 4; ni++)
#pragma unroll
            for (int j = 0; j < 4; j++) acc[mi][ni][j] = 0.f;

    mma_loop(abase, (const uint32_t*)Bs2, wn, gid, tg, acc);

    float2 bv[4];
#pragma unroll
    for (int ni = 0; ni < 4; ni++) {
        int c = wn + ni * 8 + 2 * tg;
        bv[ni].x = b2[c]; bv[ni].y = b2[c + 1];
    }
#pragma unroll
    for (int mi = 0; mi < 4; mi++) {
        int r_lo = row0 + wm + mi * 16 + gid;
        int r_hi = r_lo + 8;
#pragma unroll
        for (int ni = 0; ni < 4; ni++) {
            int c = wn + ni * 8 + 2 * tg;
            float2 v0, v1;
            v0.x = acc[mi][ni][0] + bv[ni].x;
            v0.y = acc[mi][ni][1] + bv[ni].y;
            v1.x = acc[mi][ni][2] + bv[ni].x;
            v1.y = acc[mi][ni][3] + bv[ni].y;
            if (r_lo < nrows) *(float2*)(out + (size_t)r_lo * 128 + c) = v0;
            if (r_hi < nrows) *(float2*)(out + (size_t)r_hi * 128 + c) = v1;
        }
    }
}

// ---------------- degree histogram ----------------
__global__ void hist_kernel(const int* __restrict__ src, const int* __restrict__ dst,
                            const float* __restrict__ attr, float* deg, int* cnt) {
    int e = blockIdx.x * blockDim.x + threadIdx.x;
    if (e >= EE) return;
    int d = dst[e];
    float w = attr[(size_t)e * 2 + 1];
    atomicAdd(&deg[d], w);
    atomicAdd(&cnt[d], 1);
}

__global__ void dinv_kernel(float* dinv) {
    int i = blockIdx.x * blockDim.x + threadIdx.x;
    if (i < NN) dinv[i] = rsqrtf(dinv[i] + 1.0f);
}

// ---------------- scan (3 kernels) ----------------
__global__ void scan1(const int* __restrict__ in, int* __restrict__ out,
                      int* __restrict__ bsums, int n) {
    __shared__ int sh[256];
    int tid = threadIdx.x;
    int base = blockIdx.x * 1024;
    int v[4]; int tsum = 0;
#pragma unroll
    for (int j = 0; j < 4; j++) {
        int idx = base + tid * 4 + j;
        v[j] = (idx < n) ? in[idx] : 0;
        tsum += v[j];
    }
    sh[tid] = tsum; __syncthreads();
#pragma unroll
    for (int off = 1; off < 256; off <<= 1) {
        int t = (tid >= off) ? sh[tid - off] : 0;
        __syncthreads();
        sh[tid] += t;
        __syncthreads();
    }
    int run = sh[tid] - tsum;
#pragma unroll
    for (int j = 0; j < 4; j++) {
        int idx = base + tid * 4 + j;
        run += v[j];
        if (idx < n) out[idx] = run;
    }
    if (tid == 255) bsums[blockIdx.x] = sh[255];
}

__global__ void scan2(int* bs, int nb) {
    __shared__ int sh[128];
    int tid = threadIdx.x;
    int orig = (tid < nb) ? bs[tid] : 0;
    sh[tid] = orig; __syncthreads();
#pragma unroll
    for (int off = 1; off < 128; off <<= 1) {
        int t = (tid >= off) ? sh[tid - off] : 0;
        __syncthreads();
        sh[tid] += t;
        __syncthreads();
    }
    if (tid < nb) bs[tid] = sh[tid] - orig;
}

__global__ void scan3(int* out /* offs+1 */, const int* __restrict__ bs, int n,
                      int* offs0, int* cur) {
    int tid = threadIdx.x;
    int base = blockIdx.x * 1024;
    int add = bs[blockIdx.x];
#pragma unroll
    for (int j = 0; j < 4; j++) {
        int idx = base + tid * 4 + j;
        if (idx < n) {
            int v = out[idx] + add;
            out[idx] = v;
            if (idx + 1 < n) cur[idx + 1] = v;   // cursor[i] = offs[i]
        }
    }
    if (blockIdx.x == 0 && tid == 0) { offs0[0] = 0; cur[0] = 0; }
}

// ---------------- CSR fill (packed src+coef) ----------------
__global__ void fill_kernel(const int* __restrict__ src, const int* __restrict__ dst,
                            const float* __restrict__ attr, const float* __restrict__ dinv,
                            int* cursor, int2* cpack) {
    int e = blockIdx.x * blockDim.x + threadIdx.x;
    if (e >= EE) return;
    int s = src[e], d = dst[e];
    float w = attr[(size_t)e * 2 + 1];
    int pos = atomicAdd(&cursor[d], 1);
    int2 q;
    q.x = s;
    q.y = __float_as_int(dinv[s] * w * dinv[d]);
    cpack[pos] = q;
}

// ---------------- GCN aggregation: warp per node (also zeroes bn stats) ----------------
__global__ void agg_kernel(const float* __restrict__ hw, const float* __restrict__ dinv,
                           const int* __restrict__ offs, const int2* __restrict__ cpack,
                           const float* __restrict__ bias, float* __restrict__ out,
                           float* stats) {
    if (blockIdx.x == 0 && threadIdx.x < 256) stats[threadIdx.x] = 0.f;
    int gtid = blockIdx.x * blockDim.x + threadIdx.x;
    int node = gtid >> 5;
    if (node >= NN) return;
    int lane = threadIdx.x & 31;

    float di = dinv[node];
    float self = di * di;
    float4 h0 = ((const float4*)(hw + (size_t)node * 128))[lane];
    float4 acc;
    acc.x = self * h0.x; acc.y = self * h0.y; acc.z = self * h0.z; acc.w = self * h0.w;

    int p0 = offs[node], p1 = offs[node + 1];
#pragma unroll 4
    for (int p = p0; p < p1; p++) {
        int2 q = cpack[p];
        float c = __int_as_float(q.y);
        float4 v = ((const float4*)(hw + (size_t)q.x * 128))[lane];
        acc.x += c * v.x; acc.y += c * v.y; acc.z += c * v.z; acc.w += c * v.w;
    }
    float4 b = ((const float4*)bias)[lane];
    acc.x = fmaxf(acc.x + b.x, 0.f);
    acc.y = fmaxf(acc.y + b.y, 0.f);
    acc.z = fmaxf(acc.z + b.z, 0.f);
    acc.w = fmaxf(acc.w + b.w, 0.f);
    ((float4*)(out + (size_t)node * 128))[lane] = acc;
}

// ---------------- BatchNorm stats ----------------
__global__ void bn_stats(const float* __restrict__ X, float* stats, int nrows) {
    __shared__ float sh[256];
    int d = threadIdx.x & 127;
    int half = threadIdx.x >> 7;
    int r0 = blockIdx.x * 128;
    int rend = min(r0 + 128, nrows);
    float s = 0.f, q = 0.f;
    for (int r = r0 + half; r < rend; r += 2) {
        float v = X[(size_t)r * 128 + d];
        s += v; q += v * v;
    }
    sh[threadIdx.x] = s; __syncthreads();
    if (half == 0) atomicAdd(&stats[d], s + sh[128 + d]);
    __syncthreads();
    sh[threadIdx.x] = q; __syncthreads();
    if (half == 0) atomicAdd(&stats[128 + d], q + sh[128 + d]);
}

__global__ void bn_finalize(float* stats, const float* __restrict__ gamma,
                            const float* __restrict__ beta) {
    int d = threadIdx.x;
    float invn = 1.0f / (float)NN;
    float m = stats[d] * invn;
    float v = stats[128 + d] * invn - m * m;
    float sc = gamma[d] * rsqrtf(v + EPSBN);
    stats[d] = sc;
    stats[128 + d] = beta[d] - m * sc;
}

// ---------------- pooling: 8 partial blocks per group ----------------
__global__ void pool_partial(const float* __restrict__ h, const int* __restrict__ batch,
                             float* __restrict__ part, float* __restrict__ pcnt) {
    int g = blockIdx.x >> 3, c = blockIdx.x & 7;
    int lo = 0, hi = NN;
    while (lo < hi) { int mid = (lo + hi) >> 1; if (batch[mid] < g) lo = mid + 1; else hi = mid; }
    int start = lo;
    lo = start; hi = NN;
    while (lo < hi) { int mid = (lo + hi) >> 1; if (batch[mid] < g + 1) lo = mid + 1; else hi = mid; }
    int end = lo;
    int len = end - start;
    int b0 = start + (int)(((long long)len * c) >> 3);
    int b1 = start + (int)(((long long)len * (c + 1)) >> 3);
    int d = threadIdx.x;
    float s = 0.f;
    for (int r = b0; r < b1; r++) s += h[(size_t)r * 128 + d];
    part[(g * 8 + c) * 128 + d] = s;
    if (c == 0 && d == 0) pcnt[g] = (float)len;
}

// ---------------- classifier (+pool reduce) ----------------
__global__ void classify_kernel(const float* __restrict__ part, const float* __restrict__ pcnt,
                                float* __restrict__ reps,
                                const float* __restrict__ Wc1, const float* __restrict__ bc1,
                                const float* __restrict__ Wc2, const float* __restrict__ bc2,
                                float* __restrict__ logits) {
    __shared__ float rsh[128];
    __shared__ float tsh[128];
    int d = threadIdx.x;
    for (int g = 0; g < GG; g++) {
        float s = 0.f;
#pragma unroll
        for (int c = 0; c < 8; c++) s += part[(g * 8 + c) * 128 + d];
        float inv = 1.0f / fmaxf(pcnt[g], 1.0f);
        float rv = s * inv;
        reps[g * 128 + d] = rv;
        rsh[d] = rv;
        __syncthreads();
        float t = bc1[d];
#pragma unroll
        for (int k = 0; k < 128; k++) t += rsh[k] * Wc1[k * 128 + d];
        tsh[d] = fmaxf(t, 0.f);
        __syncthreads();
        if (d < CC) {
            float s2 = bc2[d];
#pragma unroll
            for (int k = 0; k < 128; k++) s2 += tsh[k] * Wc2[k * CC + d];
            logits[g * CC + d] = s2;
        }
        __syncthreads();
    }
}

// ---------------- launch ----------------
extern "C" void kernel_launch(void* const* d_in, const int* in_sizes, int n_in,
                              void* d_out, int out_size) {
    const float* x     = (const float*)d_in[0];
    const int*   ei    = (const int*)d_in[1];
    const float* ea    = (const float*)d_in[2];
    const int*   batch = (const int*)d_in[3];
    const float* Wg0 = (const float*)d_in[4],  *bg0 = (const float*)d_in[5];
    const float* gamma0 = (const float*)d_in[6], *beta0 = (const float*)d_in[7];
    const float* Wg1 = (const float*)d_in[8],  *bg1 = (const float*)d_in[9];
    const float* gamma1 = (const float*)d_in[10], *beta1 = (const float*)d_in[11];
    const float* Wl1 = (const float*)d_in[12], *bl1 = (const float*)d_in[13];
    const float* Wl2 = (const float*)d_in[14], *bl2 = (const float*)d_in[15];
    const float* Wc1 = (const float*)d_in[16], *bc1 = (const float*)d_in[17];
    const float* Wc2 = (const float*)d_in[18], *bc2 = (const float*)d_in[19];

    float* out = (float*)d_out;
    float* h_out  = out;
    float* reps   = out + (size_t)NN * DD;
    float* logits = out + (size_t)NN * DD + (size_t)GG * DD;

    float *bufA, *bufB, *dinv, *stats, *pool, *pcnt;
    int *cnt, *offs, *cur, *bsums;
    int2 *cpack;
    cudaGetSymbolAddress((void**)&bufA, g_bufA);
    cudaGetSymbolAddress((void**)&bufB, g_bufB);
    cudaGetSymbolAddress((void**)&dinv, g_dinv);
    cudaGetSymbolAddress((void**)&cnt, g_count);
    cudaGetSymbolAddress((void**)&offs, g_offs);
    cudaGetSymbolAddress((void**)&cur, g_cursor);
    cudaGetSymbolAddress((void**)&bsums, g_bsums);
    cudaGetSymbolAddress((void**)&cpack, g_cpack);
    cudaGetSymbolAddress((void**)&stats, g_stats);
    cudaGetSymbolAddress((void**)&pool, g_pool);
    cudaGetSymbolAddress((void**)&pcnt, g_pcnt);

    cudaFuncSetAttribute(gemm_tc, cudaFuncAttributeMaxDynamicSharedMemorySize, GSMEM);
    cudaFuncSetAttribute(mlp_fused, cudaFuncAttributeMaxDynamicSharedMemorySize, FSMEM);

    const int* src = ei;
    const int* dst = ei + EE;

    const int TB = 256;
    const int gridN  = (NN + TB - 1) / TB;
    const int gridE  = (EE + TB - 1) / TB;
    const int gridG  = (NN + 127) / 128;   // 782
    const int gridAg = (NN * 32 + TB - 1) / TB;
    const int nScanB = (NN + 1023) / 1024;

    // 1-3: degree prep
    zero2<<<gridN, TB>>>(dinv, cnt, NN);
    hist_kernel<<<gridE, TB>>>(src, dst, ea, dinv, cnt);
    dinv_kernel<<<gridN, TB>>>(dinv);

    // 4: layer-0 GEMM (independent of CSR) — placed 4th for ncu capture
    gemm_tc<<<gridG, 256, GSMEM>>>(x, Wg0, nullptr, nullptr, bufA, NN, 0);

    // 5-8: scan + CSR fill
    scan1<<<nScanB, 256>>>(cnt, offs + 1, bsums, NN);
    scan2<<<1, 128>>>(bsums, nScanB);
    scan3<<<nScanB, 256>>>(offs + 1, bsums, NN, offs, cur);
    fill_kernel<<<gridE, TB>>>(src, dst, ea, dinv, cur, cpack);

    // GCN layer 0
    agg_kernel<<<gridAg, TB>>>(bufA, dinv, offs, cpack, bg0, bufB, stats);
    bn_stats<<<gridG, 256>>>(bufB, stats, NN);
    bn_finalize<<<1, 128>>>(stats, gamma0, beta0);

    // GCN layer 1 (bn0 affine fused into GEMM A-load)
    gemm_tc<<<gridG, 256, GSMEM>>>(bufB, Wg1, stats, nullptr, bufA, NN, 0);
    agg_kernel<<<gridAg, TB>>>(bufA, dinv, offs, cpack, bg1, bufB, stats);
    bn_stats<<<gridG, 256>>>(bufB, stats, NN);
    bn_finalize<<<1, 128>>>(stats, gamma1, beta1);

    // fused MLP head (bn1 affine fused into A-load)
    mlp_fused<<<gridG, 256, FSMEM>>>(bufB, Wl1, Wl2, stats, bl1, bl2, h_out, NN);

    // pooling + classifier
    pool_partial<<<GG * 8, 128>>>(h_out, batch, pool, pcnt);
    classify_kernel<<<1, 128>>>(pool, pcnt, reps, Wc1, bc1, Wc2, bc2, logits);
}

// round 5
// speedup vs baseline: 2.0730x; 1.3367x over previous
#include <cuda_runtime.h>
#include <cstdint>

#define NN 100000
#define EE 1600000
#define DD 128
#define GG 64
#define CC 2
#define EPSBN 1e-5f

// ---------------- scratch (static device globals; no allocation) ----------------
__device__ float g_bufA[(size_t)NN * DD];
__device__ float g_bufB[(size_t)NN * DD];
__device__ float g_dinv[NN];
__device__ int   g_count[NN];
__device__ int   g_offs[NN + 1];
__device__ int   g_cursor[NN];
__device__ int   g_bsums[512];
__device__ int2  g_cpack[EE];
__device__ float g_stats[2 * DD];
__device__ float g_pool[GG * 8 * DD];
__device__ float g_pcnt[GG];
__device__ float g_wt[4 * 128 * 128];   // tf32-preconverted weights, row-major [k][n]

// ---------------- helpers ----------------
__device__ __forceinline__ uint32_t cvt_tf32(float x) {
    uint32_t u;
    asm("cvt.rna.tf32.f32 %0, %1;" : "=r"(u) : "f"(x));
    return u;
}
__device__ __forceinline__ uint32_t smem_u32(const void* p) {
    uint32_t a;
    asm("{ .reg .u64 t; cvta.to.shared.u64 t, %1; cvt.u32.u64 %0, t; }" : "=r"(a) : "l"(p));
    return a;
}
__device__ __forceinline__ void mma_tf32(float* d, const uint32_t* a, const uint32_t* b) {
    asm volatile(
        "mma.sync.aligned.m16n8k8.row.col.f32.tf32.tf32.f32 "
        "{%0,%1,%2,%3}, {%4,%5,%6,%7}, {%8,%9}, {%0,%1,%2,%3};"
        : "+f"(d[0]), "+f"(d[1]), "+f"(d[2]), "+f"(d[3])
        : "r"(a[0]), "r"(a[1]), "r"(a[2]), "r"(a[3]), "r"(b[0]), "r"(b[1]));
}
__device__ __forceinline__ void ldsm4(uint32_t* a, uint32_t addr) {
    asm volatile("ldmatrix.sync.aligned.m8n8.x4.shared.b16 {%0,%1,%2,%3}, [%4];"
        : "=r"(a[0]), "=r"(a[1]), "=r"(a[2]), "=r"(a[3]) : "r"(addr));
}
__device__ __forceinline__ void cp_async16(uint32_t saddr, const void* gaddr) {
    asm volatile("cp.async.cg.shared.global [%0], [%1], 16;" :: "r"(saddr), "l"(gaddr));
}

#define PA 132
#define PB 136      // mlp_fused B pitch
#define PB2 72      // gemm_tc B pitch (72 mod 32 == 8: conflict-free)
#define GSMEM ((128 * PA + 128 * PB2) * 4)
#define FSMEM ((128 * PA + 2 * 128 * PB) * 4)

// ---------------- utility ----------------
__global__ void zero2(float* a, int* b, int n) {
    int i = blockIdx.x * blockDim.x + threadIdx.x;
    if (i < n) { a[i] = 0.f; b[i] = 0; }
}

// ---------------- weight tf32 pre-conversion ----------------
__global__ void wprep(const float* __restrict__ W0, const float* __restrict__ W1,
                      const float* __restrict__ W2, const float* __restrict__ W3,
                      float* __restrict__ wt) {
    int i = blockIdx.x * blockDim.x + threadIdx.x;   // 0..65535
    const float* W = (i < 16384) ? W0 : (i < 32768) ? W1 : (i < 49152) ? W2 : W3;
    wt[i] = __uint_as_float(cvt_tf32(W[i & 16383]));
}

// ---------------- A staging (NT threads) ----------------
template<int NT>
__device__ __forceinline__ void stage_A(const float* __restrict__ A, const float* __restrict__ affine,
                                        float* As, int row0, int nrows, int tid) {
#pragma unroll
    for (int i = 0; i < 4096 / NT; i++) {
        int f = i * NT + tid;
        int row = f >> 5, kq = f & 31;
        float4 v = make_float4(0.f, 0.f, 0.f, 0.f);
        if (row0 + row < nrows)
            v = ((const float4*)A)[(size_t)(row0 + row) * 32 + kq];
        if (affine) {
            int k0 = kq * 4;
            v.x = v.x * affine[k0 + 0] + affine[128 + k0 + 0];
            v.y = v.y * affine[k0 + 1] + affine[128 + k0 + 1];
            v.z = v.z * affine[k0 + 2] + affine[128 + k0 + 2];
            v.w = v.w * affine[k0 + 3] + affine[128 + k0 + 3];
        }
        uint4 t;
        t.x = cvt_tf32(v.x); t.y = cvt_tf32(v.y); t.z = cvt_tf32(v.z); t.w = cvt_tf32(v.w);
        *(uint4*)&As[row * PA + kq * 4] = t;
    }
}

// ---------------- MMA mainloop ----------------
template<int PBX>
__device__ __forceinline__ void mma_loop(uint32_t abase, const uint32_t* Bsu,
                                         int wn, int gid, int tg, float acc[4][4][4]) {
#pragma unroll
    for (int ks = 0; ks < 16; ks++) {
        int k0 = ks * 8;
        uint32_t a[4][4];
#pragma unroll
        for (int mi = 0; mi < 4; mi++)
            ldsm4(a[mi], abase + (uint32_t)(mi * 16 * PA * 4 + ks * 32));
        uint32_t b[4][2];
#pragma unroll
        for (int ni = 0; ni < 4; ni++) {
            int c = wn + ni * 8 + gid;
            b[ni][0] = Bsu[(k0 + tg) * PBX + c];
            b[ni][1] = Bsu[(k0 + tg + 4) * PBX + c];
        }
#pragma unroll
        for (int mi = 0; mi < 4; mi++)
#pragma unroll
            for (int ni = 0; ni < 4; ni++)
                mma_tf32(acc[mi][ni], a[mi], b[ni]);
    }
}

// ---------------- GEMM: 128 threads, tile 128M x 64N, grid (rows/128, 2) ----------------
__global__ void __launch_bounds__(128) gemm_tc(const float* __restrict__ A,
                                               const float* __restrict__ WT,   // tf32 pre-converted
                                               const float* __restrict__ affine,
                                               const float* __restrict__ bias,
                                               float* __restrict__ out,
                                               int nrows, int relu) {
    extern __shared__ float smem[];
    float* As = smem;               // [128][PA]
    float* Bs = smem + 128 * PA;    // [128][PB2]
    int tid = threadIdx.x, wid = tid >> 5, lane = tid & 31;
    int row0 = blockIdx.x * 128, n0 = blockIdx.y * 64;
    int gid = lane >> 2, tg = lane & 3;
    int wm = (wid >> 1) * 64, wn = (wid & 1) * 32;

    // B staging via cp.async (issued first, lands during A staging)
    uint32_t bbase = smem_u32(Bs);
#pragma unroll
    for (int i = 0; i < 16; i++) {
        int f = i * 128 + tid;
        int k = f >> 4, q = f & 15;
        cp_async16(bbase + (uint32_t)((k * PB2 + q * 4) << 2),
                   WT + (size_t)k * 128 + n0 + q * 4);
    }
    asm volatile("cp.async.commit_group;");

    stage_A<128>(A, affine, As, row0, nrows, tid);

    asm volatile("cp.async.wait_group 0;" ::: "memory");
    __syncthreads();

    int ldrow = wm + ((lane >> 3) & 1) * 8 + (lane & 7);
    uint32_t abase = smem_u32(As) + (uint32_t)((ldrow * PA + ((lane >> 4) << 2)) << 2);

    float acc[4][4][4];
#pragma unroll
    for (int mi = 0; mi < 4; mi++)
#pragma unroll
        for (int ni = 0; ni < 4; ni++)
#pragma unroll
            for (int j = 0; j < 4; j++) acc[mi][ni][j] = 0.f;

    mma_loop<PB2>(abase, (const uint32_t*)Bs, wn, gid, tg, acc);

    float2 bv[4];
#pragma unroll
    for (int ni = 0; ni < 4; ni++) {
        int c = n0 + wn + ni * 8 + 2 * tg;
        if (bias) { bv[ni].x = bias[c]; bv[ni].y = bias[c + 1]; }
        else      { bv[ni].x = 0.f;     bv[ni].y = 0.f; }
    }
#pragma unroll
    for (int mi = 0; mi < 4; mi++) {
        int r_lo = row0 + wm + mi * 16 + gid;
        int r_hi = r_lo + 8;
#pragma unroll
        for (int ni = 0; ni < 4; ni++) {
            int c = n0 + wn + ni * 8 + 2 * tg;
            float2 v0, v1;
            v0.x = acc[mi][ni][0] + bv[ni].x;
            v0.y = acc[mi][ni][1] + bv[ni].y;
            v1.x = acc[mi][ni][2] + bv[ni].x;
            v1.y = acc[mi][ni][3] + bv[ni].y;
            if (relu) {
                v0.x = fmaxf(v0.x, 0.f); v0.y = fmaxf(v0.y, 0.f);
                v1.x = fmaxf(v1.x, 0.f); v1.y = fmaxf(v1.y, 0.f);
            }
            if (r_lo < nrows) *(float2*)(out + (size_t)r_lo * 128 + c) = v0;
            if (r_hi < nrows) *(float2*)(out + (size_t)r_hi * 128 + c) = v1;
        }
    }
}

// ---------------- fused MLP head: out = (relu(affine(A)@W1+b1)) @ W2 + b2 ----------------
__global__ void __launch_bounds__(256) mlp_fused(const float* __restrict__ A,
                                                 const float* __restrict__ W1T,
                                                 const float* __restrict__ W2T,
                                                 const float* __restrict__ affine,
                                                 const float* __restrict__ b1,
                                                 const float* __restrict__ b2,
                                                 float* __restrict__ out, int nrows) {
    extern __shared__ float smem[];
    float* As  = smem;
    float* Bs1 = smem + 128 * PA;
    float* Bs2 = Bs1 + 128 * PB;
    int tid = threadIdx.x, wid = tid >> 5, lane = tid & 31;
    int row0 = blockIdx.x * 128;
    int gid = lane >> 2, tg = lane & 3;
    int wm = (wid >> 2) * 64, wn = (wid & 3) * 32;

    // both B tiles via cp.async
    uint32_t b1base = smem_u32(Bs1), b2base = smem_u32(Bs2);
#pragma unroll
    for (int i = 0; i < 16; i++) {
        int f = i * 256 + tid;
        int k = f >> 5, q = f & 31;
        cp_async16(b1base + (uint32_t)((k * PB + q * 4) << 2), W1T + (size_t)k * 128 + q * 4);
        cp_async16(b2base + (uint32_t)((k * PB + q * 4) << 2), W2T + (size_t)k * 128 + q * 4);
    }
    asm volatile("cp.async.commit_group;");

    stage_A<256>(A, affine, As, row0, nrows, tid);

    asm volatile("cp.async.wait_group 0;" ::: "memory");
    __syncthreads();

    int ldrow = wm + ((lane >> 3) & 1) * 8 + (lane & 7);
    uint32_t abase = smem_u32(As) + (uint32_t)((ldrow * PA + ((lane >> 4) << 2)) << 2);

    float acc[4][4][4];
#pragma unroll
    for (int mi = 0; mi < 4; mi++)
#pragma unroll
        for (int ni = 0; ni < 4; ni++)
#pragma unroll
            for (int j = 0; j < 4; j++) acc[mi][ni][j] = 0.f;

    mma_loop<PB>(abase, (const uint32_t*)Bs1, wn, gid, tg, acc);
    __syncthreads();

    // write T = relu(acc + b1) back into As as tf32
    uint32_t* Asu = (uint32_t*)As;
#pragma unroll
    for (int ni = 0; ni < 4; ni++) {
        int c = wn + ni * 8 + 2 * tg;
        float bx = b1[c], by = b1[c + 1];
#pragma unroll
        for (int mi = 0; mi < 4; mi++) {
            int r = wm + mi * 16 + gid;
            uint2 t0, t1;
            t0.x = cvt_tf32(fmaxf(acc[mi][ni][0] + bx, 0.f));
            t0.y = cvt_tf32(fmaxf(acc[mi][ni][1] + by, 0.f));
            t1.x = cvt_tf32(fmaxf(acc[mi][ni][2] + bx, 0.f));
            t1.y = cvt_tf32(fmaxf(acc[mi][ni][3] + by, 0.f));
            *(uint2*)&Asu[r * PA + c] = t0;
            *(uint2*)&Asu[(r + 8) * PA + c] = t1;
        }
    }
    __syncthreads();

#pragma unroll
    for (int mi = 0; mi < 4; mi++)
#pragma unroll
        for (int ni = 0; ni < 4; ni++)
#pragma unroll
            for (int j = 0; j < 4; j++) acc[mi][ni][j] = 0.f;

    mma_loop<PB>(abase, (const uint32_t*)Bs2, wn, gid, tg, acc);

    float2 bv[4];
#pragma unroll
    for (int ni = 0; ni < 4; ni++) {
        int c = wn + ni * 8 + 2 * tg;
        bv[ni].x = b2[c]; bv[ni].y = b2[c + 1];
    }
#pragma unroll
    for (int mi = 0; mi < 4; mi++) {
        int r_lo = row0 + wm + mi * 16 + gid;
        int r_hi = r_lo + 8;
#pragma unroll
        for (int ni = 0; ni < 4; ni++) {
            int c = wn + ni * 8 + 2 * tg;
            float2 v0, v1;
            v0.x = acc[mi][ni][0] + bv[ni].x;
            v0.y = acc[mi][ni][1] + bv[ni].y;
            v1.x = acc[mi][ni][2] + bv[ni].x;
            v1.y = acc[mi][ni][3] + bv[ni].y;
            if (r_lo < nrows) *(float2*)(out + (size_t)r_lo * 128 + c) = v0;
            if (r_hi < nrows) *(float2*)(out + (size_t)r_hi * 128 + c) = v1;
        }
    }
}

// ---------------- degree histogram ----------------
__global__ void hist_kernel(const int* __restrict__ src, const int* __restrict__ dst,
                            const float* __restrict__ attr, float* deg, int* cnt) {
    int e = blockIdx.x * blockDim.x + threadIdx.x;
    if (e >= EE) return;
    int d = dst[e];
    float w = attr[(size_t)e * 2 + 1];
    atomicAdd(&deg[d], w);
    atomicAdd(&cnt[d], 1);
}

__global__ void dinv_kernel(float* dinv) {
    int i = blockIdx.x * blockDim.x + threadIdx.x;
    if (i < NN) dinv[i] = rsqrtf(dinv[i] + 1.0f);
}

// ---------------- scan ----------------
__global__ void scan1(const int* __restrict__ in, int* __restrict__ out,
                      int* __restrict__ bsums, int n) {
    __shared__ int sh[256];
    int tid = threadIdx.x;
    int base = blockIdx.x * 1024;
    int v[4]; int tsum = 0;
#pragma unroll
    for (int j = 0; j < 4; j++) {
        int idx = base + tid * 4 + j;
        v[j] = (idx < n) ? in[idx] : 0;
        tsum += v[j];
    }
    sh[tid] = tsum; __syncthreads();
#pragma unroll
    for (int off = 1; off < 256; off <<= 1) {
        int t = (tid >= off) ? sh[tid - off] : 0;
        __syncthreads();
        sh[tid] += t;
        __syncthreads();
    }
    int run = sh[tid] - tsum;
#pragma unroll
    for (int j = 0; j < 4; j++) {
        int idx = base + tid * 4 + j;
        run += v[j];
        if (idx < n) out[idx] = run;
    }
    if (tid == 255) bsums[blockIdx.x] = sh[255];
}

__global__ void scan2(int* bs, int nb) {
    __shared__ int sh[128];
    int tid = threadIdx.x;
    int orig = (tid < nb) ? bs[tid] : 0;
    sh[tid] = orig; __syncthreads();
#pragma unroll
    for (int off = 1; off < 128; off <<= 1) {
        int t = (tid >= off) ? sh[tid - off] : 0;
        __syncthreads();
        sh[tid] += t;
        __syncthreads();
    }
    if (tid < nb) bs[tid] = sh[tid] - orig;
}

__global__ void scan3(int* out /* offs+1 */, const int* __restrict__ bs, int n,
                      int* offs0, int* cur) {
    int tid = threadIdx.x;
    int base = blockIdx.x * 1024;
    int add = bs[blockIdx.x];
#pragma unroll
    for (int j = 0; j < 4; j++) {
        int idx = base + tid * 4 + j;
        if (idx < n) {
            int v = out[idx] + add;
            out[idx] = v;
            if (idx + 1 < n) cur[idx + 1] = v;
        }
    }
    if (blockIdx.x == 0 && tid == 0) { offs0[0] = 0; cur[0] = 0; }
}

// ---------------- CSR fill ----------------
__global__ void fill_kernel(const int* __restrict__ src, const int* __restrict__ dst,
                            const float* __restrict__ attr, const float* __restrict__ dinv,
                            int* cursor, int2* cpack) {
    int e = blockIdx.x * blockDim.x + threadIdx.x;
    if (e >= EE) return;
    int s = src[e], d = dst[e];
    float w = attr[(size_t)e * 2 + 1];
    int pos = atomicAdd(&cursor[d], 1);
    int2 q;
    q.x = s;
    q.y = __float_as_int(dinv[s] * w * dinv[d]);
    cpack[pos] = q;
}

// ---------------- GCN aggregation ----------------
__global__ void agg_kernel(const float* __restrict__ hw, const float* __restrict__ dinv,
                           const int* __restrict__ offs, const int2* __restrict__ cpack,
                           const float* __restrict__ bias, float* __restrict__ out,
                           float* stats) {
    if (blockIdx.x == 0 && threadIdx.x < 256) stats[threadIdx.x] = 0.f;
    int gtid = blockIdx.x * blockDim.x + threadIdx.x;
    int node = gtid >> 5;
    if (node >= NN) return;
    int lane = threadIdx.x & 31;

    float di = dinv[node];
    float self = di * di;
    float4 h0 = ((const float4*)(hw + (size_t)node * 128))[lane];
    float4 acc;
    acc.x = self * h0.x; acc.y = self * h0.y; acc.z = self * h0.z; acc.w = self * h0.w;

    int p0 = offs[node], p1 = offs[node + 1];
#pragma unroll 4
    for (int p = p0; p < p1; p++) {
        int2 q = cpack[p];
        float c = __int_as_float(q.y);
        float4 v = ((const float4*)(hw + (size_t)q.x * 128))[lane];
        acc.x += c * v.x; acc.y += c * v.y; acc.z += c * v.z; acc.w += c * v.w;
    }
    float4 b = ((const float4*)bias)[lane];
    acc.x = fmaxf(acc.x + b.x, 0.f);
    acc.y = fmaxf(acc.y + b.y, 0.f);
    acc.z = fmaxf(acc.z + b.z, 0.f);
    acc.w = fmaxf(acc.w + b.w, 0.f);
    ((float4*)(out + (size_t)node * 128))[lane] = acc;
}

// ---------------- BatchNorm stats (296 blocks: low atomic contention) ----------------
#define BNBLK 296
#define BNCHUNK 338
__global__ void bn_stats(const float* __restrict__ X, float* stats, int nrows) {
    __shared__ float sh[256];
    int d = threadIdx.x & 127;
    int half = threadIdx.x >> 7;
    int r0 = blockIdx.x * BNCHUNK;
    int rend = min(r0 + BNCHUNK, nrows);
    float s = 0.f, q = 0.f;
    for (int r = r0 + half; r < rend; r += 2) {
        float v = X[(size_t)r * 128 + d];
        s += v; q += v * v;
    }
    sh[threadIdx.x] = s; __syncthreads();
    if (half == 0) atomicAdd(&stats[d], s + sh[128 + d]);
    __syncthreads();
    sh[threadIdx.x] = q; __syncthreads();
    if (half == 0) atomicAdd(&stats[128 + d], q + sh[128 + d]);
}

__global__ void bn_finalize(float* stats, const float* __restrict__ gamma,
                            const float* __restrict__ beta) {
    int d = threadIdx.x;
    float invn = 1.0f / (float)NN;
    float m = stats[d] * invn;
    float v = stats[128 + d] * invn - m * m;
    float sc = gamma[d] * rsqrtf(v + EPSBN);
    stats[d] = sc;
    stats[128 + d] = beta[d] - m * sc;
}

// ---------------- pooling: 8 partial blocks per group ----------------
__global__ void pool_partial(const float* __restrict__ h, const int* __restrict__ batch,
                             float* __restrict__ part, float* __restrict__ pcnt) {
    int g = blockIdx.x >> 3, c = blockIdx.x & 7;
    int lo = 0, hi = NN;
    while (lo < hi) { int mid = (lo + hi) >> 1; if (batch[mid] < g) lo = mid + 1; else hi = mid; }
    int start = lo;
    lo = start; hi = NN;
    while (lo < hi) { int mid = (lo + hi) >> 1; if (batch[mid] < g + 1) lo = mid + 1; else hi = mid; }
    int end = lo;
    int len = end - start;
    int b0 = start + (int)(((long long)len * c) >> 3);
    int b1 = start + (int)(((long long)len * (c + 1)) >> 3);
    int d = threadIdx.x;
    float s = 0.f;
    for (int r = b0; r < b1; r++) s += h[(size_t)r * 128 + d];
    part[(g * 8 + c) * 128 + d] = s;
    if (c == 0 && d == 0) pcnt[g] = (float)len;
}

// ---------------- classifier: one block per group ----------------
__global__ void classify_kernel(const float* __restrict__ part, const float* __restrict__ pcnt,
                                float* __restrict__ reps,
                                const float* __restrict__ Wc1, const float* __restrict__ bc1,
                                const float* __restrict__ Wc2, const float* __restrict__ bc2,
                                float* __restrict__ logits) {
    __shared__ float rsh[128];
    __shared__ float tsh[128];
    int g = blockIdx.x;
    int d = threadIdx.x;
    float s = 0.f;
#pragma unroll
    for (int c = 0; c < 8; c++) s += part[(g * 8 + c) * 128 + d];
    float inv = 1.0f / fmaxf(pcnt[g], 1.0f);
    float rv = s * inv;
    reps[g * 128 + d] = rv;
    rsh[d] = rv;
    __syncthreads();
    float t = bc1[d];
#pragma unroll
    for (int k = 0; k < 128; k++) t += rsh[k] * Wc1[k * 128 + d];
    tsh[d] = fmaxf(t, 0.f);
    __syncthreads();
    if (d < CC) {
        float s2 = bc2[d];
#pragma unroll
        for (int k = 0; k < 128; k++) s2 += tsh[k] * Wc2[k * CC + d];
        logits[g * CC + d] = s2;
    }
}

// ---------------- launch ----------------
extern "C" void kernel_launch(void* const* d_in, const int* in_sizes, int n_in,
                              void* d_out, int out_size) {
    const float* x     = (const float*)d_in[0];
    const int*   ei    = (const int*)d_in[1];
    const float* ea    = (const float*)d_in[2];
    const int*   batch = (const int*)d_in[3];
    const float* Wg0 = (const float*)d_in[4],  *bg0 = (const float*)d_in[5];
    const float* gamma0 = (const float*)d_in[6], *beta0 = (const float*)d_in[7];
    const float* Wg1 = (const float*)d_in[8],  *bg1 = (const float*)d_in[9];
    const float* gamma1 = (const float*)d_in[10], *beta1 = (const float*)d_in[11];
    const float* Wl1 = (const float*)d_in[12], *bl1 = (const float*)d_in[13];
    const float* Wl2 = (const float*)d_in[14], *bl2 = (const float*)d_in[15];
    const float* Wc1 = (const float*)d_in[16], *bc1 = (const float*)d_in[17];
    const float* Wc2 = (const float*)d_in[18], *bc2 = (const float*)d_in[19];

    float* out = (float*)d_out;
    float* h_out  = out;
    float* reps   = out + (size_t)NN * DD;
    float* logits = out + (size_t)NN * DD + (size_t)GG * DD;

    float *bufA, *bufB, *dinv, *stats, *pool, *pcnt, *wt;
    int *cnt, *offs, *cur, *bsums;
    int2 *cpack;
    cudaGetSymbolAddress((void**)&bufA, g_bufA);
    cudaGetSymbolAddress((void**)&bufB, g_bufB);
    cudaGetSymbolAddress((void**)&dinv, g_dinv);
    cudaGetSymbolAddress((void**)&cnt, g_count);
    cudaGetSymbolAddress((void**)&offs, g_offs);
    cudaGetSymbolAddress((void**)&cur, g_cursor);
    cudaGetSymbolAddress((void**)&bsums, g_bsums);
    cudaGetSymbolAddress((void**)&cpack, g_cpack);
    cudaGetSymbolAddress((void**)&stats, g_stats);
    cudaGetSymbolAddress((void**)&pool, g_pool);
    cudaGetSymbolAddress((void**)&pcnt, g_pcnt);
    cudaGetSymbolAddress((void**)&wt, g_wt);

    cudaFuncSetAttribute(gemm_tc, cudaFuncAttributeMaxDynamicSharedMemorySize, GSMEM);
    cudaFuncSetAttribute(mlp_fused, cudaFuncAttributeMaxDynamicSharedMemorySize, FSMEM);

    const int* src = ei;
    const int* dst = ei + EE;

    const int TB = 256;
    const int gridN  = (NN + TB - 1) / TB;
    const int gridE  = (EE + TB - 1) / TB;
    const int gridG  = (NN + 127) / 128;   // 782
    const int gridAg = (NN * 32 + TB - 1) / TB;
    const int nScanB = (NN + 1023) / 1024;
    dim3 gemmGrid(gridG, 2);

    // prep
    wprep<<<256, 256>>>(Wg0, Wg1, Wl1, Wl2, wt);
    zero2<<<gridN, TB>>>(dinv, cnt, NN);
    hist_kernel<<<gridE, TB>>>(src, dst, ea, dinv, cnt);
    dinv_kernel<<<gridN, TB>>>(dinv);

    // layer-0 GEMM (independent of CSR)
    gemm_tc<<<gemmGrid, 128, GSMEM>>>(x, wt + 0 * 16384, nullptr, nullptr, bufA, NN, 0);

    // scan + CSR fill
    scan1<<<nScanB, 256>>>(cnt, offs + 1, bsums, NN);
    scan2<<<1, 128>>>(bsums, nScanB);
    scan3<<<nScanB, 256>>>(offs + 1, bsums, NN, offs, cur);
    fill_kernel<<<gridE, TB>>>(src, dst, ea, dinv, cur, cpack);

    // GCN layer 0
    agg_kernel<<<gridAg, TB>>>(bufA, dinv, offs, cpack, bg0, bufB, stats);
    bn_stats<<<BNBLK, 256>>>(bufB, stats, NN);
    bn_finalize<<<1, 128>>>(stats, gamma0, beta0);

    // GCN layer 1 (bn0 affine fused into GEMM A-load)
    gemm_tc<<<gemmGrid, 128, GSMEM>>>(bufB, wt + 1 * 16384, stats, nullptr, bufA, NN, 0);
    agg_kernel<<<gridAg, TB>>>(bufA, dinv, offs, cpack, bg1, bufB, stats);
    bn_stats<<<BNBLK, 256>>>(bufB, stats, NN);
    bn_finalize<<<1, 128>>>(stats, gamma1, beta1);

    // fused MLP head (bn1 affine fused into A-load)
    mlp_fused<<<gridG, 256, FSMEM>>>(bufB, wt + 2 * 16384, wt + 3 * 16384, stats, bl1, bl2, h_out, NN);

    // pooling + classifier
    pool_partial<<<GG * 8, 128>>>(h_out, batch, pool, pcnt);
    classify_kernel<<<GG, 128>>>(pool, pcnt, reps, Wc1, bc1, Wc2, bc2, logits);
}

// round 6
// speedup vs baseline: 2.2287x; 1.0751x over previous
#include <cuda_runtime.h>
#include <cuda_fp16.h>
#include <cstdint>

#define NN 100000
#define EE 1600000
#define DD 128
#define GG 64
#define CC 2
#define EPSBN 1e-5f

// ---------------- scratch (static device globals; no allocation) ----------------
__device__ float g_bufA[(size_t)NN * DD];   // reused as fp16 (half the space) for GCN layers
__device__ float g_bufB[(size_t)NN * DD];
__device__ float g_dinv[NN];
__device__ int   g_count[NN];
__device__ int   g_offs[NN + 1];
__device__ int   g_cursor[NN];
__device__ int   g_bsums[512];
__device__ int2  g_cpack[EE];
__device__ float g_stats[2 * DD];
__device__ float g_pool[GG * 8 * DD];
__device__ float g_pcnt[GG];
__device__ float g_wt[4 * 128 * 128];   // tf32-preconverted weights, row-major [k][n]

// ---------------- helpers ----------------
__device__ __forceinline__ uint32_t cvt_tf32(float x) {
    uint32_t u;
    asm("cvt.rna.tf32.f32 %0, %1;" : "=r"(u) : "f"(x));
    return u;
}
__device__ __forceinline__ uint32_t smem_u32(const void* p) {
    uint32_t a;
    asm("{ .reg .u64 t; cvta.to.shared.u64 t, %1; cvt.u32.u64 %0, t; }" : "=r"(a) : "l"(p));
    return a;
}
__device__ __forceinline__ void mma_tf32(float* d, const uint32_t* a, const uint32_t* b) {
    asm volatile(
        "mma.sync.aligned.m16n8k8.row.col.f32.tf32.tf32.f32 "
        "{%0,%1,%2,%3}, {%4,%5,%6,%7}, {%8,%9}, {%0,%1,%2,%3};"
        : "+f"(d[0]), "+f"(d[1]), "+f"(d[2]), "+f"(d[3])
        : "r"(a[0]), "r"(a[1]), "r"(a[2]), "r"(a[3]), "r"(b[0]), "r"(b[1]));
}
__device__ __forceinline__ void ldsm4(uint32_t* a, uint32_t addr) {
    asm volatile("ldmatrix.sync.aligned.m8n8.x4.shared.b16 {%0,%1,%2,%3}, [%4];"
        : "=r"(a[0]), "=r"(a[1]), "=r"(a[2]), "=r"(a[3]) : "r"(addr));
}
__device__ __forceinline__ void cp_async16(uint32_t saddr, const void* gaddr) {
    asm volatile("cp.async.cg.shared.global [%0], [%1], 16;" :: "r"(saddr), "l"(gaddr));
}

#define PA 132
#define PB 136      // mlp_fused B pitch
#define PB2 72      // gemm_tc B pitch (72 mod 32 == 8: conflict-free)
#define GSMEM ((128 * PA + 128 * PB2) * 4)
#define FSMEM ((128 * PA + 2 * 128 * PB) * 4)

// ---------------- utility ----------------
__global__ void zero2(float* a, int* b, int n) {
    int i = blockIdx.x * blockDim.x + threadIdx.x;
    if (i < n) { a[i] = 0.f; b[i] = 0; }
}

// ---------------- weight tf32 pre-conversion ----------------
__global__ void wprep(const float* __restrict__ W0, const float* __restrict__ W1,
                      const float* __restrict__ W2, const float* __restrict__ W3,
                      float* __restrict__ wt) {
    int i = blockIdx.x * blockDim.x + threadIdx.x;   // 0..65535
    const float* W = (i < 16384) ? W0 : (i < 32768) ? W1 : (i < 49152) ? W2 : W3;
    wt[i] = __uint_as_float(cvt_tf32(W[i & 16383]));
}

// ---------------- A staging (NT threads) ----------------
template<int NT>
__device__ __forceinline__ void stage_A(const float* __restrict__ A, const float* __restrict__ affine,
                                        float* As, int row0, int nrows, int tid) {
#pragma unroll
    for (int i = 0; i < 4096 / NT; i++) {
        int f = i * NT + tid;
        int row = f >> 5, kq = f & 31;
        float4 v = make_float4(0.f, 0.f, 0.f, 0.f);
        if (row0 + row < nrows)
            v = ((const float4*)A)[(size_t)(row0 + row) * 32 + kq];
        if (affine) {
            int k0 = kq * 4;
            v.x = v.x * affine[k0 + 0] + affine[128 + k0 + 0];
            v.y = v.y * affine[k0 + 1] + affine[128 + k0 + 1];
            v.z = v.z * affine[k0 + 2] + affine[128 + k0 + 2];
            v.w = v.w * affine[k0 + 3] + affine[128 + k0 + 3];
        }
        uint4 t;
        t.x = cvt_tf32(v.x); t.y = cvt_tf32(v.y); t.z = cvt_tf32(v.z); t.w = cvt_tf32(v.w);
        *(uint4*)&As[row * PA + kq * 4] = t;
    }
}

// ---------------- MMA mainloop ----------------
template<int PBX>
__device__ __forceinline__ void mma_loop(uint32_t abase, const uint32_t* Bsu,
                                         int wn, int gid, int tg, float acc[4][4][4]) {
#pragma unroll
    for (int ks = 0; ks < 16; ks++) {
        int k0 = ks * 8;
        uint32_t a[4][4];
#pragma unroll
        for (int mi = 0; mi < 4; mi++)
            ldsm4(a[mi], abase + (uint32_t)(mi * 16 * PA * 4 + ks * 32));
        uint32_t b[4][2];
#pragma unroll
        for (int ni = 0; ni < 4; ni++) {
            int c = wn + ni * 8 + gid;
            b[ni][0] = Bsu[(k0 + tg) * PBX + c];
            b[ni][1] = Bsu[(k0 + tg + 4) * PBX + c];
        }
#pragma unroll
        for (int mi = 0; mi < 4; mi++)
#pragma unroll
            for (int ni = 0; ni < 4; ni++)
                mma_tf32(acc[mi][ni], a[mi], b[ni]);
    }
}

// ---------------- GEMM: 128 threads, tile 128M x 64N, fp16 output ----------------
__global__ void __launch_bounds__(128) gemm_tc(const float* __restrict__ A,
                                               const float* __restrict__ WT,
                                               const float* __restrict__ affine,
                                               __half* __restrict__ out,
                                               int nrows) {
    extern __shared__ float smem[];
    float* As = smem;               // [128][PA]
    float* Bs = smem + 128 * PA;    // [128][PB2]
    int tid = threadIdx.x, wid = tid >> 5, lane = tid & 31;
    int row0 = blockIdx.x * 128, n0 = blockIdx.y * 64;
    int gid = lane >> 2, tg = lane & 3;
    int wm = (wid >> 1) * 64, wn = (wid & 1) * 32;

    uint32_t bbase = smem_u32(Bs);
#pragma unroll
    for (int i = 0; i < 16; i++) {
        int f = i * 128 + tid;
        int k = f >> 4, q = f & 15;
        cp_async16(bbase + (uint32_t)((k * PB2 + q * 4) << 2),
                   WT + (size_t)k * 128 + n0 + q * 4);
    }
    asm volatile("cp.async.commit_group;");

    stage_A<128>(A, affine, As, row0, nrows, tid);

    asm volatile("cp.async.wait_group 0;" ::: "memory");
    __syncthreads();

    int ldrow = wm + ((lane >> 3) & 1) * 8 + (lane & 7);
    uint32_t abase = smem_u32(As) + (uint32_t)((ldrow * PA + ((lane >> 4) << 2)) << 2);

    float acc[4][4][4];
#pragma unroll
    for (int mi = 0; mi < 4; mi++)
#pragma unroll
        for (int ni = 0; ni < 4; ni++)
#pragma unroll
            for (int j = 0; j < 4; j++) acc[mi][ni][j] = 0.f;

    mma_loop<PB2>(abase, (const uint32_t*)Bs, wn, gid, tg, acc);

#pragma unroll
    for (int mi = 0; mi < 4; mi++) {
        int r_lo = row0 + wm + mi * 16 + gid;
        int r_hi = r_lo + 8;
#pragma unroll
        for (int ni = 0; ni < 4; ni++) {
            int c = n0 + wn + ni * 8 + 2 * tg;
            __half2 p0 = __floats2half2_rn(acc[mi][ni][0], acc[mi][ni][1]);
            __half2 p1 = __floats2half2_rn(acc[mi][ni][2], acc[mi][ni][3]);
            if (r_lo < nrows) *(__half2*)(out + (size_t)r_lo * 128 + c) = p0;
            if (r_hi < nrows) *(__half2*)(out + (size_t)r_hi * 128 + c) = p1;
        }
    }
}

// ---------------- fused MLP head: out = (relu(affine(A)@W1+b1)) @ W2 + b2 (fp32 out) -----
__global__ void __launch_bounds__(256) mlp_fused(const float* __restrict__ A,
                                                 const float* __restrict__ W1T,
                                                 const float* __restrict__ W2T,
                                                 const float* __restrict__ affine,
                                                 const float* __restrict__ b1,
                                                 const float* __restrict__ b2,
                                                 float* __restrict__ out, int nrows) {
    extern __shared__ float smem[];
    float* As  = smem;
    float* Bs1 = smem + 128 * PA;
    float* Bs2 = Bs1 + 128 * PB;
    int tid = threadIdx.x, wid = tid >> 5, lane = tid & 31;
    int row0 = blockIdx.x * 128;
    int gid = lane >> 2, tg = lane & 3;
    int wm = (wid >> 2) * 64, wn = (wid & 3) * 32;

    uint32_t b1base = smem_u32(Bs1), b2base = smem_u32(Bs2);
#pragma unroll
    for (int i = 0; i < 16; i++) {
        int f = i * 256 + tid;
        int k = f >> 5, q = f & 31;
        cp_async16(b1base + (uint32_t)((k * PB + q * 4) << 2), W1T + (size_t)k * 128 + q * 4);
        cp_async16(b2base + (uint32_t)((k * PB + q * 4) << 2), W2T + (size_t)k * 128 + q * 4);
    }
    asm volatile("cp.async.commit_group;");

    stage_A<256>(A, affine, As, row0, nrows, tid);

    asm volatile("cp.async.wait_group 0;" ::: "memory");
    __syncthreads();

    int ldrow = wm + ((lane >> 3) & 1) * 8 + (lane & 7);
    uint32_t abase = smem_u32(As) + (uint32_t)((ldrow * PA + ((lane >> 4) << 2)) << 2);

    float acc[4][4][4];
#pragma unroll
    for (int mi = 0; mi < 4; mi++)
#pragma unroll
        for (int ni = 0; ni < 4; ni++)
#pragma unroll
            for (int j = 0; j < 4; j++) acc[mi][ni][j] = 0.f;

    mma_loop<PB>(abase, (const uint32_t*)Bs1, wn, gid, tg, acc);
    __syncthreads();

    uint32_t* Asu = (uint32_t*)As;
#pragma unroll
    for (int ni = 0; ni < 4; ni++) {
        int c = wn + ni * 8 + 2 * tg;
        float bx = b1[c], by = b1[c + 1];
#pragma unroll
        for (int mi = 0; mi < 4; mi++) {
            int r = wm + mi * 16 + gid;
            uint2 t0, t1;
            t0.x = cvt_tf32(fmaxf(acc[mi][ni][0] + bx, 0.f));
            t0.y = cvt_tf32(fmaxf(acc[mi][ni][1] + by, 0.f));
            t1.x = cvt_tf32(fmaxf(acc[mi][ni][2] + bx, 0.f));
            t1.y = cvt_tf32(fmaxf(acc[mi][ni][3] + by, 0.f));
            *(uint2*)&Asu[r * PA + c] = t0;
            *(uint2*)&Asu[(r + 8) * PA + c] = t1;
        }
    }
    __syncthreads();

#pragma unroll
    for (int mi = 0; mi < 4; mi++)
#pragma unroll
        for (int ni = 0; ni < 4; ni++)
#pragma unroll
            for (int j = 0; j < 4; j++) acc[mi][ni][j] = 0.f;

    mma_loop<PB>(abase, (const uint32_t*)Bs2, wn, gid, tg, acc);

    float2 bv[4];
#pragma unroll
    for (int ni = 0; ni < 4; ni++) {
        int c = wn + ni * 8 + 2 * tg;
        bv[ni].x = b2[c]; bv[ni].y = b2[c + 1];
    }
#pragma unroll
    for (int mi = 0; mi < 4; mi++) {
        int r_lo = row0 + wm + mi * 16 + gid;
        int r_hi = r_lo + 8;
#pragma unroll
        for (int ni = 0; ni < 4; ni++) {
            int c = wn + ni * 8 + 2 * tg;
            float2 v0, v1;
            v0.x = acc[mi][ni][0] + bv[ni].x;
            v0.y = acc[mi][ni][1] + bv[ni].y;
            v1.x = acc[mi][ni][2] + bv[ni].x;
            v1.y = acc[mi][ni][3] + bv[ni].y;
            if (r_lo < nrows) *(float2*)(out + (size_t)r_lo * 128 + c) = v0;
            if (r_hi < nrows) *(float2*)(out + (size_t)r_hi * 128 + c) = v1;
        }
    }
}

// ---------------- degree histogram ----------------
__global__ void hist_kernel(const int* __restrict__ src, const int* __restrict__ dst,
                            const float* __restrict__ attr, float* deg, int* cnt) {
    int e = blockIdx.x * blockDim.x + threadIdx.x;
    if (e >= EE) return;
    int d = dst[e];
    float w = attr[(size_t)e * 2 + 1];
    atomicAdd(&deg[d], w);
    atomicAdd(&cnt[d], 1);
}

// ---------------- scan (dinv folded into scan1) ----------------
__global__ void scan1(const int* __restrict__ in, int* __restrict__ out,
                      int* __restrict__ bsums, int n, float* dinv) {
    __shared__ int sh[256];
    int tid = threadIdx.x;
    int base = blockIdx.x * 1024;
    int v[4]; int tsum = 0;
#pragma unroll
    for (int j = 0; j < 4; j++) {
        int idx = base + tid * 4 + j;
        v[j] = (idx < n) ? in[idx] : 0;
        if (idx < n) dinv[idx] = rsqrtf(dinv[idx] + 1.0f);
        tsum += v[j];
    }
    sh[tid] = tsum; __syncthreads();
#pragma unroll
    for (int off = 1; off < 256; off <<= 1) {
        int t = (tid >= off) ? sh[tid - off] : 0;
        __syncthreads();
        sh[tid] += t;
        __syncthreads();
    }
    int run = sh[tid] - tsum;
#pragma unroll
    for (int j = 0; j < 4; j++) {
        int idx = base + tid * 4 + j;
        run += v[j];
        if (idx < n) out[idx] = run;
    }
    if (tid == 255) bsums[blockIdx.x] = sh[255];
}

__global__ void scan2(int* bs, int nb) {
    __shared__ int sh[128];
    int tid = threadIdx.x;
    int orig = (tid < nb) ? bs[tid] : 0;
    sh[tid] = orig; __syncthreads();
#pragma unroll
    for (int off = 1; off < 128; off <<= 1) {
        int t = (tid >= off) ? sh[tid - off] : 0;
        __syncthreads();
        sh[tid] += t;
        __syncthreads();
    }
    if (tid < nb) bs[tid] = sh[tid] - orig;
}

__global__ void scan3(int* out /* offs+1 */, const int* __restrict__ bs, int n,
                      int* offs0, int* cur) {
    int tid = threadIdx.x;
    int base = blockIdx.x * 1024;
    int add = bs[blockIdx.x];
#pragma unroll
    for (int j = 0; j < 4; j++) {
        int idx = base + tid * 4 + j;
        if (idx < n) {
            int v = out[idx] + add;
            out[idx] = v;
            if (idx + 1 < n) cur[idx + 1] = v;
        }
    }
    if (blockIdx.x == 0 && tid == 0) { offs0[0] = 0; cur[0] = 0; }
}

// ---------------- CSR fill ----------------
__global__ void fill_kernel(const int* __restrict__ src, const int* __restrict__ dst,
                            const float* __restrict__ attr, const float* __restrict__ dinv,
                            int* cursor, int2* cpack) {
    int e = blockIdx.x * blockDim.x + threadIdx.x;
    if (e >= EE) return;
    int s = src[e], d = dst[e];
    float w = attr[(size_t)e * 2 + 1];
    int pos = atomicAdd(&cursor[d], 1);
    int2 q;
    q.x = s;
    q.y = __float_as_int(dinv[s] * w * dinv[d]);
    cpack[pos] = q;
}

// ---------------- GCN aggregation (fp16 feature gather, fp32 accumulate) ----------------
__global__ void agg_kernel(const __half* __restrict__ hw, const float* __restrict__ dinv,
                           const int* __restrict__ offs, const int2* __restrict__ cpack,
                           const float* __restrict__ bias, float* __restrict__ out,
                           float* stats) {
    if (blockIdx.x == 0 && threadIdx.x < 256) stats[threadIdx.x] = 0.f;
    int gtid = blockIdx.x * blockDim.x + threadIdx.x;
    int node = gtid >> 5;
    if (node >= NN) return;
    int lane = threadIdx.x & 31;

    const uint2* feat = (const uint2*)hw;   // 4 halfs per uint2; 32 per node

    float di = dinv[node];
    float self = di * di;
    uint2 q0 = feat[(size_t)node * 32 + lane];
    __half2 h01 = *(__half2*)&q0.x, h23 = *(__half2*)&q0.y;
    float2 f01 = __half22float2(h01), f23 = __half22float2(h23);
    float4 acc;
    acc.x = self * f01.x; acc.y = self * f01.y;
    acc.z = self * f23.x; acc.w = self * f23.y;

    int p0 = offs[node], p1 = offs[node + 1];
#pragma unroll 4
    for (int p = p0; p < p1; p++) {
        int2 e = cpack[p];
        float c = __int_as_float(e.y);
        uint2 qv = feat[(size_t)e.x * 32 + lane];
        __half2 v01 = *(__half2*)&qv.x, v23 = *(__half2*)&qv.y;
        float2 g01 = __half22float2(v01), g23 = __half22float2(v23);
        acc.x += c * g01.x; acc.y += c * g01.y;
        acc.z += c * g23.x; acc.w += c * g23.y;
    }
    float4 b = ((const float4*)bias)[lane];
    acc.x = fmaxf(acc.x + b.x, 0.f);
    acc.y = fmaxf(acc.y + b.y, 0.f);
    acc.z = fmaxf(acc.z + b.z, 0.f);
    acc.w = fmaxf(acc.w + b.w, 0.f);
    ((float4*)(out + (size_t)node * 128))[lane] = acc;
}

// ---------------- BatchNorm stats ----------------
#define BNBLK 296
#define BNCHUNK 338
__global__ void bn_stats(const float* __restrict__ X, float* stats, int nrows) {
    __shared__ float sh[256];
    int d = threadIdx.x & 127;
    int half = threadIdx.x >> 7;
    int r0 = blockIdx.x * BNCHUNK;
    int rend = min(r0 + BNCHUNK, nrows);
    float s = 0.f, q = 0.f;
    for (int r = r0 + half; r < rend; r += 2) {
        float v = X[(size_t)r * 128 + d];
        s += v; q += v * v;
    }
    sh[threadIdx.x] = s; __syncthreads();
    if (half == 0) atomicAdd(&stats[d], s + sh[128 + d]);
    __syncthreads();
    sh[threadIdx.x] = q; __syncthreads();
    if (half == 0) atomicAdd(&stats[128 + d], q + sh[128 + d]);
}

__global__ void bn_finalize(float* stats, const float* __restrict__ gamma,
                            const float* __restrict__ beta) {
    int d = threadIdx.x;
    float invn = 1.0f / (float)NN;
    float m = stats[d] * invn;
    float v = stats[128 + d] * invn - m * m;
    float sc = gamma[d] * rsqrtf(v + EPSBN);
    stats[d] = sc;
    stats[128 + d] = beta[d] - m * sc;
}

// ---------------- pooling: 8 partial blocks per group ----------------
__global__ void pool_partial(const float* __restrict__ h, const int* __restrict__ batch,
                             float* __restrict__ part, float* __restrict__ pcnt) {
    int g = blockIdx.x >> 3, c = blockIdx.x & 7;
    int lo = 0, hi = NN;
    while (lo < hi) { int mid = (lo + hi) >> 1; if (batch[mid] < g) lo = mid + 1; else hi = mid; }
    int start = lo;
    lo = start; hi = NN;
    while (lo < hi) { int mid = (lo + hi) >> 1; if (batch[mid] < g + 1) lo = mid + 1; else hi = mid; }
    int end = lo;
    int len = end - start;
    int b0 = start + (int)(((long long)len * c) >> 3);
    int b1 = start + (int)(((long long)len * (c + 1)) >> 3);
    int d = threadIdx.x;
    float s = 0.f;
    for (int r = b0; r < b1; r++) s += h[(size_t)r * 128 + d];
    part[(g * 8 + c) * 128 + d] = s;
    if (c == 0 && d == 0) pcnt[g] = (float)len;
}

// ---------------- classifier: one block per group ----------------
__global__ void classify_kernel(const float* __restrict__ part, const float* __restrict__ pcnt,
                                float* __restrict__ reps,
                                const float* __restrict__ Wc1, const float* __restrict__ bc1,
                                const float* __restrict__ Wc2, const float* __restrict__ bc2,
                                float* __restrict__ logits) {
    __shared__ float rsh[128];
    __shared__ float tsh[128];
    int g = blockIdx.x;
    int d = threadIdx.x;
    float s = 0.f;
#pragma unroll
    for (int c = 0; c < 8; c++) s += part[(g * 8 + c) * 128 + d];
    float inv = 1.0f / fmaxf(pcnt[g], 1.0f);
    float rv = s * inv;
    reps[g * 128 + d] = rv;
    rsh[d] = rv;
    __syncthreads();
    float t = bc1[d];
#pragma unroll
    for (int k = 0; k < 128; k++) t += rsh[k] * Wc1[k * 128 + d];
    tsh[d] = fmaxf(t, 0.f);
    __syncthreads();
    if (d < CC) {
        float s2 = bc2[d];
#pragma unroll
        for (int k = 0; k < 128; k++) s2 += tsh[k] * Wc2[k * CC + d];
        logits[g * CC + d] = s2;
    }
}

// ---------------- launch ----------------
extern "C" void kernel_launch(void* const* d_in, const int* in_sizes, int n_in,
                              void* d_out, int out_size) {
    const float* x     = (const float*)d_in[0];
    const int*   ei    = (const int*)d_in[1];
    const float* ea    = (const float*)d_in[2];
    const int*   batch = (const int*)d_in[3];
    const float* Wg0 = (const float*)d_in[4],  *bg0 = (const float*)d_in[5];
    const float* gamma0 = (const float*)d_in[6], *beta0 = (const float*)d_in[7];
    const float* Wg1 = (const float*)d_in[8],  *bg1 = (const float*)d_in[9];
    const float* gamma1 = (const float*)d_in[10], *beta1 = (const float*)d_in[11];
    const float* Wl1 = (const float*)d_in[12], *bl1 = (const float*)d_in[13];
    const float* Wl2 = (const float*)d_in[14], *bl2 = (const float*)d_in[15];
    const float* Wc1 = (const float*)d_in[16], *bc1 = (const float*)d_in[17];
    const float* Wc2 = (const float*)d_in[18], *bc2 = (const float*)d_in[19];

    float* out = (float*)d_out;
    float* h_out  = out;
    float* reps   = out + (size_t)NN * DD;
    float* logits = out + (size_t)NN * DD + (size_t)GG * DD;

    float *bufA, *bufB, *dinv, *stats, *pool, *pcnt, *wt;
    int *cnt, *offs, *cur, *bsums;
    int2 *cpack;
    cudaGetSymbolAddress((void**)&bufA, g_bufA);
    cudaGetSymbolAddress((void**)&bufB, g_bufB);
    cudaGetSymbolAddress((void**)&dinv, g_dinv);
    cudaGetSymbolAddress((void**)&cnt, g_count);
    cudaGetSymbolAddress((void**)&offs, g_offs);
    cudaGetSymbolAddress((void**)&cur, g_cursor);
    cudaGetSymbolAddress((void**)&bsums, g_bsums);
    cudaGetSymbolAddress((void**)&cpack, g_cpack);
    cudaGetSymbolAddress((void**)&stats, g_stats);
    cudaGetSymbolAddress((void**)&pool, g_pool);
    cudaGetSymbolAddress((void**)&pcnt, g_pcnt);
    cudaGetSymbolAddress((void**)&wt, g_wt);

    __half* bufAh = (__half*)bufA;

    cudaFuncSetAttribute(gemm_tc, cudaFuncAttributeMaxDynamicSharedMemorySize, GSMEM);
    cudaFuncSetAttribute(mlp_fused, cudaFuncAttributeMaxDynamicSharedMemorySize, FSMEM);

    const int* src = ei;
    const int* dst = ei + EE;

    const int TB = 256;
    const int gridN  = (NN + TB - 1) / TB;
    const int gridE  = (EE + TB - 1) / TB;
    const int gridG  = (NN + 127) / 128;   // 782
    const int gridAg = (NN * 32 + TB - 1) / TB;
    const int nScanB = (NN + 1023) / 1024;
    dim3 gemmGrid(gridG, 2);

    // prep (gemm_tc kept as 4th launch for ncu capture)
    zero2<<<gridN, TB>>>(dinv, cnt, NN);
    hist_kernel<<<gridE, TB>>>(src, dst, ea, dinv, cnt);
    wprep<<<256, 256>>>(Wg0, Wg1, Wl1, Wl2, wt);
    gemm_tc<<<gemmGrid, 128, GSMEM>>>(x, wt + 0 * 16384, nullptr, bufAh, NN);

    // scan (+dinv) + CSR fill
    scan1<<<nScanB, 256>>>(cnt, offs + 1, bsums, NN, dinv);
    scan2<<<1, 128>>>(bsums, nScanB);
    scan3<<<nScanB, 256>>>(offs + 1, bsums, NN, offs, cur);
    fill_kernel<<<gridE, TB>>>(src, dst, ea, dinv, cur, cpack);

    // GCN layer 0
    agg_kernel<<<gridAg, TB>>>(bufAh, dinv, offs, cpack, bg0, bufB, stats);
    bn_stats<<<BNBLK, 256>>>(bufB, stats, NN);
    bn_finalize<<<1, 128>>>(stats, gamma0, beta0);

    // GCN layer 1 (bn0 affine fused into GEMM A-load)
    gemm_tc<<<gemmGrid, 128, GSMEM>>>(bufB, wt + 1 * 16384, stats, bufAh, NN);
    agg_kernel<<<gridAg, TB>>>(bufAh, dinv, offs, cpack, bg1, bufB, stats);
    bn_stats<<<BNBLK, 256>>>(bufB, stats, NN);
    bn_finalize<<<1, 128>>>(stats, gamma1, beta1);

    // fused MLP head (bn1 affine fused into A-load)
    mlp_fused<<<gridG, 256, FSMEM>>>(bufB, wt + 2 * 16384, wt + 3 * 16384, stats, bl1, bl2, h_out, NN);

    // pooling + classifier
    pool_partial<<<GG * 8, 128>>>(h_out, batch, pool, pcnt);
    classify_kernel<<<GG, 128>>>(pool, pcnt, reps, Wc1, bc1, Wc2, bc2, logits);
}

// round 7
// speedup vs baseline: 2.6767x; 1.2010x over previous
#include <cuda_runtime.h>
#include <cuda_fp16.h>
#include <cstdint>

#define NN 100000
#define EE 1600000
#define DD 128
#define GG 64
#define CC 2
#define EPSBN 1e-5f

// ---------------- scratch (static device globals; no allocation) ----------------
__device__ __half g_bufA[(size_t)NN * DD];
__device__ __half g_bufB[(size_t)NN * DD];
__device__ float g_dinv[NN];
__device__ int   g_count[NN];
__device__ int   g_offs[NN + 1];
__device__ int   g_cursor[NN];
__device__ int   g_bsums[512];
__device__ int2  g_cpack[EE];
__device__ float g_stats[2 * DD];
__device__ float g_pool[GG * 8 * DD];
__device__ float g_pcnt[GG];
__device__ __half g_wt[4 * 128 * 128];   // fp16 weights, TRANSPOSED: [n][k]

// ---------------- helpers ----------------
__device__ __forceinline__ uint32_t smem_u32(const void* p) {
    uint32_t a;
    asm("{ .reg .u64 t; cvta.to.shared.u64 t, %1; cvt.u32.u64 %0, t; }" : "=r"(a) : "l"(p));
    return a;
}
__device__ __forceinline__ void mma_f16(float* d, const uint32_t* a, const uint32_t* b) {
    asm volatile(
        "mma.sync.aligned.m16n8k16.row.col.f32.f16.f16.f32 "
        "{%0,%1,%2,%3}, {%4,%5,%6,%7}, {%8,%9}, {%0,%1,%2,%3};"
        : "+f"(d[0]), "+f"(d[1]), "+f"(d[2]), "+f"(d[3])
        : "r"(a[0]), "r"(a[1]), "r"(a[2]), "r"(a[3]), "r"(b[0]), "r"(b[1]));
}
__device__ __forceinline__ void ldsm4(uint32_t* a, uint32_t addr) {
    asm volatile("ldmatrix.sync.aligned.m8n8.x4.shared.b16 {%0,%1,%2,%3}, [%4];"
        : "=r"(a[0]), "=r"(a[1]), "=r"(a[2]), "=r"(a[3]) : "r"(addr));
}
__device__ __forceinline__ void cp_async16(uint32_t saddr, const void* gaddr) {
    asm volatile("cp.async.cg.shared.global [%0], [%1], 16;" :: "r"(saddr), "l"(gaddr));
}

// SMEM half pitches
#define PA2 136             // A pitch in halfs (272 B/row; row*68 words -> conflict-free ldsm)
#define PBK 136             // B pitch in halfs ([n][k] layout)
#define GSMEM ((128 * PA2 + 64 * PBK) * 2)        // 52.2 KB -> 4 CTAs/SM
#define FSMEM ((128 * PA2 + 2 * 128 * PBK) * 2)   // 104.4 KB

// ---------------- utility ----------------
__global__ void zero2(float* a, int* b, int n) {
    int i = blockIdx.x * blockDim.x + threadIdx.x;
    if (i < n) { a[i] = 0.f; b[i] = 0; }
}

// ---------------- weight fp16 transpose prep: wt[m][n][k] = (half)W_m[k][n] ----------------
__global__ void wprep(const float* __restrict__ W0, const float* __restrict__ W1,
                      const float* __restrict__ W2, const float* __restrict__ W3,
                      __half* __restrict__ wt) {
    int i = blockIdx.x * blockDim.x + threadIdx.x;   // 0..65535
    const float* W = (i < 16384) ? W0 : (i < 32768) ? W1 : (i < 49152) ? W2 : W3;
    int j = i & 16383;
    int n = j >> 7, k = j & 127;
    wt[i] = __float2half(W[k * 128 + n]);
}

// ---------------- A staging: fp32 source ----------------
template<int NT>
__device__ __forceinline__ void stage_A_f32(const float* __restrict__ A, __half* As,
                                            int row0, int nrows, int tid) {
#pragma unroll
    for (int i = 0; i < 4096 / NT; i++) {
        int f = i * NT + tid;
        int row = f >> 5, kq = f & 31;
        float4 v = make_float4(0.f, 0.f, 0.f, 0.f);
        if (row0 + row < nrows)
            v = ((const float4*)A)[(size_t)(row0 + row) * 32 + kq];
        __half2 h0 = __floats2half2_rn(v.x, v.y);
        __half2 h1 = __floats2half2_rn(v.z, v.w);
        uint2 t; t.x = *(uint32_t*)&h0; t.y = *(uint32_t*)&h1;
        *(uint2*)&As[row * PA2 + kq * 4] = t;
    }
}

// ---------------- A staging: fp16 source + affine ----------------
template<int NT>
__device__ __forceinline__ void stage_A_f16(const __half* __restrict__ A,
                                            const float* __restrict__ affine,
                                            __half* As, int row0, int nrows, int tid) {
#pragma unroll
    for (int i = 0; i < 4096 / NT; i++) {
        int f = i * NT + tid;
        int row = f >> 5, kq = f & 31;
        uint2 q = make_uint2(0u, 0u);
        if (row0 + row < nrows)
            q = ((const uint2*)A)[(size_t)(row0 + row) * 32 + kq];
        float2 f01 = __half22float2(*(__half2*)&q.x);
        float2 f23 = __half22float2(*(__half2*)&q.y);
        int k0 = kq * 4;
        f01.x = f01.x * affine[k0 + 0] + affine[128 + k0 + 0];
        f01.y = f01.y * affine[k0 + 1] + affine[128 + k0 + 1];
        f23.x = f23.x * affine[k0 + 2] + affine[128 + k0 + 2];
        f23.y = f23.y * affine[k0 + 3] + affine[128 + k0 + 3];
        __half2 h0 = __floats2half2_rn(f01.x, f01.y);
        __half2 h1 = __floats2half2_rn(f23.x, f23.y);
        uint2 t; t.x = *(uint32_t*)&h0; t.y = *(uint32_t*)&h1;
        *(uint2*)&As[row * PA2 + kq * 4] = t;
    }
}

// ---------------- fp16 MMA mainloop: 8 k16-steps ----------------
__device__ __forceinline__ void mma_loop_h(uint32_t abase, const __half* Bs,
                                           int wn, int gid, int tg, float acc[4][4][4]) {
#pragma unroll
    for (int ks = 0; ks < 8; ks++) {
        int k0 = ks * 16;
        uint32_t a[4][4];
#pragma unroll
        for (int mi = 0; mi < 4; mi++)
            ldsm4(a[mi], abase + (uint32_t)(mi * 16 * PA2 * 2 + ks * 32));
        uint32_t b[4][2];
#pragma unroll
        for (int ni = 0; ni < 4; ni++) {
            int c = wn + ni * 8 + gid;
            b[ni][0] = *(const uint32_t*)&Bs[c * PBK + k0 + 2 * tg];
            b[ni][1] = *(const uint32_t*)&Bs[c * PBK + k0 + 8 + 2 * tg];
        }
#pragma unroll
        for (int mi = 0; mi < 4; mi++)
#pragma unroll
            for (int ni = 0; ni < 4; ni++)
                mma_f16(acc[mi][ni], a[mi], b[ni]);
    }
}

// ---------------- GEMM: 128 threads, tile 128M x 64N, fp16 in/out ----------------
// affine == nullptr: A is fp32 (Af32); else A is fp16 (Ah) with affine applied.
__global__ void __launch_bounds__(128) gemm_tc(const float* __restrict__ Af32,
                                               const __half* __restrict__ Ah,
                                               const __half* __restrict__ WT,   // [n][k] fp16
                                               const float* __restrict__ affine,
                                               __half* __restrict__ out,
                                               int nrows) {
    extern __shared__ __half smemh[];
    __half* As = smemh;                 // [128][PA2]
    __half* Bs = smemh + 128 * PA2;     // [64][PBK]
    int tid = threadIdx.x, wid = tid >> 5, lane = tid & 31;
    int row0 = blockIdx.x * 128, n0 = blockIdx.y * 64;
    int gid = lane >> 2, tg = lane & 3;
    int wm = (wid >> 1) * 64, wn = (wid & 1) * 32;

    // B staging via cp.async: 64 rows x 128 k halfs = 16 chunks/row
    uint32_t bbase = smem_u32(Bs);
#pragma unroll
    for (int i = 0; i < 8; i++) {
        int f = i * 128 + tid;
        int n = f >> 4, q = f & 15;
        cp_async16(bbase + (uint32_t)((n * PBK + q * 8) * 2),
                   WT + (size_t)(n0 + n) * 128 + q * 8);
    }
    asm volatile("cp.async.commit_group;");

    if (affine) stage_A_f16<128>(Ah, affine, As, row0, nrows, tid);
    else        stage_A_f32<128>(Af32, As, row0, nrows, tid);

    asm volatile("cp.async.wait_group 0;" ::: "memory");
    __syncthreads();

    int ldrow = wm + ((lane >> 3) & 1) * 8 + (lane & 7);
    uint32_t abase = smem_u32(As) + (uint32_t)(ldrow * PA2 * 2 + ((lane >> 4) << 4));

    float acc[4][4][4];
#pragma unroll
    for (int mi = 0; mi < 4; mi++)
#pragma unroll
        for (int ni = 0; ni < 4; ni++)
#pragma unroll
            for (int j = 0; j < 4; j++) acc[mi][ni][j] = 0.f;

    mma_loop_h(abase, Bs, wn, gid, tg, acc);

#pragma unroll
    for (int mi = 0; mi < 4; mi++) {
        int r_lo = row0 + wm + mi * 16 + gid;
        int r_hi = r_lo + 8;
#pragma unroll
        for (int ni = 0; ni < 4; ni++) {
            int c = n0 + wn + ni * 8 + 2 * tg;
            __half2 p0 = __floats2half2_rn(acc[mi][ni][0], acc[mi][ni][1]);
            __half2 p1 = __floats2half2_rn(acc[mi][ni][2], acc[mi][ni][3]);
            if (r_lo < nrows) *(__half2*)(out + (size_t)r_lo * 128 + c) = p0;
            if (r_hi < nrows) *(__half2*)(out + (size_t)r_hi * 128 + c) = p1;
        }
    }
}

// ---------------- fused MLP head: out = (relu(affine(A)@W1+b1)) @ W2 + b2 (fp32 out) ----
__global__ void __launch_bounds__(256) mlp_fused(const __half* __restrict__ A,
                                                 const __half* __restrict__ W1T,
                                                 const __half* __restrict__ W2T,
                                                 const float* __restrict__ affine,
                                                 const float* __restrict__ b1,
                                                 const float* __restrict__ b2,
                                                 float* __restrict__ out, int nrows) {
    extern __shared__ __half smemh[];
    __half* As  = smemh;
    __half* Bs1 = smemh + 128 * PA2;
    __half* Bs2 = Bs1 + 128 * PBK;
    int tid = threadIdx.x, wid = tid >> 5, lane = tid & 31;
    int row0 = blockIdx.x * 128;
    int gid = lane >> 2, tg = lane & 3;
    int wm = (wid >> 2) * 64, wn = (wid & 3) * 32;

    uint32_t b1base = smem_u32(Bs1), b2base = smem_u32(Bs2);
#pragma unroll
    for (int i = 0; i < 8; i++) {
        int f = i * 256 + tid;
        int n = f >> 4, q = f & 15;
        cp_async16(b1base + (uint32_t)((n * PBK + q * 8) * 2), W1T + (size_t)n * 128 + q * 8);
        cp_async16(b2base + (uint32_t)((n * PBK + q * 8) * 2), W2T + (size_t)n * 128 + q * 8);
    }
    asm volatile("cp.async.commit_group;");

    stage_A_f16<256>(A, affine, As, row0, nrows, tid);

    asm volatile("cp.async.wait_group 0;" ::: "memory");
    __syncthreads();

    int ldrow = wm + ((lane >> 3) & 1) * 8 + (lane & 7);
    uint32_t abase = smem_u32(As) + (uint32_t)(ldrow * PA2 * 2 + ((lane >> 4) << 4));

    float acc[4][4][4];
#pragma unroll
    for (int mi = 0; mi < 4; mi++)
#pragma unroll
        for (int ni = 0; ni < 4; ni++)
#pragma unroll
            for (int j = 0; j < 4; j++) acc[mi][ni][j] = 0.f;

    mma_loop_h(abase, Bs1, wn, gid, tg, acc);
    __syncthreads();

    // write T = relu(acc + b1) back into As as fp16
#pragma unroll
    for (int ni = 0; ni < 4; ni++) {
        int c = wn + ni * 8 + 2 * tg;
        float bx = b1[c], by = b1[c + 1];
#pragma unroll
        for (int mi = 0; mi < 4; mi++) {
            int r = wm + mi * 16 + gid;
            __half2 t0 = __floats2half2_rn(fmaxf(acc[mi][ni][0] + bx, 0.f),
                                           fmaxf(acc[mi][ni][1] + by, 0.f));
            __half2 t1 = __floats2half2_rn(fmaxf(acc[mi][ni][2] + bx, 0.f),
                                           fmaxf(acc[mi][ni][3] + by, 0.f));
            *(__half2*)&As[r * PA2 + c] = t0;
            *(__half2*)&As[(r + 8) * PA2 + c] = t1;
        }
    }
    __syncthreads();

#pragma unroll
    for (int mi = 0; mi < 4; mi++)
#pragma unroll
        for (int ni = 0; ni < 4; ni++)
#pragma unroll
            for (int j = 0; j < 4; j++) acc[mi][ni][j] = 0.f;

    mma_loop_h(abase, Bs2, wn, gid, tg, acc);

    float2 bv[4];
#pragma unroll
    for (int ni = 0; ni < 4; ni++) {
        int c = wn + ni * 8 + 2 * tg;
        bv[ni].x = b2[c]; bv[ni].y = b2[c + 1];
    }
#pragma unroll
    for (int mi = 0; mi < 4; mi++) {
        int r_lo = row0 + wm + mi * 16 + gid;
        int r_hi = r_lo + 8;
#pragma unroll
        for (int ni = 0; ni < 4; ni++) {
            int c = wn + ni * 8 + 2 * tg;
            float2 v0, v1;
            v0.x = acc[mi][ni][0] + bv[ni].x;
            v0.y = acc[mi][ni][1] + bv[ni].y;
            v1.x = acc[mi][ni][2] + bv[ni].x;
            v1.y = acc[mi][ni][3] + bv[ni].y;
            if (r_lo < nrows) *(float2*)(out + (size_t)r_lo * 128 + c) = v0;
            if (r_hi < nrows) *(float2*)(out + (size_t)r_hi * 128 + c) = v1;
        }
    }
}

// ---------------- degree histogram ----------------
__global__ void hist_kernel(const int* __restrict__ src, const int* __restrict__ dst,
                            const float* __restrict__ attr, float* deg, int* cnt) {
    int e = blockIdx.x * blockDim.x + threadIdx.x;
    if (e >= EE) return;
    int d = dst[e];
    float w = attr[(size_t)e * 2 + 1];
    atomicAdd(&deg[d], w);
    atomicAdd(&cnt[d], 1);
}

// ---------------- scan (dinv folded into scan1) ----------------
__global__ void scan1(const int* __restrict__ in, int* __restrict__ out,
                      int* __restrict__ bsums, int n, float* dinv) {
    __shared__ int sh[256];
    int tid = threadIdx.x;
    int base = blockIdx.x * 1024;
    int v[4]; int tsum = 0;
#pragma unroll
    for (int j = 0; j < 4; j++) {
        int idx = base + tid * 4 + j;
        v[j] = (idx < n) ? in[idx] : 0;
        if (idx < n) dinv[idx] = rsqrtf(dinv[idx] + 1.0f);
        tsum += v[j];
    }
    sh[tid] = tsum; __syncthreads();
#pragma unroll
    for (int off = 1; off < 256; off <<= 1) {
        int t = (tid >= off) ? sh[tid - off] : 0;
        __syncthreads();
        sh[tid] += t;
        __syncthreads();
    }
    int run = sh[tid] - tsum;
#pragma unroll
    for (int j = 0; j < 4; j++) {
        int idx = base + tid * 4 + j;
        run += v[j];
        if (idx < n) out[idx] = run;
    }
    if (tid == 255) bsums[blockIdx.x] = sh[255];
}

__global__ void scan2(int* bs, int nb) {
    __shared__ int sh[128];
    int tid = threadIdx.x;
    int orig = (tid < nb) ? bs[tid] : 0;
    sh[tid] = orig; __syncthreads();
#pragma unroll
    for (int off = 1; off < 128; off <<= 1) {
        int t = (tid >= off) ? sh[tid - off] : 0;
        __syncthreads();
        sh[tid] += t;
        __syncthreads();
    }
    if (tid < nb) bs[tid] = sh[tid] - orig;
}

__global__ void scan3(int* out /* offs+1 */, const int* __restrict__ bs, int n,
                      int* offs0, int* cur) {
    int tid = threadIdx.x;
    int base = blockIdx.x * 1024;
    int add = bs[blockIdx.x];
#pragma unroll
    for (int j = 0; j < 4; j++) {
        int idx = base + tid * 4 + j;
        if (idx < n) {
            int v = out[idx] + add;
            out[idx] = v;
            if (idx + 1 < n) cur[idx + 1] = v;
        }
    }
    if (blockIdx.x == 0 && tid == 0) { offs0[0] = 0; cur[0] = 0; }
}

// ---------------- CSR fill ----------------
__global__ void fill_kernel(const int* __restrict__ src, const int* __restrict__ dst,
                            const float* __restrict__ attr, const float* __restrict__ dinv,
                            int* cursor, int2* cpack) {
    int e = blockIdx.x * blockDim.x + threadIdx.x;
    if (e >= EE) return;
    int s = src[e], d = dst[e];
    float w = attr[(size_t)e * 2 + 1];
    int pos = atomicAdd(&cursor[d], 1);
    int2 q;
    q.x = s;
    q.y = __float_as_int(dinv[s] * w * dinv[d]);
    cpack[pos] = q;
}

// ---------------- GCN aggregation (fp16 gather, fp32 accumulate, fp16 out) ------------
__global__ void agg_kernel(const __half* __restrict__ hw, const float* __restrict__ dinv,
                           const int* __restrict__ offs, const int2* __restrict__ cpack,
                           const float* __restrict__ bias, __half* __restrict__ out,
                           float* stats) {
    if (blockIdx.x == 0 && threadIdx.x < 256) stats[threadIdx.x] = 0.f;
    int gtid = blockIdx.x * blockDim.x + threadIdx.x;
    int node = gtid >> 5;
    if (node >= NN) return;
    int lane = threadIdx.x & 31;

    const uint2* feat = (const uint2*)hw;

    float di = dinv[node];
    float self = di * di;
    uint2 q0 = feat[(size_t)node * 32 + lane];
    float2 f01 = __half22float2(*(__half2*)&q0.x);
    float2 f23 = __half22float2(*(__half2*)&q0.y);
    float4 acc;
    acc.x = self * f01.x; acc.y = self * f01.y;
    acc.z = self * f23.x; acc.w = self * f23.y;

    int p0 = offs[node], p1 = offs[node + 1];
#pragma unroll 4
    for (int p = p0; p < p1; p++) {
        int2 e = cpack[p];
        float c = __int_as_float(e.y);
        uint2 qv = feat[(size_t)e.x * 32 + lane];
        float2 g01 = __half22float2(*(__half2*)&qv.x);
        float2 g23 = __half22float2(*(__half2*)&qv.y);
        acc.x += c * g01.x; acc.y += c * g01.y;
        acc.z += c * g23.x; acc.w += c * g23.y;
    }
    float4 b = ((const float4*)bias)[lane];
    __half2 o0 = __floats2half2_rn(fmaxf(acc.x + b.x, 0.f), fmaxf(acc.y + b.y, 0.f));
    __half2 o1 = __floats2half2_rn(fmaxf(acc.z + b.z, 0.f), fmaxf(acc.w + b.w, 0.f));
    uint2 o; o.x = *(uint32_t*)&o0; o.y = *(uint32_t*)&o1;
    ((uint2*)out)[(size_t)node * 32 + lane] = o;
}

// ---------------- BatchNorm stats (fp16 input) ----------------
#define BNBLK 296
#define BNCHUNK 338
__global__ void bn_stats(const __half* __restrict__ X, float* stats, int nrows) {
    __shared__ float sh[256];
    int d = threadIdx.x & 127;
    int half = threadIdx.x >> 7;
    int r0 = blockIdx.x * BNCHUNK;
    int rend = min(r0 + BNCHUNK, nrows);
    float s = 0.f, q = 0.f;
    for (int r = r0 + half; r < rend; r += 2) {
        float v = __half2float(X[(size_t)r * 128 + d]);
        s += v; q += v * v;
    }
    sh[threadIdx.x] = s; __syncthreads();
    if (half == 0) atomicAdd(&stats[d], s + sh[128 + d]);
    __syncthreads();
    sh[threadIdx.x] = q; __syncthreads();
    if (half == 0) atomicAdd(&stats[128 + d], q + sh[128 + d]);
}

__global__ void bn_finalize(float* stats, const float* __restrict__ gamma,
                            const float* __restrict__ beta) {
    int d = threadIdx.x;
    float invn = 1.0f / (float)NN;
    float m = stats[d] * invn;
    float v = stats[128 + d] * invn - m * m;
    float sc = gamma[d] * rsqrtf(v + EPSBN);
    stats[d] = sc;
    stats[128 + d] = beta[d] - m * sc;
}

// ---------------- pooling: 8 partial blocks per group ----------------
__global__ void pool_partial(const float* __restrict__ h, const int* __restrict__ batch,
                             float* __restrict__ part, float* __restrict__ pcnt) {
    int g = blockIdx.x >> 3, c = blockIdx.x & 7;
    int lo = 0, hi = NN;
    while (lo < hi) { int mid = (lo + hi) >> 1; if (batch[mid] < g) lo = mid + 1; else hi = mid; }
    int start = lo;
    lo = start; hi = NN;
    while (lo < hi) { int mid = (lo + hi) >> 1; if (batch[mid] < g + 1) lo = mid + 1; else hi = mid; }
    int end = lo;
    int len = end - start;
    int b0 = start + (int)(((long long)len * c) >> 3);
    int b1 = start + (int)(((long long)len * (c + 1)) >> 3);
    int d = threadIdx.x;
    float s = 0.f;
    for (int r = b0; r < b1; r++) s += h[(size_t)r * 128 + d];
    part[(g * 8 + c) * 128 + d] = s;
    if (c == 0 && d == 0) pcnt[g] = (float)len;
}

// ---------------- classifier: one block per group ----------------
__global__ void classify_kernel(const float* __restrict__ part, const float* __restrict__ pcnt,
                                float* __restrict__ reps,
                                const float* __restrict__ Wc1, const float* __restrict__ bc1,
                                const float* __restrict__ Wc2, const float* __restrict__ bc2,
                                float* __restrict__ logits) {
    __shared__ float rsh[128];
    __shared__ float tsh[128];
    int g = blockIdx.x;
    int d = threadIdx.x;
    float s = 0.f;
#pragma unroll
    for (int c = 0; c < 8; c++) s += part[(g * 8 + c) * 128 + d];
    float inv = 1.0f / fmaxf(pcnt[g], 1.0f);
    float rv = s * inv;
    reps[g * 128 + d] = rv;
    rsh[d] = rv;
    __syncthreads();
    float t = bc1[d];
#pragma unroll
    for (int k = 0; k < 128; k++) t += rsh[k] * Wc1[k * 128 + d];
    tsh[d] = fmaxf(t, 0.f);
    __syncthreads();
    if (d < CC) {
        float s2 = bc2[d];
#pragma unroll
        for (int k = 0; k < 128; k++) s2 += tsh[k] * Wc2[k * CC + d];
        logits[g * CC + d] = s2;
    }
}

// ---------------- launch ----------------
extern "C" void kernel_launch(void* const* d_in, const int* in_sizes, int n_in,
                              void* d_out, int out_size) {
    const float* x     = (const float*)d_in[0];
    const int*   ei    = (const int*)d_in[1];
    const float* ea    = (const float*)d_in[2];
    const int*   batch = (const int*)d_in[3];
    const float* Wg0 = (const float*)d_in[4],  *bg0 = (const float*)d_in[5];
    const float* gamma0 = (const float*)d_in[6], *beta0 = (const float*)d_in[7];
    const float* Wg1 = (const float*)d_in[8],  *bg1 = (const float*)d_in[9];
    const float* gamma1 = (const float*)d_in[10], *beta1 = (const float*)d_in[11];
    const float* Wl1 = (const float*)d_in[12], *bl1 = (const float*)d_in[13];
    const float* Wl2 = (const float*)d_in[14], *bl2 = (const float*)d_in[15];
    const float* Wc1 = (const float*)d_in[16], *bc1 = (const float*)d_in[17];
    const float* Wc2 = (const float*)d_in[18], *bc2 = (const float*)d_in[19];

    float* out = (float*)d_out;
    float* h_out  = out;
    float* reps   = out + (size_t)NN * DD;
    float* logits = out + (size_t)NN * DD + (size_t)GG * DD;

    float *dinv, *stats, *pool, *pcnt;
    __half *bufAh, *bufBh, *wt;
    int *cnt, *offs, *cur, *bsums;
    int2 *cpack;
    cudaGetSymbolAddress((void**)&bufAh, g_bufA);
    cudaGetSymbolAddress((void**)&bufBh, g_bufB);
    cudaGetSymbolAddress((void**)&dinv, g_dinv);
    cudaGetSymbolAddress((void**)&cnt, g_count);
    cudaGetSymbolAddress((void**)&offs, g_offs);
    cudaGetSymbolAddress((void**)&cur, g_cursor);
    cudaGetSymbolAddress((void**)&bsums, g_bsums);
    cudaGetSymbolAddress((void**)&cpack, g_cpack);
    cudaGetSymbolAddress((void**)&stats, g_stats);
    cudaGetSymbolAddress((void**)&pool, g_pool);
    cudaGetSymbolAddress((void**)&pcnt, g_pcnt);
    cudaGetSymbolAddress((void**)&wt, g_wt);

    cudaFuncSetAttribute(gemm_tc, cudaFuncAttributeMaxDynamicSharedMemorySize, GSMEM);
    cudaFuncSetAttribute(mlp_fused, cudaFuncAttributeMaxDynamicSharedMemorySize, FSMEM);

    const int* src = ei;
    const int* dst = ei + EE;

    const int TB = 256;
    const int gridN  = (NN + TB - 1) / TB;
    const int gridE  = (EE + TB - 1) / TB;
    const int gridG  = (NN + 127) / 128;   // 782
    const int gridAg = (NN * 32 + TB - 1) / TB;
    const int nScanB = (NN + 1023) / 1024;
    dim3 gemmGrid(gridG, 2);

    // prep (gemm_tc kept as 4th launch for ncu capture)
    zero2<<<gridN, TB>>>(dinv, cnt, NN);
    hist_kernel<<<gridE, TB>>>(src, dst, ea, dinv, cnt);
    wprep<<<256, 256>>>(Wg0, Wg1, Wl1, Wl2, wt);
    gemm_tc<<<gemmGrid, 128, GSMEM>>>(x, nullptr, wt + 0 * 16384, nullptr, bufAh, NN);

    // scan (+dinv) + CSR fill
    scan1<<<nScanB, 256>>>(cnt, offs + 1, bsums, NN, dinv);
    scan2<<<1, 128>>>(bsums, nScanB);
    scan3<<<nScanB, 256>>>(offs + 1, bsums, NN, offs, cur);
    fill_kernel<<<gridE, TB>>>(src, dst, ea, dinv, cur, cpack);

    // GCN layer 0
    agg_kernel<<<gridAg, TB>>>(bufAh, dinv, offs, cpack, bg0, bufBh, stats);
    bn_stats<<<BNBLK, 256>>>(bufBh, stats, NN);
    bn_finalize<<<1, 128>>>(stats, gamma0, beta0);

    // GCN layer 1 (bn0 affine fused into GEMM A-load)
    gemm_tc<<<gemmGrid, 128, GSMEM>>>(nullptr, bufBh, wt + 1 * 16384, stats, bufAh, NN);
    agg_kernel<<<gridAg, TB>>>(bufAh, dinv, offs, cpack, bg1, bufBh, stats);
    bn_stats<<<BNBLK, 256>>>(bufBh, stats, NN);
    bn_finalize<<<1, 128>>>(stats, gamma1, beta1);

    // fused MLP head (bn1 affine fused into A-load)
    mlp_fused<<<gridG, 256, FSMEM>>>(bufBh, wt + 2 * 16384, wt + 3 * 16384, stats, bl1, bl2, h_out, NN);

    // pooling + classifier
    pool_partial<<<GG * 8, 128>>>(h_out, batch, pool, pcnt);
    classify_kernel<<<GG, 128>>>(pool, pcnt, reps, Wc1, bc1, Wc2, bc2, logits);
}

// round 8
// speedup vs baseline: 2.7402x; 1.0237x over previous
#include <cuda_runtime.h>
#include <cuda_fp16.h>
#include <cstdint>

#define NN 100000
#define EE 1600000
#define DD 128
#define GG 64
#define CC 2
#define EPSBN 1e-5f

// ---------------- scratch (static device globals; no allocation) ----------------
__device__ __half g_bufA[(size_t)NN * DD];
__device__ __half g_bufB[(size_t)NN * DD];
__device__ float g_dinv[NN];
__device__ int   g_count[NN];
__device__ int   g_offs[NN + 1];
__device__ int   g_cursor[NN];
__device__ int   g_bsums[512];
__device__ int2  g_cpack[EE];
__device__ float g_stats[2 * DD];
__device__ float g_pool[GG * 8 * DD];
__device__ float g_pcnt[GG];
__device__ __half g_wt[4 * 128 * 128];   // fp16 weights, TRANSPOSED: [n][k]

// ---------------- helpers ----------------
__device__ __forceinline__ uint32_t smem_u32(const void* p) {
    uint32_t a;
    asm("{ .reg .u64 t; cvta.to.shared.u64 t, %1; cvt.u32.u64 %0, t; }" : "=r"(a) : "l"(p));
    return a;
}
__device__ __forceinline__ void mma_f16(float* d, const uint32_t* a, const uint32_t* b) {
    asm volatile(
        "mma.sync.aligned.m16n8k16.row.col.f32.f16.f16.f32 "
        "{%0,%1,%2,%3}, {%4,%5,%6,%7}, {%8,%9}, {%0,%1,%2,%3};"
        : "+f"(d[0]), "+f"(d[1]), "+f"(d[2]), "+f"(d[3])
        : "r"(a[0]), "r"(a[1]), "r"(a[2]), "r"(a[3]), "r"(b[0]), "r"(b[1]));
}
__device__ __forceinline__ void ldsm4(uint32_t* a, uint32_t addr) {
    asm volatile("ldmatrix.sync.aligned.m8n8.x4.shared.b16 {%0,%1,%2,%3}, [%4];"
        : "=r"(a[0]), "=r"(a[1]), "=r"(a[2]), "=r"(a[3]) : "r"(addr));
}
__device__ __forceinline__ void cp_async16(uint32_t saddr, const void* gaddr) {
    asm volatile("cp.async.cg.shared.global [%0], [%1], 16;" :: "r"(saddr), "l"(gaddr));
}

// SMEM half pitches
#define PA2 136
#define PBK 136
#define GSMEM ((128 * PA2 + 128 * PBK) * 2)       // 69.6 KB
#define FSMEM ((128 * PA2 + 2 * 128 * PBK) * 2)   // 104.4 KB

// ---------------- prep: zero deg/cnt + weight fp16 transpose ----------------
__global__ void prep(float* deg, int* cnt,
                     const float* __restrict__ W0, const float* __restrict__ W1,
                     const float* __restrict__ W2, const float* __restrict__ W3,
                     __half* __restrict__ wt) {
    int i = blockIdx.x * blockDim.x + threadIdx.x;
    if (i < NN) { deg[i] = 0.f; cnt[i] = 0; }
    if (i < 65536) {
        const float* W = (i < 16384) ? W0 : (i < 32768) ? W1 : (i < 49152) ? W2 : W3;
        int j = i & 16383;
        int n = j >> 7, k = j & 127;
        wt[i] = __float2half(W[k * 128 + n]);
    }
}

// ---------------- A staging (256 threads) ----------------
__device__ __forceinline__ void stage_A_f32(const float* __restrict__ A, __half* As,
                                            int row0, int nrows, int tid) {
#pragma unroll
    for (int i = 0; i < 16; i++) {
        int f = i * 256 + tid;
        int row = f >> 5, kq = f & 31;
        float4 v = make_float4(0.f, 0.f, 0.f, 0.f);
        if (row0 + row < nrows)
            v = ((const float4*)A)[(size_t)(row0 + row) * 32 + kq];
        __half2 h0 = __floats2half2_rn(v.x, v.y);
        __half2 h1 = __floats2half2_rn(v.z, v.w);
        uint2 t; t.x = *(uint32_t*)&h0; t.y = *(uint32_t*)&h1;
        *(uint2*)&As[row * PA2 + kq * 4] = t;
    }
}
__device__ __forceinline__ void stage_A_f16(const __half* __restrict__ A,
                                            const float* __restrict__ affine,
                                            __half* As, int row0, int nrows, int tid) {
#pragma unroll
    for (int i = 0; i < 16; i++) {
        int f = i * 256 + tid;
        int row = f >> 5, kq = f & 31;
        uint2 q = make_uint2(0u, 0u);
        if (row0 + row < nrows)
            q = ((const uint2*)A)[(size_t)(row0 + row) * 32 + kq];
        float2 f01 = __half22float2(*(__half2*)&q.x);
        float2 f23 = __half22float2(*(__half2*)&q.y);
        int k0 = kq * 4;
        f01.x = f01.x * affine[k0 + 0] + affine[128 + k0 + 0];
        f01.y = f01.y * affine[k0 + 1] + affine[128 + k0 + 1];
        f23.x = f23.x * affine[k0 + 2] + affine[128 + k0 + 2];
        f23.y = f23.y * affine[k0 + 3] + affine[128 + k0 + 3];
        __half2 h0 = __floats2half2_rn(f01.x, f01.y);
        __half2 h1 = __floats2half2_rn(f23.x, f23.y);
        uint2 t; t.x = *(uint32_t*)&h0; t.y = *(uint32_t*)&h1;
        *(uint2*)&As[row * PA2 + kq * 4] = t;
    }
}

// ---------------- fp16 MMA mainloop: 8 k16-steps ----------------
__device__ __forceinline__ void mma_loop_h(uint32_t abase, const __half* Bs,
                                           int wn, int gid, int tg, float acc[4][4][4]) {
#pragma unroll
    for (int ks = 0; ks < 8; ks++) {
        int k0 = ks * 16;
        uint32_t a[4][4];
#pragma unroll
        for (int mi = 0; mi < 4; mi++)
            ldsm4(a[mi], abase + (uint32_t)(mi * 16 * PA2 * 2 + ks * 32));
        uint32_t b[4][2];
#pragma unroll
        for (int ni = 0; ni < 4; ni++) {
            int c = wn + ni * 8 + gid;
            b[ni][0] = *(const uint32_t*)&Bs[c * PBK + k0 + 2 * tg];
            b[ni][1] = *(const uint32_t*)&Bs[c * PBK + k0 + 8 + 2 * tg];
        }
#pragma unroll
        for (int mi = 0; mi < 4; mi++)
#pragma unroll
            for (int ni = 0; ni < 4; ni++)
                mma_f16(acc[mi][ni], a[mi], b[ni]);
    }
}

// ---------------- GEMM: 256 threads, tile 128M x 128N, fp16 in/out ----------------
__global__ void __launch_bounds__(256) gemm_tc(const float* __restrict__ Af32,
                                               const __half* __restrict__ Ah,
                                               const __half* __restrict__ WT,
                                               const float* __restrict__ affine,
                                               __half* __restrict__ out,
                                               int nrows) {
    extern __shared__ __half smemh[];
    __half* As = smemh;                 // [128][PA2]
    __half* Bs = smemh + 128 * PA2;     // [128][PBK]
    int tid = threadIdx.x, wid = tid >> 5, lane = tid & 31;
    int row0 = blockIdx.x * 128;
    int gid = lane >> 2, tg = lane & 3;
    int wm = (wid >> 2) * 64, wn = (wid & 3) * 32;

    uint32_t bbase = smem_u32(Bs);
#pragma unroll
    for (int i = 0; i < 8; i++) {
        int f = i * 256 + tid;
        int n = f >> 4, q = f & 15;
        cp_async16(bbase + (uint32_t)((n * PBK + q * 8) * 2),
                   WT + (size_t)n * 128 + q * 8);
    }
    asm volatile("cp.async.commit_group;");

    if (affine) stage_A_f16(Ah, affine, As, row0, nrows, tid);
    else        stage_A_f32(Af32, As, row0, nrows, tid);

    asm volatile("cp.async.wait_group 0;" ::: "memory");
    __syncthreads();

    int ldrow = wm + ((lane >> 3) & 1) * 8 + (lane & 7);
    uint32_t abase = smem_u32(As) + (uint32_t)(ldrow * PA2 * 2 + ((lane >> 4) << 4));

    float acc[4][4][4];
#pragma unroll
    for (int mi = 0; mi < 4; mi++)
#pragma unroll
        for (int ni = 0; ni < 4; ni++)
#pragma unroll
            for (int j = 0; j < 4; j++) acc[mi][ni][j] = 0.f;

    mma_loop_h(abase, Bs, wn, gid, tg, acc);

#pragma unroll
    for (int mi = 0; mi < 4; mi++) {
        int r_lo = row0 + wm + mi * 16 + gid;
        int r_hi = r_lo + 8;
#pragma unroll
        for (int ni = 0; ni < 4; ni++) {
            int c = wn + ni * 8 + 2 * tg;
            __half2 p0 = __floats2half2_rn(acc[mi][ni][0], acc[mi][ni][1]);
            __half2 p1 = __floats2half2_rn(acc[mi][ni][2], acc[mi][ni][3]);
            if (r_lo < nrows) *(__half2*)(out + (size_t)r_lo * 128 + c) = p0;
            if (r_hi < nrows) *(__half2*)(out + (size_t)r_hi * 128 + c) = p1;
        }
    }
}

// ---------------- fused MLP head: out = (relu(affine(A)@W1+b1)) @ W2 + b2 (fp32 out) ----
__global__ void __launch_bounds__(256) mlp_fused(const __half* __restrict__ A,
                                                 const __half* __restrict__ W1T,
                                                 const __half* __restrict__ W2T,
                                                 const float* __restrict__ affine,
                                                 const float* __restrict__ b1,
                                                 const float* __restrict__ b2,
                                                 float* __restrict__ out, int nrows) {
    extern __shared__ __half smemh[];
    __half* As  = smemh;
    __half* Bs1 = smemh + 128 * PA2;
    __half* Bs2 = Bs1 + 128 * PBK;
    int tid = threadIdx.x, wid = tid >> 5, lane = tid & 31;
    int row0 = blockIdx.x * 128;
    int gid = lane >> 2, tg = lane & 3;
    int wm = (wid >> 2) * 64, wn = (wid & 3) * 32;

    uint32_t b1base = smem_u32(Bs1), b2base = smem_u32(Bs2);
#pragma unroll
    for (int i = 0; i < 8; i++) {
        int f = i * 256 + tid;
        int n = f >> 4, q = f & 15;
        cp_async16(b1base + (uint32_t)((n * PBK + q * 8) * 2), W1T + (size_t)n * 128 + q * 8);
        cp_async16(b2base + (uint32_t)((n * PBK + q * 8) * 2), W2T + (size_t)n * 128 + q * 8);
    }
    asm volatile("cp.async.commit_group;");

    stage_A_f16(A, affine, As, row0, nrows, tid);

    asm volatile("cp.async.wait_group 0;" ::: "memory");
    __syncthreads();

    int ldrow = wm + ((lane >> 3) & 1) * 8 + (lane & 7);
    uint32_t abase = smem_u32(As) + (uint32_t)(ldrow * PA2 * 2 + ((lane >> 4) << 4));

    float acc[4][4][4];
#pragma unroll
    for (int mi = 0; mi < 4; mi++)
#pragma unroll
        for (int ni = 0; ni < 4; ni++)
#pragma unroll
            for (int j = 0; j < 4; j++) acc[mi][ni][j] = 0.f;

    mma_loop_h(abase, Bs1, wn, gid, tg, acc);
    __syncthreads();

#pragma unroll
    for (int ni = 0; ni < 4; ni++) {
        int c = wn + ni * 8 + 2 * tg;
        float bx = b1[c], by = b1[c + 1];
#pragma unroll
        for (int mi = 0; mi < 4; mi++) {
            int r = wm + mi * 16 + gid;
            __half2 t0 = __floats2half2_rn(fmaxf(acc[mi][ni][0] + bx, 0.f),
                                           fmaxf(acc[mi][ni][1] + by, 0.f));
            __half2 t1 = __floats2half2_rn(fmaxf(acc[mi][ni][2] + bx, 0.f),
                                           fmaxf(acc[mi][ni][3] + by, 0.f));
            *(__half2*)&As[r * PA2 + c] = t0;
            *(__half2*)&As[(r + 8) * PA2 + c] = t1;
        }
    }
    __syncthreads();

#pragma unroll
    for (int mi = 0; mi < 4; mi++)
#pragma unroll
        for (int ni = 0; ni < 4; ni++)
#pragma unroll
            for (int j = 0; j < 4; j++) acc[mi][ni][j] = 0.f;

    mma_loop_h(abase, Bs2, wn, gid, tg, acc);

    float2 bv[4];
#pragma unroll
    for (int ni = 0; ni < 4; ni++) {
        int c = wn + ni * 8 + 2 * tg;
        bv[ni].x = b2[c]; bv[ni].y = b2[c + 1];
    }
#pragma unroll
    for (int mi = 0; mi < 4; mi++) {
        int r_lo = row0 + wm + mi * 16 + gid;
        int r_hi = r_lo + 8;
#pragma unroll
        for (int ni = 0; ni < 4; ni++) {
            int c = wn + ni * 8 + 2 * tg;
            float2 v0, v1;
            v0.x = acc[mi][ni][0] + bv[ni].x;
            v0.y = acc[mi][ni][1] + bv[ni].y;
            v1.x = acc[mi][ni][2] + bv[ni].x;
            v1.y = acc[mi][ni][3] + bv[ni].y;
            if (r_lo < nrows) *(float2*)(out + (size_t)r_lo * 128 + c) = v0;
            if (r_hi < nrows) *(float2*)(out + (size_t)r_hi * 128 + c) = v1;
        }
    }
}

// ---------------- degree histogram: 2 edges per thread ----------------
__global__ void hist_kernel(const int* __restrict__ src, const int* __restrict__ dst,
                            const float* __restrict__ attr, float* deg, int* cnt) {
    int i = blockIdx.x * blockDim.x + threadIdx.x;
    if (i >= EE / 2) return;
    int2 d2 = ((const int2*)dst)[i];
    float4 a2 = ((const float4*)attr)[i];
    atomicAdd(&deg[d2.x], a2.y);
    atomicAdd(&cnt[d2.x], 1);
    atomicAdd(&deg[d2.y], a2.w);
    atomicAdd(&cnt[d2.y], 1);
}

// ---------------- scan (dinv folded into scan1) ----------------
__global__ void scan1(const int* __restrict__ in, int* __restrict__ out,
                      int* __restrict__ bsums, int n, float* dinv) {
    __shared__ int sh[256];
    int tid = threadIdx.x;
    int base = blockIdx.x * 1024;
    int v[4]; int tsum = 0;
#pragma unroll
    for (int j = 0; j < 4; j++) {
        int idx = base + tid * 4 + j;
        v[j] = (idx < n) ? in[idx] : 0;
        if (idx < n) dinv[idx] = rsqrtf(dinv[idx] + 1.0f);
        tsum += v[j];
    }
    sh[tid] = tsum; __syncthreads();
#pragma unroll
    for (int off = 1; off < 256; off <<= 1) {
        int t = (tid >= off) ? sh[tid - off] : 0;
        __syncthreads();
        sh[tid] += t;
        __syncthreads();
    }
    int run = sh[tid] - tsum;
#pragma unroll
    for (int j = 0; j < 4; j++) {
        int idx = base + tid * 4 + j;
        run += v[j];
        if (idx < n) out[idx] = run;
    }
    if (tid == 255) bsums[blockIdx.x] = sh[255];
}

__global__ void scan2(int* bs, int nb) {
    __shared__ int sh[128];
    int tid = threadIdx.x;
    int orig = (tid < nb) ? bs[tid] : 0;
    sh[tid] = orig; __syncthreads();
#pragma unroll
    for (int off = 1; off < 128; off <<= 1) {
        int t = (tid >= off) ? sh[tid - off] : 0;
        __syncthreads();
        sh[tid] += t;
        __syncthreads();
    }
    if (tid < nb) bs[tid] = sh[tid] - orig;
}

__global__ void scan3(int* out /* offs+1 */, const int* __restrict__ bs, int n,
                      int* offs0, int* cur) {
    int tid = threadIdx.x;
    int base = blockIdx.x * 1024;
    int add = bs[blockIdx.x];
#pragma unroll
    for (int j = 0; j < 4; j++) {
        int idx = base + tid * 4 + j;
        if (idx < n) {
            int v = out[idx] + add;
            out[idx] = v;
            if (idx + 1 < n) cur[idx + 1] = v;
        }
    }
    if (blockIdx.x == 0 && tid == 0) { offs0[0] = 0; cur[0] = 0; }
}

// ---------------- CSR fill: 2 edges per thread ----------------
__global__ void fill_kernel(const int* __restrict__ src, const int* __restrict__ dst,
                            const float* __restrict__ attr, const float* __restrict__ dinv,
                            int* cursor, int2* cpack) {
    int i = blockIdx.x * blockDim.x + threadIdx.x;
    if (i >= EE / 2) return;
    int2 s2 = ((const int2*)src)[i];
    int2 d2 = ((const int2*)dst)[i];
    float4 a2 = ((const float4*)attr)[i];
    {
        int pos = atomicAdd(&cursor[d2.x], 1);
        int2 q; q.x = s2.x; q.y = __float_as_int(dinv[s2.x] * a2.y * dinv[d2.x]);
        cpack[pos] = q;
    }
    {
        int pos = atomicAdd(&cursor[d2.y], 1);
        int2 q; q.x = s2.y; q.y = __float_as_int(dinv[s2.y] * a2.w * dinv[d2.y]);
        cpack[pos] = q;
    }
}

// ---------------- GCN aggregation: HALF-WARP per node, uint4 gathers ----------------
__global__ void agg_kernel(const __half* __restrict__ hw, const float* __restrict__ dinv,
                           const int* __restrict__ offs, const int2* __restrict__ cpack,
                           const float* __restrict__ bias, __half* __restrict__ out,
                           float* stats) {
    if (blockIdx.x == 0 && threadIdx.x < 256) stats[threadIdx.x] = 0.f;
    int gtid = blockIdx.x * blockDim.x + threadIdx.x;
    int node = gtid >> 4;
    if (node >= NN) return;
    int lane = threadIdx.x & 15;

    const uint4* feat = (const uint4*)hw;   // 8 halfs per uint4; 16 per row

    float di = dinv[node];
    float self = di * di;
    float acc[8];
    {
        uint4 q = feat[(size_t)node * 16 + lane];
        float2 a = __half22float2(*(__half2*)&q.x);
        float2 b = __half22float2(*(((__half2*)&q.x) + 1));
        float2 c = __half22float2(*(__half2*)&q.z);
        float2 d = __half22float2(*(((__half2*)&q.z) + 1));
        acc[0] = self * a.x; acc[1] = self * a.y;
        acc[2] = self * b.x; acc[3] = self * b.y;
        acc[4] = self * c.x; acc[5] = self * c.y;
        acc[6] = self * d.x; acc[7] = self * d.y;
    }

    int p0 = offs[node], p1 = offs[node + 1];
#pragma unroll 4
    for (int p = p0; p < p1; p++) {
        int2 e = cpack[p];
        float c = __int_as_float(e.y);
        uint4 q = feat[(size_t)e.x * 16 + lane];
        float2 g0 = __half22float2(*(__half2*)&q.x);
        float2 g1 = __half22float2(*(((__half2*)&q.x) + 1));
        float2 g2 = __half22float2(*(__half2*)&q.z);
        float2 g3 = __half22float2(*(((__half2*)&q.z) + 1));
        acc[0] += c * g0.x; acc[1] += c * g0.y;
        acc[2] += c * g1.x; acc[3] += c * g1.y;
        acc[4] += c * g2.x; acc[5] += c * g2.y;
        acc[6] += c * g3.x; acc[7] += c * g3.y;
    }

    float4 b0 = ((const float4*)bias)[lane * 2];
    float4 b1 = ((const float4*)bias)[lane * 2 + 1];
    __half2 h0 = __floats2half2_rn(fmaxf(acc[0] + b0.x, 0.f), fmaxf(acc[1] + b0.y, 0.f));
    __half2 h1 = __floats2half2_rn(fmaxf(acc[2] + b0.z, 0.f), fmaxf(acc[3] + b0.w, 0.f));
    __half2 h2 = __floats2half2_rn(fmaxf(acc[4] + b1.x, 0.f), fmaxf(acc[5] + b1.y, 0.f));
    __half2 h3 = __floats2half2_rn(fmaxf(acc[6] + b1.z, 0.f), fmaxf(acc[7] + b1.w, 0.f));
    uint4 o;
    o.x = *(uint32_t*)&h0; o.y = *(uint32_t*)&h1;
    o.z = *(uint32_t*)&h2; o.w = *(uint32_t*)&h3;
    ((uint4*)out)[(size_t)node * 16 + lane] = o;
}

// ---------------- BatchNorm stats (fp16 input) ----------------
#define BNBLK 296
#define BNCHUNK 338
__global__ void bn_stats(const __half* __restrict__ X, float* stats, int nrows) {
    __shared__ float sh[256];
    int d = threadIdx.x & 127;
    int half = threadIdx.x >> 7;
    int r0 = blockIdx.x * BNCHUNK;
    int rend = min(r0 + BNCHUNK, nrows);
    float s = 0.f, q = 0.f;
    for (int r = r0 + half; r < rend; r += 2) {
        float v = __half2float(X[(size_t)r * 128 + d]);
        s += v; q += v * v;
    }
    sh[threadIdx.x] = s; __syncthreads();
    if (half == 0) atomicAdd(&stats[d], s + sh[128 + d]);
    __syncthreads();
    sh[threadIdx.x] = q; __syncthreads();
    if (half == 0) atomicAdd(&stats[128 + d], q + sh[128 + d]);
}

__global__ void bn_finalize(float* stats, const float* __restrict__ gamma,
                            const float* __restrict__ beta) {
    int d = threadIdx.x;
    float invn = 1.0f / (float)NN;
    float m = stats[d] * invn;
    float v = stats[128 + d] * invn - m * m;
    float sc = gamma[d] * rsqrtf(v + EPSBN);
    stats[d] = sc;
    stats[128 + d] = beta[d] - m * sc;
}

// ---------------- pooling: 8 partial blocks per group ----------------
__global__ void pool_partial(const float* __restrict__ h, const int* __restrict__ batch,
                             float* __restrict__ part, float* __restrict__ pcnt) {
    int g = blockIdx.x >> 3, c = blockIdx.x & 7;
    int lo = 0, hi = NN;
    while (lo < hi) { int mid = (lo + hi) >> 1; if (batch[mid] < g) lo = mid + 1; else hi = mid; }
    int start = lo;
    lo = start; hi = NN;
    while (lo < hi) { int mid = (lo + hi) >> 1; if (batch[mid] < g + 1) lo = mid + 1; else hi = mid; }
    int end = lo;
    int len = end - start;
    int b0 = start + (int)(((long long)len * c) >> 3);
    int b1 = start + (int)(((long long)len * (c + 1)) >> 3);
    int d = threadIdx.x;
    float s = 0.f;
    for (int r = b0; r < b1; r++) s += h[(size_t)r * 128 + d];
    part[(g * 8 + c) * 128 + d] = s;
    if (c == 0 && d == 0) pcnt[g] = (float)len;
}

// ---------------- classifier: one block per group ----------------
__global__ void classify_kernel(const float* __restrict__ part, const float* __restrict__ pcnt,
                                float* __restrict__ reps,
                                const float* __restrict__ Wc1, const float* __restrict__ bc1,
                                const float* __restrict__ Wc2, const float* __restrict__ bc2,
                                float* __restrict__ logits) {
    __shared__ float rsh[128];
    __shared__ float tsh[128];
    int g = blockIdx.x;
    int d = threadIdx.x;
    float s = 0.f;
#pragma unroll
    for (int c = 0; c < 8; c++) s += part[(g * 8 + c) * 128 + d];
    float inv = 1.0f / fmaxf(pcnt[g], 1.0f);
    float rv = s * inv;
    reps[g * 128 + d] = rv;
    rsh[d] = rv;
    __syncthreads();
    float t = bc1[d];
#pragma unroll
    for (int k = 0; k < 128; k++) t += rsh[k] * Wc1[k * 128 + d];
    tsh[d] = fmaxf(t, 0.f);
    __syncthreads();
    if (d < CC) {
        float s2 = bc2[d];
#pragma unroll
        for (int k = 0; k < 128; k++) s2 += tsh[k] * Wc2[k * CC + d];
        logits[g * CC + d] = s2;
    }
}

// ---------------- launch ----------------
extern "C" void kernel_launch(void* const* d_in, const int* in_sizes, int n_in,
                              void* d_out, int out_size) {
    const float* x     = (const float*)d_in[0];
    const int*   ei    = (const int*)d_in[1];
    const float* ea    = (const float*)d_in[2];
    const int*   batch = (const int*)d_in[3];
    const float* Wg0 = (const float*)d_in[4],  *bg0 = (const float*)d_in[5];
    const float* gamma0 = (const float*)d_in[6], *beta0 = (const float*)d_in[7];
    const float* Wg1 = (const float*)d_in[8],  *bg1 = (const float*)d_in[9];
    const float* gamma1 = (const float*)d_in[10], *beta1 = (const float*)d_in[11];
    const float* Wl1 = (const float*)d_in[12], *bl1 = (const float*)d_in[13];
    const float* Wl2 = (const float*)d_in[14], *bl2 = (const float*)d_in[15];
    const float* Wc1 = (const float*)d_in[16], *bc1 = (const float*)d_in[17];
    const float* Wc2 = (const float*)d_in[18], *bc2 = (const float*)d_in[19];

    float* out = (float*)d_out;
    float* h_out  = out;
    float* reps   = out + (size_t)NN * DD;
    float* logits = out + (size_t)NN * DD + (size_t)GG * DD;

    float *dinv, *stats, *pool, *pcnt;
    __half *bufAh, *bufBh, *wt;
    int *cnt, *offs, *cur, *bsums;
    int2 *cpack;
    cudaGetSymbolAddress((void**)&bufAh, g_bufA);
    cudaGetSymbolAddress((void**)&bufBh, g_bufB);
    cudaGetSymbolAddress((void**)&dinv, g_dinv);
    cudaGetSymbolAddress((void**)&cnt, g_count);
    cudaGetSymbolAddress((void**)&offs, g_offs);
    cudaGetSymbolAddress((void**)&cur, g_cursor);
    cudaGetSymbolAddress((void**)&bsums, g_bsums);
    cudaGetSymbolAddress((void**)&cpack, g_cpack);
    cudaGetSymbolAddress((void**)&stats, g_stats);
    cudaGetSymbolAddress((void**)&pool, g_pool);
    cudaGetSymbolAddress((void**)&pcnt, g_pcnt);
    cudaGetSymbolAddress((void**)&wt, g_wt);

    cudaFuncSetAttribute(gemm_tc, cudaFuncAttributeMaxDynamicSharedMemorySize, GSMEM);
    cudaFuncSetAttribute(mlp_fused, cudaFuncAttributeMaxDynamicSharedMemorySize, FSMEM);

    const int* src = ei;
    const int* dst = ei + EE;

    const int TB = 256;
    const int gridE2 = (EE / 2 + TB - 1) / TB;      // 3125
    const int gridG  = (NN + 127) / 128;            // 782
    const int gridAg = (NN * 16 + TB - 1) / TB;     // 6250
    const int nScanB = (NN + 1023) / 1024;

    // prep (zero + weights) -> hist -> scan1 -> gemm0 (4th: profiled)
    prep<<<(NN + TB - 1) / TB, TB>>>(dinv, cnt, Wg0, Wg1, Wl1, Wl2, wt);
    hist_kernel<<<gridE2, TB>>>(src, dst, ea, dinv, cnt);
    scan1<<<nScanB, 256>>>(cnt, offs + 1, bsums, NN, dinv);
    gemm_tc<<<gridG, 256, GSMEM>>>(x, nullptr, wt + 0 * 16384, nullptr, bufAh, NN);
    scan2<<<1, 128>>>(bsums, nScanB);
    scan3<<<nScanB, 256>>>(offs + 1, bsums, NN, offs, cur);
    fill_kernel<<<gridE2, TB>>>(src, dst, ea, dinv, cur, cpack);

    // GCN layer 0
    agg_kernel<<<gridAg, TB>>>(bufAh, dinv, offs, cpack, bg0, bufBh, stats);
    bn_stats<<<BNBLK, 256>>>(bufBh, stats, NN);
    bn_finalize<<<1, 128>>>(stats, gamma0, beta0);

    // GCN layer 1 (bn0 affine fused into GEMM A-load)
    gemm_tc<<<gridG, 256, GSMEM>>>(nullptr, bufBh, wt + 1 * 16384, stats, bufAh, NN);
    agg_kernel<<<gridAg, TB>>>(bufAh, dinv, offs, cpack, bg1, bufBh, stats);
    bn_stats<<<BNBLK, 256>>>(bufBh, stats, NN);
    bn_finalize<<<1, 128>>>(stats, gamma1, beta1);

    // fused MLP head (bn1 affine fused into A-load)
    mlp_fused<<<gridG, 256, FSMEM>>>(bufBh, wt + 2 * 16384, wt + 3 * 16384, stats, bl1, bl2, h_out, NN);

    // pooling + classifier
    pool_partial<<<GG * 8, 128>>>(h_out, batch, pool, pcnt);
    classify_kernel<<<GG, 128>>>(pool, pcnt, reps, Wc1, bc1, Wc2, bc2, logits);
}

// round 9
// speedup vs baseline: 2.7873x; 1.0172x over previous
#include <cuda_runtime.h>
#include <cuda_fp16.h>
#include <cstdint>

#define NN 100000
#define EE 1600000
#define DD 128
#define GG 64
#define CC 2
#define EPSBN 1e-5f

// ---------------- scratch (static device globals; no allocation) ----------------
__device__ __half g_bufA[(size_t)NN * DD];
__device__ __half g_bufB[(size_t)NN * DD];
__device__ float g_dinv[NN];
__device__ int   g_count[NN];
__device__ int   g_offs[NN + 1];
__device__ int   g_cursor[NN];
__device__ int   g_bsums[512];
__device__ int2  g_cpack[EE];
__device__ float g_stats[2 * DD];
__device__ float g_pool[GG * 8 * DD];
__device__ float g_pcnt[GG];
__device__ __half g_wt[4 * 128 * 128];   // fp16 weights, TRANSPOSED: [n][k]

// ---------------- helpers ----------------
__device__ __forceinline__ uint32_t smem_u32(const void* p) {
    uint32_t a;
    asm("{ .reg .u64 t; cvta.to.shared.u64 t, %1; cvt.u32.u64 %0, t; }" : "=r"(a) : "l"(p));
    return a;
}
__device__ __forceinline__ void mma_f16(float* d, const uint32_t* a, const uint32_t* b) {
    asm volatile(
        "mma.sync.aligned.m16n8k16.row.col.f32.f16.f16.f32 "
        "{%0,%1,%2,%3}, {%4,%5,%6,%7}, {%8,%9}, {%0,%1,%2,%3};"
        : "+f"(d[0]), "+f"(d[1]), "+f"(d[2]), "+f"(d[3])
        : "r"(a[0]), "r"(a[1]), "r"(a[2]), "r"(a[3]), "r"(b[0]), "r"(b[1]));
}
__device__ __forceinline__ void ldsm4(uint32_t* a, uint32_t addr) {
    asm volatile("ldmatrix.sync.aligned.m8n8.x4.shared.b16 {%0,%1,%2,%3}, [%4];"
        : "=r"(a[0]), "=r"(a[1]), "=r"(a[2]), "=r"(a[3]) : "r"(addr));
}
__device__ __forceinline__ void cp_async16(uint32_t saddr, const void* gaddr) {
    asm volatile("cp.async.cg.shared.global [%0], [%1], 16;" :: "r"(saddr), "l"(gaddr));
}

// SMEM half pitches
#define PA2 136
#define PBK 136
#define GSMEM ((128 * PA2 + 128 * PBK) * 2)       // 69.6 KB -> 2 CTAs/SM

// ---------------- prep: zero deg/cnt + weight fp16 transpose ----------------
__global__ void prep(float* deg, int* cnt,
                     const float* __restrict__ W0, const float* __restrict__ W1,
                     const float* __restrict__ W2, const float* __restrict__ W3,
                     __half* __restrict__ wt) {
    int i = blockIdx.x * blockDim.x + threadIdx.x;
    if (i < NN) { deg[i] = 0.f; cnt[i] = 0; }
    if (i < 65536) {
        const float* W = (i < 16384) ? W0 : (i < 32768) ? W1 : (i < 49152) ? W2 : W3;
        int j = i & 16383;
        int n = j >> 7, k = j & 127;
        wt[i] = __float2half(W[k * 128 + n]);
    }
}

// ---------------- A staging (256 threads) ----------------
__device__ __forceinline__ void stage_A_f32(const float* __restrict__ A, __half* As,
                                            int row0, int nrows, int tid) {
#pragma unroll
    for (int i = 0; i < 16; i++) {
        int f = i * 256 + tid;
        int row = f >> 5, kq = f & 31;
        float4 v = make_float4(0.f, 0.f, 0.f, 0.f);
        if (row0 + row < nrows)
            v = ((const float4*)A)[(size_t)(row0 + row) * 32 + kq];
        __half2 h0 = __floats2half2_rn(v.x, v.y);
        __half2 h1 = __floats2half2_rn(v.z, v.w);
        uint2 t; t.x = *(uint32_t*)&h0; t.y = *(uint32_t*)&h1;
        *(uint2*)&As[row * PA2 + kq * 4] = t;
    }
}
__device__ __forceinline__ void stage_A_f16(const __half* __restrict__ A,
                                            const float* __restrict__ affine,
                                            __half* As, int row0, int nrows, int tid) {
#pragma unroll
    for (int i = 0; i < 16; i++) {
        int f = i * 256 + tid;
        int row = f >> 5, kq = f & 31;
        uint2 q = make_uint2(0u, 0u);
        if (row0 + row < nrows)
            q = ((const uint2*)A)[(size_t)(row0 + row) * 32 + kq];
        float2 f01 = __half22float2(*(__half2*)&q.x);
        float2 f23 = __half22float2(*(__half2*)&q.y);
        int k0 = kq * 4;
        f01.x = f01.x * affine[k0 + 0] + affine[128 + k0 + 0];
        f01.y = f01.y * affine[k0 + 1] + affine[128 + k0 + 1];
        f23.x = f23.x * affine[k0 + 2] + affine[128 + k0 + 2];
        f23.y = f23.y * affine[k0 + 3] + affine[128 + k0 + 3];
        __half2 h0 = __floats2half2_rn(f01.x, f01.y);
        __half2 h1 = __floats2half2_rn(f23.x, f23.y);
        uint2 t; t.x = *(uint32_t*)&h0; t.y = *(uint32_t*)&h1;
        *(uint2*)&As[row * PA2 + kq * 4] = t;
    }
}

// ---------------- fp16 MMA mainloop: 8 k16-steps ----------------
__device__ __forceinline__ void mma_loop_h(uint32_t abase, const __half* Bs,
                                           int wn, int gid, int tg, float acc[4][4][4]) {
#pragma unroll
    for (int ks = 0; ks < 8; ks++) {
        int k0 = ks * 16;
        uint32_t a[4][4];
#pragma unroll
        for (int mi = 0; mi < 4; mi++)
            ldsm4(a[mi], abase + (uint32_t)(mi * 16 * PA2 * 2 + ks * 32));
        uint32_t b[4][2];
#pragma unroll
        for (int ni = 0; ni < 4; ni++) {
            int c = wn + ni * 8 + gid;
            b[ni][0] = *(const uint32_t*)&Bs[c * PBK + k0 + 2 * tg];
            b[ni][1] = *(const uint32_t*)&Bs[c * PBK + k0 + 8 + 2 * tg];
        }
#pragma unroll
        for (int mi = 0; mi < 4; mi++)
#pragma unroll
            for (int ni = 0; ni < 4; ni++)
                mma_f16(acc[mi][ni], a[mi], b[ni]);
    }
}

// ---------------- GEMM: 256 threads, tile 128M x 128N, fp16 in/out ----------------
__global__ void __launch_bounds__(256) gemm_tc(const float* __restrict__ Af32,
                                               const __half* __restrict__ Ah,
                                               const __half* __restrict__ WT,
                                               const float* __restrict__ affine,
                                               __half* __restrict__ out,
                                               int nrows) {
    extern __shared__ __half smemh[];
    __half* As = smemh;                 // [128][PA2]
    __half* Bs = smemh + 128 * PA2;     // [128][PBK]
    int tid = threadIdx.x, wid = tid >> 5, lane = tid & 31;
    int row0 = blockIdx.x * 128;
    int gid = lane >> 2, tg = lane & 3;
    int wm = (wid >> 2) * 64, wn = (wid & 3) * 32;

    uint32_t bbase = smem_u32(Bs);
#pragma unroll
    for (int i = 0; i < 8; i++) {
        int f = i * 256 + tid;
        int n = f >> 4, q = f & 15;
        cp_async16(bbase + (uint32_t)((n * PBK + q * 8) * 2),
                   WT + (size_t)n * 128 + q * 8);
    }
    asm volatile("cp.async.commit_group;");

    if (affine) stage_A_f16(Ah, affine, As, row0, nrows, tid);
    else        stage_A_f32(Af32, As, row0, nrows, tid);

    asm volatile("cp.async.wait_group 0;" ::: "memory");
    __syncthreads();

    int ldrow = wm + ((lane >> 3) & 1) * 8 + (lane & 7);
    uint32_t abase = smem_u32(As) + (uint32_t)(ldrow * PA2 * 2 + ((lane >> 4) << 4));

    float acc[4][4][4];
#pragma unroll
    for (int mi = 0; mi < 4; mi++)
#pragma unroll
        for (int ni = 0; ni < 4; ni++)
#pragma unroll
            for (int j = 0; j < 4; j++) acc[mi][ni][j] = 0.f;

    mma_loop_h(abase, Bs, wn, gid, tg, acc);

#pragma unroll
    for (int mi = 0; mi < 4; mi++) {
        int r_lo = row0 + wm + mi * 16 + gid;
        int r_hi = r_lo + 8;
#pragma unroll
        for (int ni = 0; ni < 4; ni++) {
            int c = wn + ni * 8 + 2 * tg;
            __half2 p0 = __floats2half2_rn(acc[mi][ni][0], acc[mi][ni][1]);
            __half2 p1 = __floats2half2_rn(acc[mi][ni][2], acc[mi][ni][3]);
            if (r_lo < nrows) *(__half2*)(out + (size_t)r_lo * 128 + c) = p0;
            if (r_hi < nrows) *(__half2*)(out + (size_t)r_hi * 128 + c) = p1;
        }
    }
}

// ---------------- fused MLP head with single B buffer (2 CTAs/SM) ----------------
__global__ void __launch_bounds__(256) mlp_fused(const __half* __restrict__ A,
                                                 const __half* __restrict__ W1T,
                                                 const __half* __restrict__ W2T,
                                                 const float* __restrict__ affine,
                                                 const float* __restrict__ b1,
                                                 const float* __restrict__ b2,
                                                 float* __restrict__ out, int nrows) {
    extern __shared__ __half smemh[];
    __half* As = smemh;
    __half* Bs = smemh + 128 * PA2;
    int tid = threadIdx.x, wid = tid >> 5, lane = tid & 31;
    int row0 = blockIdx.x * 128;
    int gid = lane >> 2, tg = lane & 3;
    int wm = (wid >> 2) * 64, wn = (wid & 3) * 32;

    uint32_t bbase = smem_u32(Bs);
#pragma unroll
    for (int i = 0; i < 8; i++) {
        int f = i * 256 + tid;
        int n = f >> 4, q = f & 15;
        cp_async16(bbase + (uint32_t)((n * PBK + q * 8) * 2), W1T + (size_t)n * 128 + q * 8);
    }
    asm volatile("cp.async.commit_group;");

    stage_A_f16(A, affine, As, row0, nrows, tid);

    asm volatile("cp.async.wait_group 0;" ::: "memory");
    __syncthreads();

    int ldrow = wm + ((lane >> 3) & 1) * 8 + (lane & 7);
    uint32_t abase = smem_u32(As) + (uint32_t)(ldrow * PA2 * 2 + ((lane >> 4) << 4));

    float acc[4][4][4];
#pragma unroll
    for (int mi = 0; mi < 4; mi++)
#pragma unroll
        for (int ni = 0; ni < 4; ni++)
#pragma unroll
            for (int j = 0; j < 4; j++) acc[mi][ni][j] = 0.f;

    mma_loop_h(abase, Bs, wn, gid, tg, acc);
    __syncthreads();   // all reads of Bs (W1) and As done

    // overwrite Bs with W2 (async; overlaps with T writeback below)
#pragma unroll
    for (int i = 0; i < 8; i++) {
        int f = i * 256 + tid;
        int n = f >> 4, q = f & 15;
        cp_async16(bbase + (uint32_t)((n * PBK + q * 8) * 2), W2T + (size_t)n * 128 + q * 8);
    }
    asm volatile("cp.async.commit_group;");

    // write T = relu(acc + b1) back into As as fp16
#pragma unroll
    for (int ni = 0; ni < 4; ni++) {
        int c = wn + ni * 8 + 2 * tg;
        float bx = b1[c], by = b1[c + 1];
#pragma unroll
        for (int mi = 0; mi < 4; mi++) {
            int r = wm + mi * 16 + gid;
            __half2 t0 = __floats2half2_rn(fmaxf(acc[mi][ni][0] + bx, 0.f),
                                           fmaxf(acc[mi][ni][1] + by, 0.f));
            __half2 t1 = __floats2half2_rn(fmaxf(acc[mi][ni][2] + bx, 0.f),
                                           fmaxf(acc[mi][ni][3] + by, 0.f));
            *(__half2*)&As[r * PA2 + c] = t0;
            *(__half2*)&As[(r + 8) * PA2 + c] = t1;
        }
    }
    asm volatile("cp.async.wait_group 0;" ::: "memory");
    __syncthreads();

#pragma unroll
    for (int mi = 0; mi < 4; mi++)
#pragma unroll
        for (int ni = 0; ni < 4; ni++)
#pragma unroll
            for (int j = 0; j < 4; j++) acc[mi][ni][j] = 0.f;

    mma_loop_h(abase, Bs, wn, gid, tg, acc);

    float2 bv[4];
#pragma unroll
    for (int ni = 0; ni < 4; ni++) {
        int c = wn + ni * 8 + 2 * tg;
        bv[ni].x = b2[c]; bv[ni].y = b2[c + 1];
    }
#pragma unroll
    for (int mi = 0; mi < 4; mi++) {
        int r_lo = row0 + wm + mi * 16 + gid;
        int r_hi = r_lo + 8;
#pragma unroll
        for (int ni = 0; ni < 4; ni++) {
            int c = wn + ni * 8 + 2 * tg;
            float2 v0, v1;
            v0.x = acc[mi][ni][0] + bv[ni].x;
            v0.y = acc[mi][ni][1] + bv[ni].y;
            v1.x = acc[mi][ni][2] + bv[ni].x;
            v1.y = acc[mi][ni][3] + bv[ni].y;
            if (r_lo < nrows) *(float2*)(out + (size_t)r_lo * 128 + c) = v0;
            if (r_hi < nrows) *(float2*)(out + (size_t)r_hi * 128 + c) = v1;
        }
    }
}

// ---------------- degree histogram: 2 edges per thread ----------------
__global__ void hist_kernel(const int* __restrict__ src, const int* __restrict__ dst,
                            const float* __restrict__ attr, float* deg, int* cnt) {
    int i = blockIdx.x * blockDim.x + threadIdx.x;
    if (i >= EE / 2) return;
    int2 d2 = ((const int2*)dst)[i];
    float4 a2 = ((const float4*)attr)[i];
    atomicAdd(&deg[d2.x], a2.y);
    atomicAdd(&cnt[d2.x], 1);
    atomicAdd(&deg[d2.y], a2.w);
    atomicAdd(&cnt[d2.y], 1);
}

// ---------------- scan (dinv folded into scan1) ----------------
__global__ void scan1(const int* __restrict__ in, int* __restrict__ out,
                      int* __restrict__ bsums, int n, float* dinv) {
    __shared__ int sh[256];
    int tid = threadIdx.x;
    int base = blockIdx.x * 1024;
    int v[4]; int tsum = 0;
#pragma unroll
    for (int j = 0; j < 4; j++) {
        int idx = base + tid * 4 + j;
        v[j] = (idx < n) ? in[idx] : 0;
        if (idx < n) dinv[idx] = rsqrtf(dinv[idx] + 1.0f);
        tsum += v[j];
    }
    sh[tid] = tsum; __syncthreads();
#pragma unroll
    for (int off = 1; off < 256; off <<= 1) {
        int t = (tid >= off) ? sh[tid - off] : 0;
        __syncthreads();
        sh[tid] += t;
        __syncthreads();
    }
    int run = sh[tid] - tsum;
#pragma unroll
    for (int j = 0; j < 4; j++) {
        int idx = base + tid * 4 + j;
        run += v[j];
        if (idx < n) out[idx] = run;
    }
    if (tid == 255) bsums[blockIdx.x] = sh[255];
}

__global__ void scan2(int* bs, int nb) {
    __shared__ int sh[128];
    int tid = threadIdx.x;
    int orig = (tid < nb) ? bs[tid] : 0;
    sh[tid] = orig; __syncthreads();
#pragma unroll
    for (int off = 1; off < 128; off <<= 1) {
        int t = (tid >= off) ? sh[tid - off] : 0;
        __syncthreads();
        sh[tid] += t;
        __syncthreads();
    }
    if (tid < nb) bs[tid] = sh[tid] - orig;
}

__global__ void scan3(int* out /* offs+1 */, const int* __restrict__ bs, int n,
                      int* offs0, int* cur) {
    int tid = threadIdx.x;
    int base = blockIdx.x * 1024;
    int add = bs[blockIdx.x];
#pragma unroll
    for (int j = 0; j < 4; j++) {
        int idx = base + tid * 4 + j;
        if (idx < n) {
            int v = out[idx] + add;
            out[idx] = v;
            if (idx + 1 < n) cur[idx + 1] = v;
        }
    }
    if (blockIdx.x == 0 && tid == 0) { offs0[0] = 0; cur[0] = 0; }
}

// ---------------- CSR fill: 2 edges per thread ----------------
__global__ void fill_kernel(const int* __restrict__ src, const int* __restrict__ dst,
                            const float* __restrict__ attr, const float* __restrict__ dinv,
                            int* cursor, int2* cpack) {
    int i = blockIdx.x * blockDim.x + threadIdx.x;
    if (i >= EE / 2) return;
    int2 s2 = ((const int2*)src)[i];
    int2 d2 = ((const int2*)dst)[i];
    float4 a2 = ((const float4*)attr)[i];
    {
        int pos = atomicAdd(&cursor[d2.x], 1);
        int2 q; q.x = s2.x; q.y = __float_as_int(dinv[s2.x] * a2.y * dinv[d2.x]);
        cpack[pos] = q;
    }
    {
        int pos = atomicAdd(&cursor[d2.y], 1);
        int2 q; q.x = s2.y; q.y = __float_as_int(dinv[s2.y] * a2.w * dinv[d2.y]);
        cpack[pos] = q;
    }
}

// ---------------- GCN aggregation: HALF-WARP per node, uint4 gathers ----------------
__global__ void agg_kernel(const __half* __restrict__ hw, const float* __restrict__ dinv,
                           const int* __restrict__ offs, const int2* __restrict__ cpack,
                           const float* __restrict__ bias, __half* __restrict__ out,
                           float* stats) {
    if (blockIdx.x == 0 && threadIdx.x < 256) stats[threadIdx.x] = 0.f;
    int gtid = blockIdx.x * blockDim.x + threadIdx.x;
    int node = gtid >> 4;
    if (node >= NN) return;
    int lane = threadIdx.x & 15;

    const uint4* feat = (const uint4*)hw;

    float di = dinv[node];
    float self = di * di;
    float acc[8];
    {
        uint4 q = feat[(size_t)node * 16 + lane];
        float2 a = __half22float2(*(__half2*)&q.x);
        float2 b = __half22float2(*(((__half2*)&q.x) + 1));
        float2 c = __half22float2(*(__half2*)&q.z);
        float2 d = __half22float2(*(((__half2*)&q.z) + 1));
        acc[0] = self * a.x; acc[1] = self * a.y;
        acc[2] = self * b.x; acc[3] = self * b.y;
        acc[4] = self * c.x; acc[5] = self * c.y;
        acc[6] = self * d.x; acc[7] = self * d.y;
    }

    int p0 = offs[node], p1 = offs[node + 1];
#pragma unroll 4
    for (int p = p0; p < p1; p++) {
        int2 e = cpack[p];
        float c = __int_as_float(e.y);
        uint4 q = feat[(size_t)e.x * 16 + lane];
        float2 g0 = __half22float2(*(__half2*)&q.x);
        float2 g1 = __half22float2(*(((__half2*)&q.x) + 1));
        float2 g2 = __half22float2(*(__half2*)&q.z);
        float2 g3 = __half22float2(*(((__half2*)&q.z) + 1));
        acc[0] += c * g0.x; acc[1] += c * g0.y;
        acc[2] += c * g1.x; acc[3] += c * g1.y;
        acc[4] += c * g2.x; acc[5] += c * g2.y;
        acc[6] += c * g3.x; acc[7] += c * g3.y;
    }

    float4 b0 = ((const float4*)bias)[lane * 2];
    float4 b1 = ((const float4*)bias)[lane * 2 + 1];
    __half2 h0 = __floats2half2_rn(fmaxf(acc[0] + b0.x, 0.f), fmaxf(acc[1] + b0.y, 0.f));
    __half2 h1 = __floats2half2_rn(fmaxf(acc[2] + b0.z, 0.f), fmaxf(acc[3] + b0.w, 0.f));
    __half2 h2 = __floats2half2_rn(fmaxf(acc[4] + b1.x, 0.f), fmaxf(acc[5] + b1.y, 0.f));
    __half2 h3 = __floats2half2_rn(fmaxf(acc[6] + b1.z, 0.f), fmaxf(acc[7] + b1.w, 0.f));
    uint4 o;
    o.x = *(uint32_t*)&h0; o.y = *(uint32_t*)&h1;
    o.z = *(uint32_t*)&h2; o.w = *(uint32_t*)&h3;
    ((uint4*)out)[(size_t)node * 16 + lane] = o;
}

// ---------------- BatchNorm stats (fp16 input) ----------------
#define BNBLK 296
#define BNCHUNK 338
__global__ void bn_stats(const __half* __restrict__ X, float* stats, int nrows) {
    __shared__ float sh[256];
    int d = threadIdx.x & 127;
    int half = threadIdx.x >> 7;
    int r0 = blockIdx.x * BNCHUNK;
    int rend = min(r0 + BNCHUNK, nrows);
    float s = 0.f, q = 0.f;
    for (int r = r0 + half; r < rend; r += 2) {
        float v = __half2float(X[(size_t)r * 128 + d]);
        s += v; q += v * v;
    }
    sh[threadIdx.x] = s; __syncthreads();
    if (half == 0) atomicAdd(&stats[d], s + sh[128 + d]);
    __syncthreads();
    sh[threadIdx.x] = q; __syncthreads();
    if (half == 0) atomicAdd(&stats[128 + d], q + sh[128 + d]);
}

__global__ void bn_finalize(float* stats, const float* __restrict__ gamma,
                            const float* __restrict__ beta) {
    int d = threadIdx.x;
    float invn = 1.0f / (float)NN;
    float m = stats[d] * invn;
    float v = stats[128 + d] * invn - m * m;
    float sc = gamma[d] * rsqrtf(v + EPSBN);
    stats[d] = sc;
    stats[128 + d] = beta[d] - m * sc;
}

// ---------------- pooling: 8 partial blocks per group ----------------
__global__ void pool_partial(const float* __restrict__ h, const int* __restrict__ batch,
                             float* __restrict__ part, float* __restrict__ pcnt) {
    int g = blockIdx.x >> 3, c = blockIdx.x & 7;
    int lo = 0, hi = NN;
    while (lo < hi) { int mid = (lo + hi) >> 1; if (batch[mid] < g) lo = mid + 1; else hi = mid; }
    int start = lo;
    lo = start; hi = NN;
    while (lo < hi) { int mid = (lo + hi) >> 1; if (batch[mid] < g + 1) lo = mid + 1; else hi = mid; }
    int end = lo;
    int len = end - start;
    int b0 = start + (int)(((long long)len * c) >> 3);
    int b1 = start + (int)(((long long)len * (c + 1)) >> 3);
    int d = threadIdx.x;
    float s = 0.f;
    for (int r = b0; r < b1; r++) s += h[(size_t)r * 128 + d];
    part[(g * 8 + c) * 128 + d] = s;
    if (c == 0 && d == 0) pcnt[g] = (float)len;
}

// ---------------- classifier: one block per group ----------------
__global__ void classify_kernel(const float* __restrict__ part, const float* __restrict__ pcnt,
                                float* __restrict__ reps,
                                const float* __restrict__ Wc1, const float* __restrict__ bc1,
                                const float* __restrict__ Wc2, const float* __restrict__ bc2,
                                float* __restrict__ logits) {
    __shared__ float rsh[128];
    __shared__ float tsh[128];
    int g = blockIdx.x;
    int d = threadIdx.x;
    float s = 0.f;
#pragma unroll
    for (int c = 0; c < 8; c++) s += part[(g * 8 + c) * 128 + d];
    float inv = 1.0f / fmaxf(pcnt[g], 1.0f);
    float rv = s * inv;
    reps[g * 128 + d] = rv;
    rsh[d] = rv;
    __syncthreads();
    float t = bc1[d];
#pragma unroll
    for (int k = 0; k < 128; k++) t += rsh[k] * Wc1[k * 128 + d];
    tsh[d] = fmaxf(t, 0.f);
    __syncthreads();
    if (d < CC) {
        float s2 = bc2[d];
#pragma unroll
        for (int k = 0; k < 128; k++) s2 += tsh[k] * Wc2[k * CC + d];
        logits[g * CC + d] = s2;
    }
}

// ---------------- launch ----------------
extern "C" void kernel_launch(void* const* d_in, const int* in_sizes, int n_in,
                              void* d_out, int out_size) {
    const float* x     = (const float*)d_in[0];
    const int*   ei    = (const int*)d_in[1];
    const float* ea    = (const float*)d_in[2];
    const int*   batch = (const int*)d_in[3];
    const float* Wg0 = (const float*)d_in[4],  *bg0 = (const float*)d_in[5];
    const float* gamma0 = (const float*)d_in[6], *beta0 = (const float*)d_in[7];
    const float* Wg1 = (const float*)d_in[8],  *bg1 = (const float*)d_in[9];
    const float* gamma1 = (const float*)d_in[10], *beta1 = (const float*)d_in[11];
    const float* Wl1 = (const float*)d_in[12], *bl1 = (const float*)d_in[13];
    const float* Wl2 = (const float*)d_in[14], *bl2 = (const float*)d_in[15];
    const float* Wc1 = (const float*)d_in[16], *bc1 = (const float*)d_in[17];
    const float* Wc2 = (const float*)d_in[18], *bc2 = (const float*)d_in[19];

    float* out = (float*)d_out;
    float* h_out  = out;
    float* reps   = out + (size_t)NN * DD;
    float* logits = out + (size_t)NN * DD + (size_t)GG * DD;

    float *dinv, *stats, *pool, *pcnt;
    __half *bufAh, *bufBh, *wt;
    int *cnt, *offs, *cur, *bsums;
    int2 *cpack;
    cudaGetSymbolAddress((void**)&bufAh, g_bufA);
    cudaGetSymbolAddress((void**)&bufBh, g_bufB);
    cudaGetSymbolAddress((void**)&dinv, g_dinv);
    cudaGetSymbolAddress((void**)&cnt, g_count);
    cudaGetSymbolAddress((void**)&offs, g_offs);
    cudaGetSymbolAddress((void**)&cur, g_cursor);
    cudaGetSymbolAddress((void**)&bsums, g_bsums);
    cudaGetSymbolAddress((void**)&cpack, g_cpack);
    cudaGetSymbolAddress((void**)&stats, g_stats);
    cudaGetSymbolAddress((void**)&pool, g_pool);
    cudaGetSymbolAddress((void**)&pcnt, g_pcnt);
    cudaGetSymbolAddress((void**)&wt, g_wt);

    cudaFuncSetAttribute(gemm_tc, cudaFuncAttributeMaxDynamicSharedMemorySize, GSMEM);
    cudaFuncSetAttribute(mlp_fused, cudaFuncAttributeMaxDynamicSharedMemorySize, GSMEM);

    const int* src = ei;
    const int* dst = ei + EE;

    const int TB = 256;
    const int gridE2 = (EE / 2 + TB - 1) / TB;      // 3125
    const int gridG  = (NN + 127) / 128;            // 782
    const int gridAg = (NN * 16 + TB - 1) / TB;     // 6250
    const int nScanB = (NN + 1023) / 1024;

    // side stream for CSR build (created per call; not destroyed — capture-safe)
    cudaStream_t sB;
    cudaStreamCreateWithFlags(&sB, cudaStreamNonBlocking);
    cudaEvent_t eFork, eJoin;
    cudaEventCreateWithFlags(&eFork, cudaEventDisableTiming);
    cudaEventCreateWithFlags(&eJoin, cudaEventDisableTiming);

    // prep on main stream, then fork
    prep<<<(NN + TB - 1) / TB, TB>>>(dinv, cnt, Wg0, Wg1, Wl1, Wl2, wt);
    cudaEventRecord(eFork, 0);
    cudaStreamWaitEvent(sB, eFork, 0);

    // branch B (side stream): CSR build
    hist_kernel<<<gridE2, TB, 0, sB>>>(src, dst, ea, dinv, cnt);
    scan1<<<nScanB, 256, 0, sB>>>(cnt, offs + 1, bsums, NN, dinv);
    scan2<<<1, 128, 0, sB>>>(bsums, nScanB);
    scan3<<<nScanB, 256, 0, sB>>>(offs + 1, bsums, NN, offs, cur);
    fill_kernel<<<gridE2, TB, 0, sB>>>(src, dst, ea, dinv, cur, cpack);
    cudaEventRecord(eJoin, sB);

    // branch A (main stream): layer-0 GEMM
    gemm_tc<<<gridG, 256, GSMEM>>>(x, nullptr, wt + 0 * 16384, nullptr, bufAh, NN);

    // join
    cudaStreamWaitEvent(0, eJoin, 0);

    // GCN layer 0
    agg_kernel<<<gridAg, TB>>>(bufAh, dinv, offs, cpack, bg0, bufBh, stats);
    bn_stats<<<BNBLK, 256>>>(bufBh, stats, NN);
    bn_finalize<<<1, 128>>>(stats, gamma0, beta0);

    // GCN layer 1 (bn0 affine fused into GEMM A-load)
    gemm_tc<<<gridG, 256, GSMEM>>>(nullptr, bufBh, wt + 1 * 16384, stats, bufAh, NN);
    agg_kernel<<<gridAg, TB>>>(bufAh, dinv, offs, cpack, bg1, bufBh, stats);
    bn_stats<<<BNBLK, 256>>>(bufBh, stats, NN);
    bn_finalize<<<1, 128>>>(stats, gamma1, beta1);

    // fused MLP head (bn1 affine fused into A-load)
    mlp_fused<<<gridG, 256, GSMEM>>>(bufBh, wt + 2 * 16384, wt + 3 * 16384, stats, bl1, bl2, h_out, NN);

    // pooling + classifier
    pool_partial<<<GG * 8, 128>>>(h_out, batch, pool, pcnt);
    classify_kernel<<<GG, 128>>>(pool, pcnt, reps, Wc1, bc1, Wc2, bc2, logits);
}